// round 1
// baseline (speedup 1.0000x reference)
#include <cuda_runtime.h>
#include <math.h>

#define N_TOK 4096
#define TOTF  2048
#define HID   768

// Scratch (allocation-free rule: device globals)
__device__ float g_T [N_TOK * TOTF];
__device__ float g_T2[N_TOK * TOTF];

// ---------------------------------------------------------------------------
// Conv + maxpool + relu, fused with char-embedding gather.
// Block: 32 tokens x FILT filters of one width W.
// Xs layout: [p*16+c][tok]  (window at position l = rows l*16 .. l*16+16W-1)
// Ws layout: [k*16+c][filt]
// ---------------------------------------------------------------------------
template<int W, int FILT, int TX, int TY, int MI, int MJ>
__global__ __launch_bounds__(256)
void conv_kernel(const int* __restrict__ ids, const float* __restrict__ emb,
                 const float* __restrict__ cw, const float* __restrict__ cb,
                 float* __restrict__ tout, int colBase)
{
    constexpr int TOK  = 32;
    constexpr int KDIM = 16 * W;
    extern __shared__ float sm[];
    float* Xs = sm;                 // [800][TOK]
    float* Ws = sm + 800 * TOK;     // [KDIM][FILT]

    const int n0  = blockIdx.x * TOK;
    const int f0  = blockIdx.y * FILT;
    const int tid = threadIdx.x;

    // Stage weights: cw[f][c][k] -> Ws[k*16+c][fl]
    for (int i = tid; i < FILT * KDIM; i += 256) {
        int fl = i % FILT;
        int rc = i / FILT;
        int k  = rc >> 4, c = rc & 15;
        Ws[i] = cw[((f0 + fl) * 16 + c) * W + k];
    }
    // Gather embeddings: Xs[l*16+c][tok] = emb[ids[n0+tok][l]][c]
    {
        int tok  = tid >> 3;
        int lane = tid & 7;
        const int* idrow = ids + (n0 + tok) * 50;
        for (int i4 = lane; i4 < 200; i4 += 8) {   // 200 float4 per token
            int l  = i4 >> 2;
            int cg = (i4 & 3) << 2;
            int id = idrow[l];
            float4 ev = *(const float4*)(emb + id * 16 + cg);
            int r = i4 << 2;
            Xs[(r + 0) * TOK + tok] = ev.x;
            Xs[(r + 1) * TOK + tok] = ev.y;
            Xs[(r + 2) * TOK + tok] = ev.z;
            Xs[(r + 3) * TOK + tok] = ev.w;
        }
    }
    __syncthreads();

    const int tx   = tid % TX;
    const int ty   = tid / TX;
    const int trow = ty * MI;
    const int tcol = tx * MJ;

    float mx[MI][MJ];
    #pragma unroll
    for (int i = 0; i < MI; i++)
        #pragma unroll
        for (int j = 0; j < MJ; j++) mx[i][j] = -1e30f;

    const int NPOS = 51 - W;
    for (int l = 0; l < NPOS; ++l) {
        float acc[MI][MJ];
        #pragma unroll
        for (int i = 0; i < MI; i++)
            #pragma unroll
            for (int j = 0; j < MJ; j++) acc[i][j] = 0.f;

        const float* xb = Xs + l * 16 * TOK + trow;
        const float* wb = Ws + tcol;
        #pragma unroll 16
        for (int kk = 0; kk < KDIM; ++kk) {
            float a[MI], b[MJ];
            #pragma unroll
            for (int i = 0; i < MI; i++) a[i] = xb[kk * TOK + i];
            #pragma unroll
            for (int j = 0; j < MJ; j++) b[j] = wb[kk * FILT + j];
            #pragma unroll
            for (int i = 0; i < MI; i++)
                #pragma unroll
                for (int j = 0; j < MJ; j++) acc[i][j] += a[i] * b[j];
        }
        #pragma unroll
        for (int i = 0; i < MI; i++)
            #pragma unroll
            for (int j = 0; j < MJ; j++) mx[i][j] = fmaxf(mx[i][j], acc[i][j]);
    }

    #pragma unroll
    for (int i = 0; i < MI; i++) {
        int row = n0 + trow + i;
        #pragma unroll
        for (int j = 0; j < MJ; j++) {
            float v = mx[i][j] + cb[f0 + tcol + j];   // max(y+b) = max(y)+b
            tout[row * TOTF + colBase + f0 + tcol + j] = fmaxf(v, 0.f);
        }
    }
}

// ---------------------------------------------------------------------------
// Highway layer: p = t @ W + b ; nl = p[:, :2048], gate = p[:, 2048:]
// t_new = sigmoid(gate)*t + (1-sigmoid(gate))*relu(nl)
// One block: 64 rows x 64 output columns; computes BOTH halves (dual B tiles).
// ---------------------------------------------------------------------------
__global__ __launch_bounds__(256)
void highway_kernel(const float* __restrict__ tin, const float* __restrict__ w,
                    const float* __restrict__ b, float* __restrict__ tout)
{
    __shared__ float As[16][64];
    __shared__ float Bn[16][64];
    __shared__ float Bg[16][64];
    const int m0  = blockIdx.y * 64;
    const int j0  = blockIdx.x * 64;
    const int tid = threadIdx.x;
    const int tx  = tid % 16, ty = tid / 16;

    float aN[4][4], aG[4][4];
    #pragma unroll
    for (int i = 0; i < 4; i++)
        #pragma unroll
        for (int j = 0; j < 4; j++) { aN[i][j] = 0.f; aG[i][j] = 0.f; }

    const int ar = tid >> 2;         // 0..63 A row
    const int ac = (tid & 3) << 2;   // 0,4,8,12 k group
    const int br = tid >> 4;         // 0..15 k row
    const int bc = (tid & 15) << 2;  // col group

    for (int k0 = 0; k0 < TOTF; k0 += 16) {
        float4 av = *(const float4*)&tin[(m0 + ar) * TOTF + k0 + ac];
        const float* wr = &w[(size_t)(k0 + br) * (2 * TOTF) + j0 + bc];
        float4 bnv = *(const float4*)wr;
        float4 bgv = *(const float4*)(wr + TOTF);
        __syncthreads();
        As[ac + 0][ar] = av.x; As[ac + 1][ar] = av.y;
        As[ac + 2][ar] = av.z; As[ac + 3][ar] = av.w;
        *(float4*)&Bn[br][bc] = bnv;
        *(float4*)&Bg[br][bc] = bgv;
        __syncthreads();
        #pragma unroll
        for (int kk = 0; kk < 16; ++kk) {
            float4 a  = *(const float4*)&As[kk][ty * 4];
            float4 bn = *(const float4*)&Bn[kk][tx * 4];
            float4 bg = *(const float4*)&Bg[kk][tx * 4];
            float aa[4] = {a.x, a.y, a.z, a.w};
            float nn[4] = {bn.x, bn.y, bn.z, bn.w};
            float gg[4] = {bg.x, bg.y, bg.z, bg.w};
            #pragma unroll
            for (int i = 0; i < 4; i++)
                #pragma unroll
                for (int j = 0; j < 4; j++) {
                    aN[i][j] += aa[i] * nn[j];
                    aG[i][j] += aa[i] * gg[j];
                }
        }
    }

    #pragma unroll
    for (int j = 0; j < 4; ++j) {
        int jc = j0 + tx * 4 + j;
        float bn = b[jc];
        float bg = b[jc + TOTF];
        #pragma unroll
        for (int i = 0; i < 4; ++i) {
            int m = m0 + ty * 4 + i;
            float nl = fmaxf(aN[i][j] + bn, 0.f);
            float g  = 1.f / (1.f + expf(-(aG[i][j] + bg)));
            float tv = tin[m * TOTF + jc];
            tout[m * TOTF + jc] = g * tv + (1.f - g) * nl;
        }
    }
}

// ---------------------------------------------------------------------------
// Projection: out = t @ proj_w[2048,768] + proj_b
// ---------------------------------------------------------------------------
__global__ __launch_bounds__(256)
void proj_kernel(const float* __restrict__ tin, const float* __restrict__ w,
                 const float* __restrict__ b, float* __restrict__ outp)
{
    __shared__ float As[16][64];
    __shared__ float Bs[16][64];
    const int m0  = blockIdx.y * 64;
    const int j0  = blockIdx.x * 64;
    const int tid = threadIdx.x;
    const int tx  = tid % 16, ty = tid / 16;

    float acc[4][4];
    #pragma unroll
    for (int i = 0; i < 4; i++)
        #pragma unroll
        for (int j = 0; j < 4; j++) acc[i][j] = 0.f;

    const int ar = tid >> 2;
    const int ac = (tid & 3) << 2;
    const int br = tid >> 4;
    const int bc = (tid & 15) << 2;

    for (int k0 = 0; k0 < TOTF; k0 += 16) {
        float4 av = *(const float4*)&tin[(m0 + ar) * TOTF + k0 + ac];
        float4 bv = *(const float4*)&w[(size_t)(k0 + br) * HID + j0 + bc];
        __syncthreads();
        As[ac + 0][ar] = av.x; As[ac + 1][ar] = av.y;
        As[ac + 2][ar] = av.z; As[ac + 3][ar] = av.w;
        *(float4*)&Bs[br][bc] = bv;
        __syncthreads();
        #pragma unroll
        for (int kk = 0; kk < 16; ++kk) {
            float4 a = *(const float4*)&As[kk][ty * 4];
            float4 bb = *(const float4*)&Bs[kk][tx * 4];
            float aa[4] = {a.x, a.y, a.z, a.w};
            float bbv[4] = {bb.x, bb.y, bb.z, bb.w};
            #pragma unroll
            for (int i = 0; i < 4; i++)
                #pragma unroll
                for (int j = 0; j < 4; j++) acc[i][j] += aa[i] * bbv[j];
        }
    }

    #pragma unroll
    for (int j = 0; j < 4; ++j) {
        int jc = j0 + tx * 4 + j;
        float bj = b[jc];
        #pragma unroll
        for (int i = 0; i < 4; ++i) {
            int m = m0 + ty * 4 + i;
            outp[m * HID + jc] = acc[i][j] + bj;
        }
    }
}

// ---------------------------------------------------------------------------
template<int W, int FILT, int TX, int TY, int MI, int MJ>
static void launch_conv(const int* ids, const float* emb, const float* cw,
                        const float* cb, float* tout, int colBase, int tiles)
{
    size_t smem = (size_t)(800 * 32 + 16 * W * FILT) * sizeof(float);
    cudaFuncSetAttribute(conv_kernel<W, FILT, TX, TY, MI, MJ>,
                         cudaFuncAttributeMaxDynamicSharedMemorySize, (int)smem);
    conv_kernel<W, FILT, TX, TY, MI, MJ>
        <<<dim3(N_TOK / 32, tiles), 256, smem>>>(ids, emb, cw, cb, tout, colBase);
}

extern "C" void kernel_launch(void* const* d_in, const int* in_sizes, int n_in,
                              void* d_out, int out_size)
{
    const int*   ids = (const int*)  d_in[0];
    const float* emb = (const float*)d_in[1];
    const float* cw[7]; const float* cb[7];
    for (int i = 0; i < 7; i++) {
        cw[i] = (const float*)d_in[2 + 2 * i];
        cb[i] = (const float*)d_in[3 + 2 * i];
    }
    const float* hw_w0 = (const float*)d_in[16];
    const float* hw_b0 = (const float*)d_in[17];
    const float* hw_w1 = (const float*)d_in[18];
    const float* hw_b1 = (const float*)d_in[19];
    const float* pw    = (const float*)d_in[20];
    const float* pb    = (const float*)d_in[21];
    float* out = (float*)d_out;

    float *pT = nullptr, *pT2 = nullptr;
    cudaGetSymbolAddress((void**)&pT,  g_T);
    cudaGetSymbolAddress((void**)&pT2, g_T2);

    // Conv per width: (W, FILT, TX, TY, MI, MJ), filter tiles, column base
    launch_conv<1,  32,  8, 32, 1, 4>(ids, emb, cw[0], cb[0], pT,    0, 1);
    launch_conv<2,  32,  8, 32, 1, 4>(ids, emb, cw[1], cb[1], pT,   32, 1);
    launch_conv<3,  64, 16, 16, 2, 4>(ids, emb, cw[2], cb[2], pT,   64, 1);
    launch_conv<4, 128, 32,  8, 4, 4>(ids, emb, cw[3], cb[3], pT,  128, 1);
    launch_conv<5, 128, 32,  8, 4, 4>(ids, emb, cw[4], cb[4], pT,  256, 2);
    launch_conv<6, 128, 32,  8, 4, 4>(ids, emb, cw[5], cb[5], pT,  512, 4);
    launch_conv<7, 128, 32,  8, 4, 4>(ids, emb, cw[6], cb[6], pT, 1024, 8);

    // Highway x2 (ping-pong)
    highway_kernel<<<dim3(TOTF / 64, N_TOK / 64), 256>>>(pT,  hw_w0, hw_b0, pT2);
    highway_kernel<<<dim3(TOTF / 64, N_TOK / 64), 256>>>(pT2, hw_w1, hw_b1, pT);

    // Projection
    proj_kernel<<<dim3(HID / 64, N_TOK / 64), 256>>>(pT, pw, pb, out);
}

// round 3
// speedup vs baseline: 1.4168x; 1.4168x over previous
#include <cuda_runtime.h>
#include <cuda_bf16.h>
#include <math.h>
#include <stdint.h>

#define N_TOK 4096
#define TOTF  2048
#define HID   768

__device__ float g_T [N_TOK * TOTF];
__device__ float g_T2[N_TOK * TOTF];

// ---------------------------------------------------------------------------
__device__ __forceinline__ uint32_t smem_u32(const void* p) {
    uint32_t a;
    asm("{ .reg .u64 t; cvta.to.shared.u64 t, %1; cvt.u32.u64 %0, t; }"
        : "=r"(a) : "l"(p));
    return a;
}
#define STS128(addr, a, b, c, d) \
    asm volatile("st.shared.v4.b32 [%0], {%1,%2,%3,%4};" \
                 :: "r"(addr), "r"(a), "r"(b), "r"(c), "r"(d) : "memory")
#define STS64F(addr, x, y) \
    asm volatile("st.shared.v2.f32 [%0], {%1,%2};" \
                 :: "r"(addr), "f"(x), "f"(y) : "memory")

__device__ __forceinline__ void ldsm4(uint32_t a, uint32_t* r) {
    asm volatile("ldmatrix.sync.aligned.m8n8.x4.shared.b16 {%0,%1,%2,%3}, [%4];"
                 : "=r"(r[0]), "=r"(r[1]), "=r"(r[2]), "=r"(r[3]) : "r"(a));
}
__device__ __forceinline__ void ldsm4t(uint32_t a, uint32_t* r) {
    asm volatile("ldmatrix.sync.aligned.m8n8.x4.trans.shared.b16 {%0,%1,%2,%3}, [%4];"
                 : "=r"(r[0]), "=r"(r[1]), "=r"(r[2]), "=r"(r[3]) : "r"(a));
}
__device__ __forceinline__ void mma16816(float* c, const uint32_t* a, const uint32_t* b) {
    asm volatile("mma.sync.aligned.m16n8k16.row.col.f32.bf16.bf16.f32 "
                 "{%0,%1,%2,%3}, {%4,%5,%6,%7}, {%8,%9}, {%0,%1,%2,%3};"
                 : "+f"(c[0]), "+f"(c[1]), "+f"(c[2]), "+f"(c[3])
                 : "r"(a[0]), "r"(a[1]), "r"(a[2]), "r"(a[3]), "r"(b[0]), "r"(b[1]));
}
// pack two floats into bf16x2 (hi part) and residual bf16x2 (lo part)
__device__ __forceinline__ void split2(float x0, float x1, uint32_t& hp, uint32_t& lp) {
    asm("cvt.rn.bf16x2.f32 %0, %1, %2;" : "=r"(hp) : "f"(x1), "f"(x0));
    float h0 = __uint_as_float(hp << 16);
    float h1 = __uint_as_float(hp & 0xFFFF0000u);
    float r0 = x0 - h0, r1 = x1 - h1;
    asm("cvt.rn.bf16x2.f32 %0, %1, %2;" : "=r"(lp) : "f"(r1), "f"(r0));
}

// ===========================================================================
// Conv + maxpool + relu (at fp32 roofline — unchanged)
// ===========================================================================
template<int W, int FILT, int TX, int TY, int MI, int MJ>
__global__ __launch_bounds__(256)
void conv_kernel(const int* __restrict__ ids, const float* __restrict__ emb,
                 const float* __restrict__ cw, const float* __restrict__ cb,
                 float* __restrict__ tout, int colBase)
{
    constexpr int TOK  = 32;
    constexpr int KDIM = 16 * W;
    extern __shared__ float sm[];
    float* Xs = sm;
    float* Ws = sm + 800 * TOK;

    const int n0  = blockIdx.x * TOK;
    const int f0  = blockIdx.y * FILT;
    const int tid = threadIdx.x;

    for (int i = tid; i < FILT * KDIM; i += 256) {
        int fl = i % FILT;
        int rc = i / FILT;
        int k = rc >> 4, c = rc & 15;
        Ws[i] = cw[((f0 + fl) * 16 + c) * W + k];
    }
    {
        int tok  = tid >> 3;
        int lane = tid & 7;
        const int* idrow = ids + (n0 + tok) * 50;
        for (int i4 = lane; i4 < 200; i4 += 8) {
            int l  = i4 >> 2;
            int cg = (i4 & 3) << 2;
            int id = idrow[l];
            float4 ev = *(const float4*)(emb + id * 16 + cg);
            int r = i4 << 2;
            Xs[(r + 0) * TOK + tok] = ev.x;
            Xs[(r + 1) * TOK + tok] = ev.y;
            Xs[(r + 2) * TOK + tok] = ev.z;
            Xs[(r + 3) * TOK + tok] = ev.w;
        }
    }
    __syncthreads();

    const int tx = tid % TX;
    const int ty = tid / TX;
    const int trow = ty * MI;
    const int tcol = tx * MJ;

    float mx[MI][MJ];
    #pragma unroll
    for (int i = 0; i < MI; i++)
        #pragma unroll
        for (int j = 0; j < MJ; j++) mx[i][j] = -1e30f;

    const int NPOS = 51 - W;
    for (int l = 0; l < NPOS; ++l) {
        float acc[MI][MJ];
        #pragma unroll
        for (int i = 0; i < MI; i++)
            #pragma unroll
            for (int j = 0; j < MJ; j++) acc[i][j] = 0.f;

        const float* xb = Xs + l * 16 * TOK + trow;
        const float* wb = Ws + tcol;
        #pragma unroll 16
        for (int kk = 0; kk < KDIM; ++kk) {
            float a[MI], b[MJ];
            #pragma unroll
            for (int i = 0; i < MI; i++) a[i] = xb[kk * TOK + i];
            #pragma unroll
            for (int j = 0; j < MJ; j++) b[j] = wb[kk * FILT + j];
            #pragma unroll
            for (int i = 0; i < MI; i++)
                #pragma unroll
                for (int j = 0; j < MJ; j++) acc[i][j] += a[i] * b[j];
        }
        #pragma unroll
        for (int i = 0; i < MI; i++)
            #pragma unroll
            for (int j = 0; j < MJ; j++) mx[i][j] = fmaxf(mx[i][j], acc[i][j]);
    }

    #pragma unroll
    for (int i = 0; i < MI; i++) {
        int row = n0 + trow + i;
        #pragma unroll
        for (int j = 0; j < MJ; j++) {
            float v = mx[i][j] + cb[f0 + tcol + j];
            tout[row * TOTF + colBase + f0 + tcol + j] = fmaxf(v, 0.f);
        }
    }
}

// ===========================================================================
// bf16x3 GEMM on mma.sync (HMMA). Block tile 128x128, warps 2x4 (64x32 each),
// K chunk 32, double-buffered smem, software pipeline.
//   HW=true : tile cols [0,64)=nl, [64,128)=gate (w cols +2048); gating epilogue
//   HW=false: plain GEMM + bias (projection)
// ===========================================================================
#define ASTRIDE 40     // bf16 elems per A row (32 + 8 pad)
#define BSTRIDE 136    // bf16 elems per B row (128 + 8 pad)
#define AHI 0
#define ALO 10240      // 128*40*2
#define BHI 20480
#define BLO 29184      // +32*136*2
#define BUFB 37888
#define GEMM_SMEM (2 * BUFB)   // 75776 ; C smem (128*132*4=67584) reuses it

template<bool HW>
__global__ __launch_bounds__(256, 1)
void gemm_kernel(const float* __restrict__ tin, const float* __restrict__ w,
                 const float* __restrict__ bias, float* __restrict__ outp)
{
    extern __shared__ char smg[];
    const uint32_t sb = smem_u32(smg);
    const int tid  = threadIdx.x;
    const int lane = tid & 31, wid = tid >> 5;
    const int wm = wid >> 2, wn = wid & 3;        // 2 x 4 warp grid
    const int m0 = blockIdx.y * 128;
    const int bx = blockIdx.x;
    const int LDW = HW ? (2 * TOTF) : HID;

    // ---- staging assignments ----
    const int arow = tid >> 1;
    const int acs  = (tid & 1) * 16;              // A col segment
    const float* aptr = tin + (size_t)(m0 + arow) * TOTF + acs;
    const int bkr = tid >> 3;
    const int bsg = tid & 7;                      // B col segment (16 cols)
    int bcol;
    if (HW) bcol = (bsg < 4) ? bx * 64 + bsg * 16 : TOTF + bx * 64 + (bsg - 4) * 16;
    else    bcol = bx * 128 + bsg * 16;
    const float* bptr = w + (size_t)bkr * LDW + bcol;

    const uint32_t adst = (uint32_t)((arow * ASTRIDE + acs) * 2);
    const uint32_t bdst = (uint32_t)((bkr * BSTRIDE + bsg * 16) * 2);

    float C[4][4][4];
    #pragma unroll
    for (int mi = 0; mi < 4; mi++)
        #pragma unroll
        for (int ni = 0; ni < 4; ni++)
            #pragma unroll
            for (int q = 0; q < 4; q++) C[mi][ni][q] = 0.f;

    float ar[16], br[16];

    // gload: chunk k0
    auto GLOAD = [&](int k0) {
        #pragma unroll
        for (int i = 0; i < 4; ++i) {
            float4 v = *(const float4*)(aptr + k0 + i * 4);
            ar[i * 4 + 0] = v.x; ar[i * 4 + 1] = v.y;
            ar[i * 4 + 2] = v.z; ar[i * 4 + 3] = v.w;
        }
        const float* bp = bptr + (size_t)k0 * LDW;
        #pragma unroll
        for (int i = 0; i < 4; ++i) {
            float4 v = *(const float4*)(bp + i * 4);
            br[i * 4 + 0] = v.x; br[i * 4 + 1] = v.y;
            br[i * 4 + 2] = v.z; br[i * 4 + 3] = v.w;
        }
    };
    auto CVTSTS = [&](int b) {
        const uint32_t base = sb + (uint32_t)b * BUFB;
        uint32_t hp[8], lp[8];
        #pragma unroll
        for (int j = 0; j < 8; ++j) split2(ar[2 * j], ar[2 * j + 1], hp[j], lp[j]);
        STS128(base + AHI + adst,      hp[0], hp[1], hp[2], hp[3]);
        STS128(base + AHI + adst + 16, hp[4], hp[5], hp[6], hp[7]);
        STS128(base + ALO + adst,      lp[0], lp[1], lp[2], lp[3]);
        STS128(base + ALO + adst + 16, lp[4], lp[5], lp[6], lp[7]);
        #pragma unroll
        for (int j = 0; j < 8; ++j) split2(br[2 * j], br[2 * j + 1], hp[j], lp[j]);
        STS128(base + BHI + bdst,      hp[0], hp[1], hp[2], hp[3]);
        STS128(base + BHI + bdst + 16, hp[4], hp[5], hp[6], hp[7]);
        STS128(base + BLO + bdst,      lp[0], lp[1], lp[2], lp[3]);
        STS128(base + BLO + bdst + 16, lp[4], lp[5], lp[6], lp[7]);
    };

    // lane components for ldmatrix
    const uint32_t a_ln = (uint32_t)(((wm * 64 + (lane & 15)) * ASTRIDE + (lane >> 4) * 8) * 2);
    const uint32_t b_ln = (uint32_t)(((lane & 15) * BSTRIDE + wn * 32 + (lane >> 4) * 8) * 2);

    // ---- pipeline ----
    GLOAD(0);
    CVTSTS(0);
    GLOAD(32);

    const int NCH = TOTF / 32;   // 64
    for (int ci = 0; ci < NCH; ++ci) {
        __syncthreads();
        if (ci + 1 < NCH) CVTSTS((ci + 1) & 1);
        if (ci + 2 < NCH) GLOAD((ci + 2) * 32);

        const uint32_t base = sb + (uint32_t)(ci & 1) * BUFB;
        #pragma unroll
        for (int ks = 0; ks < 2; ++ks) {
            uint32_t ahi[4][4], alo[4][4], bhi[4][2], blo[4][2];
            const uint32_t aad = base + AHI + a_ln + (uint32_t)(ks * 32);
            #pragma unroll
            for (int mi = 0; mi < 4; mi++) {
                ldsm4(aad + mi * (16 * ASTRIDE * 2), ahi[mi]);
                ldsm4(aad + (ALO - AHI) + mi * (16 * ASTRIDE * 2), alo[mi]);
            }
            const uint32_t bad = base + BHI + b_ln + (uint32_t)(ks * 16 * BSTRIDE * 2);
            #pragma unroll
            for (int ng = 0; ng < 2; ng++) {
                uint32_t t[4];
                ldsm4t(bad + ng * 32, t);
                bhi[2 * ng][0] = t[0]; bhi[2 * ng][1] = t[1];
                bhi[2 * ng + 1][0] = t[2]; bhi[2 * ng + 1][1] = t[3];
                ldsm4t(bad + (BLO - BHI) + ng * 32, t);
                blo[2 * ng][0] = t[0]; blo[2 * ng][1] = t[1];
                blo[2 * ng + 1][0] = t[2]; blo[2 * ng + 1][1] = t[3];
            }
            #pragma unroll
            for (int mi = 0; mi < 4; mi++)
                #pragma unroll
                for (int ni = 0; ni < 4; ni++) {
                    mma16816(C[mi][ni], ahi[mi], bhi[ni]);
                    mma16816(C[mi][ni], ahi[mi], blo[ni]);
                    mma16816(C[mi][ni], alo[mi], bhi[ni]);
                }
        }
    }

    // ---- epilogue: fragments -> smem C [128][132] f32 ----
    __syncthreads();
    const int crow  = wm * 64 + (lane >> 2);
    const int ccol0 = wn * 32 + (lane & 3) * 2;
    #pragma unroll
    for (int mi = 0; mi < 4; mi++)
        #pragma unroll
        for (int ni = 0; ni < 4; ni++) {
            uint32_t o0 = sb + (uint32_t)(((crow + mi * 16) * 132 + ccol0 + ni * 8) * 4);
            STS64F(o0, C[mi][ni][0], C[mi][ni][1]);
            STS64F(o0 + (uint32_t)(8 * 132 * 4), C[mi][ni][2], C[mi][ni][3]);
        }
    __syncthreads();

    const float* Cs = (const float*)smg;
    if (HW) {
        const int j0h = bx * 64;
        #pragma unroll 4
        for (int t = 0; t < 32; ++t) {
            int idx = t * 256 + tid;
            int m = idx >> 6, u = idx & 63;
            float nl = fmaxf(Cs[m * 132 + u] + bias[j0h + u], 0.f);
            float gv = Cs[m * 132 + 64 + u] + bias[TOTF + j0h + u];
            float g  = 1.f / (1.f + __expf(-gv));
            float tv = tin[(size_t)(m0 + m) * TOTF + j0h + u];
            outp[(size_t)(m0 + m) * TOTF + j0h + u] = g * tv + (1.f - g) * nl;
        }
    } else {
        const int j0 = bx * 128;
        #pragma unroll 4
        for (int t = 0; t < 64; ++t) {
            int idx = t * 256 + tid;
            int m = idx >> 7, n = idx & 127;
            outp[(size_t)(m0 + m) * HID + j0 + n] = Cs[m * 132 + n] + bias[j0 + n];
        }
    }
}

// ---------------------------------------------------------------------------
template<int W, int FILT, int TX, int TY, int MI, int MJ>
static void launch_conv(const int* ids, const float* emb, const float* cw,
                        const float* cb, float* tout, int colBase, int tiles)
{
    size_t smem = (size_t)(800 * 32 + 16 * W * FILT) * sizeof(float);
    cudaFuncSetAttribute(conv_kernel<W, FILT, TX, TY, MI, MJ>,
                         cudaFuncAttributeMaxDynamicSharedMemorySize, (int)smem);
    conv_kernel<W, FILT, TX, TY, MI, MJ>
        <<<dim3(N_TOK / 32, tiles), 256, smem>>>(ids, emb, cw, cb, tout, colBase);
}

extern "C" void kernel_launch(void* const* d_in, const int* in_sizes, int n_in,
                              void* d_out, int out_size)
{
    const int*   ids = (const int*)  d_in[0];
    const float* emb = (const float*)d_in[1];
    const float* cw[7]; const float* cb[7];
    for (int i = 0; i < 7; i++) {
        cw[i] = (const float*)d_in[2 + 2 * i];
        cb[i] = (const float*)d_in[3 + 2 * i];
    }
    const float* hw_w0 = (const float*)d_in[16];
    const float* hw_b0 = (const float*)d_in[17];
    const float* hw_w1 = (const float*)d_in[18];
    const float* hw_b1 = (const float*)d_in[19];
    const float* pw    = (const float*)d_in[20];
    const float* pb    = (const float*)d_in[21];
    float* out = (float*)d_out;

    float *pT = nullptr, *pT2 = nullptr;
    cudaGetSymbolAddress((void**)&pT,  g_T);
    cudaGetSymbolAddress((void**)&pT2, g_T2);

    launch_conv<1,  32,  8, 32, 1, 4>(ids, emb, cw[0], cb[0], pT,    0, 1);
    launch_conv<2,  32,  8, 32, 1, 4>(ids, emb, cw[1], cb[1], pT,   32, 1);
    launch_conv<3,  64, 16, 16, 2, 4>(ids, emb, cw[2], cb[2], pT,   64, 1);
    launch_conv<4, 128, 32,  8, 4, 4>(ids, emb, cw[3], cb[3], pT,  128, 1);
    launch_conv<5, 128, 32,  8, 4, 4>(ids, emb, cw[4], cb[4], pT,  256, 2);
    launch_conv<6, 128, 32,  8, 4, 4>(ids, emb, cw[5], cb[5], pT,  512, 4);
    launch_conv<7, 128, 32,  8, 4, 4>(ids, emb, cw[6], cb[6], pT, 1024, 8);

    cudaFuncSetAttribute(gemm_kernel<true>,
                         cudaFuncAttributeMaxDynamicSharedMemorySize, GEMM_SMEM);
    cudaFuncSetAttribute(gemm_kernel<false>,
                         cudaFuncAttributeMaxDynamicSharedMemorySize, GEMM_SMEM);
    gemm_kernel<true><<<dim3(32, 32), 256, GEMM_SMEM>>>(pT,  hw_w0, hw_b0, pT2);
    gemm_kernel<true><<<dim3(32, 32), 256, GEMM_SMEM>>>(pT2, hw_w1, hw_b1, pT);
    gemm_kernel<false><<<dim3(6, 32), 256, GEMM_SMEM>>>(pT, pw, pb, out);
}

// round 4
// speedup vs baseline: 2.0604x; 1.4542x over previous
#include <cuda_runtime.h>
#include <cuda_bf16.h>
#include <math.h>
#include <stdint.h>

#define N_TOK 4096
#define TOTF  2048
#define HID   768
#define VOCABN 264

__device__ float g_T [N_TOK * TOTF];
__device__ float g_T2[N_TOK * TOTF];

// pre-split bf16 hi/lo tables (written by prep kernels each launch)
__device__ __align__(16) __nv_bfloat16 g_ehi[VOCABN * 16];
__device__ __align__(16) __nv_bfloat16 g_elo[VOCABN * 16];
#define WSP_TOT 195584
__device__ __align__(16) __nv_bfloat16 g_wsp_hi[WSP_TOT];
__device__ __align__(16) __nv_bfloat16 g_wsp_lo[WSP_TOT];
// offsets (elems): w3:0  w4:3072  w5:11264  w6:31744  w7:80896

// ---------------------------------------------------------------------------
__device__ __forceinline__ uint32_t smem_u32(const void* p) {
    uint32_t a;
    asm("{ .reg .u64 t; cvta.to.shared.u64 t, %1; cvt.u32.u64 %0, t; }"
        : "=r"(a) : "l"(p));
    return a;
}
#define STS128(addr, a, b, c, d) \
    asm volatile("st.shared.v4.b32 [%0], {%1,%2,%3,%4};" \
                 :: "r"(addr), "r"(a), "r"(b), "r"(c), "r"(d) : "memory")
#define STS64F(addr, x, y) \
    asm volatile("st.shared.v2.f32 [%0], {%1,%2};" \
                 :: "r"(addr), "f"(x), "f"(y) : "memory")

__device__ __forceinline__ void ldsm4(uint32_t a, uint32_t* r) {
    asm volatile("ldmatrix.sync.aligned.m8n8.x4.shared.b16 {%0,%1,%2,%3}, [%4];"
                 : "=r"(r[0]), "=r"(r[1]), "=r"(r[2]), "=r"(r[3]) : "r"(a));
}
__device__ __forceinline__ void ldsm4t(uint32_t a, uint32_t* r) {
    asm volatile("ldmatrix.sync.aligned.m8n8.x4.trans.shared.b16 {%0,%1,%2,%3}, [%4];"
                 : "=r"(r[0]), "=r"(r[1]), "=r"(r[2]), "=r"(r[3]) : "r"(a));
}
__device__ __forceinline__ void mma16816(float* c, const uint32_t* a, const uint32_t* b) {
    asm volatile("mma.sync.aligned.m16n8k16.row.col.f32.bf16.bf16.f32 "
                 "{%0,%1,%2,%3}, {%4,%5,%6,%7}, {%8,%9}, {%0,%1,%2,%3};"
                 : "+f"(c[0]), "+f"(c[1]), "+f"(c[2]), "+f"(c[3])
                 : "r"(a[0]), "r"(a[1]), "r"(a[2]), "r"(a[3]), "r"(b[0]), "r"(b[1]));
}
__device__ __forceinline__ void split2(float x0, float x1, uint32_t& hp, uint32_t& lp) {
    asm("cvt.rn.bf16x2.f32 %0, %1, %2;" : "=r"(hp) : "f"(x1), "f"(x0));
    float h0 = __uint_as_float(hp << 16);
    float h1 = __uint_as_float(hp & 0xFFFF0000u);
    float r0 = x0 - h0, r1 = x1 - h1;
    asm("cvt.rn.bf16x2.f32 %0, %1, %2;" : "=r"(lp) : "f"(r1), "f"(r0));
}

// ===========================================================================
// Prep: split emb + conv weights into bf16 hi/lo globals
// ===========================================================================
__global__ void prep_emb_kernel(const float* __restrict__ emb) {
    int i = blockIdx.x * 256 + threadIdx.x;
    if (i < VOCABN * 16) {
        float v = emb[i];
        __nv_bfloat16 h = __float2bfloat16(v);
        g_ehi[i] = h;
        g_elo[i] = __float2bfloat16(v - __bfloat162float(h));
    }
}
template<int W, int NF>
__global__ void prep_w_kernel(const float* __restrict__ cw, int off) {
    int i = blockIdx.x * 256 + threadIdx.x;
    if (i < 16 * W * NF) {
        int row = i / NF, f = i - row * NF;
        int c = row & 15, k = row >> 4;
        float v = cw[(f * 16 + c) * W + k];
        __nv_bfloat16 h = __float2bfloat16(v);
        g_wsp_hi[off + i] = h;
        g_wsp_lo[off + i] = __float2bfloat16(v - __bfloat162float(h));
    }
}

// ===========================================================================
// fp32 SIMT conv (w=1,2 only — 3% of flops)
// ===========================================================================
template<int W, int FILT, int TX, int TY, int MI, int MJ>
__global__ __launch_bounds__(256)
void conv_kernel(const int* __restrict__ ids, const float* __restrict__ emb,
                 const float* __restrict__ cw, const float* __restrict__ cb,
                 float* __restrict__ tout, int colBase)
{
    constexpr int TOK  = 32;
    constexpr int KDIM = 16 * W;
    extern __shared__ float sm[];
    float* Xs = sm;
    float* Ws = sm + 800 * TOK;

    const int n0  = blockIdx.x * TOK;
    const int f0  = blockIdx.y * FILT;
    const int tid = threadIdx.x;

    for (int i = tid; i < FILT * KDIM; i += 256) {
        int fl = i % FILT;
        int rc = i / FILT;
        int k = rc >> 4, c = rc & 15;
        Ws[i] = cw[((f0 + fl) * 16 + c) * W + k];
    }
    {
        int tok  = tid >> 3;
        int lane = tid & 7;
        const int* idrow = ids + (n0 + tok) * 50;
        for (int i4 = lane; i4 < 200; i4 += 8) {
            int l  = i4 >> 2;
            int cg = (i4 & 3) << 2;
            int id = idrow[l];
            float4 ev = *(const float4*)(emb + id * 16 + cg);
            int r = i4 << 2;
            Xs[(r + 0) * TOK + tok] = ev.x;
            Xs[(r + 1) * TOK + tok] = ev.y;
            Xs[(r + 2) * TOK + tok] = ev.z;
            Xs[(r + 3) * TOK + tok] = ev.w;
        }
    }
    __syncthreads();

    const int tx = tid % TX;
    const int ty = tid / TX;
    const int trow = ty * MI;
    const int tcol = tx * MJ;

    float mx[MI][MJ];
    #pragma unroll
    for (int i = 0; i < MI; i++)
        #pragma unroll
        for (int j = 0; j < MJ; j++) mx[i][j] = -1e30f;

    const int NPOS = 51 - W;
    for (int l = 0; l < NPOS; ++l) {
        float acc[MI][MJ];
        #pragma unroll
        for (int i = 0; i < MI; i++)
            #pragma unroll
            for (int j = 0; j < MJ; j++) acc[i][j] = 0.f;

        const float* xb = Xs + l * 16 * TOK + trow;
        const float* wb = Ws + tcol;
        #pragma unroll 16
        for (int kk = 0; kk < KDIM; ++kk) {
            float a[MI], b[MJ];
            #pragma unroll
            for (int i = 0; i < MI; i++) a[i] = xb[kk * TOK + i];
            #pragma unroll
            for (int j = 0; j < MJ; j++) b[j] = wb[kk * FILT + j];
            #pragma unroll
            for (int i = 0; i < MI; i++)
                #pragma unroll
                for (int j = 0; j < MJ; j++) acc[i][j] += a[i] * b[j];
        }
        #pragma unroll
        for (int i = 0; i < MI; i++)
            #pragma unroll
            for (int j = 0; j < MJ; j++) mx[i][j] = fmaxf(mx[i][j], acc[i][j]);
    }

    #pragma unroll
    for (int i = 0; i < MI; i++) {
        int row = n0 + trow + i;
        #pragma unroll
        for (int j = 0; j < MJ; j++) {
            float v = mx[i][j] + cb[f0 + tcol + j];
            tout[row * TOTF + colBase + f0 + tcol + j] = fmaxf(v, 0.f);
        }
    }
}

// ===========================================================================
// HMMA conv (w=3..7): block = 8 tokens x 64 filters; warp = 1 token.
// X smem per token: 56 rows x 48B (16 bf16 data + pad), hi/lo planes.
// Step k: A tile = X rows offset by k (no im2col). B = W[k*16+c][f].
// ===========================================================================
#define CX_LO 21504u           // 8 tok * 56 * 48
#define CX_W  43008u

template<int W, int NF>
__global__ __launch_bounds__(256)
void conv_mma_kernel(const int* __restrict__ ids, const float* __restrict__ cb,
                     float* __restrict__ tout, int colBase, int wOff)
{
    constexpr int KD = 16 * W;
    constexpr int NPOS = 51 - W;
    extern __shared__ char smc[];
    const uint32_t sb = smem_u32(smc);
    const uint32_t WLO = CX_W + (uint32_t)KD * 144u;
    const int tid = threadIdx.x;
    const int lane = tid & 31, wid = tid >> 5;
    const int n0 = blockIdx.x * 8;
    const int f0 = blockIdx.y * 64;

    // ---- stage X (bf16 hi/lo, rows 50..55 zero) ----
    for (int t = tid; t < 448; t += 256) {
        int tok = t / 56, r = t - tok * 56;
        uint32_t dst = sb + (uint32_t)(tok * 2688 + r * 48);
        if (r < 50) {
            int id = ids[(n0 + tok) * 50 + r];
            const uint4* eh = (const uint4*)(g_ehi + id * 16);
            const uint4* el = (const uint4*)(g_elo + id * 16);
            uint4 h0 = eh[0], h1 = eh[1];
            uint4 l0 = el[0], l1 = el[1];
            STS128(dst,          h0.x, h0.y, h0.z, h0.w);
            STS128(dst + 16,     h1.x, h1.y, h1.z, h1.w);
            STS128(dst + CX_LO,      l0.x, l0.y, l0.z, l0.w);
            STS128(dst + CX_LO + 16, l1.x, l1.y, l1.z, l1.w);
        } else {
            STS128(dst, 0u, 0u, 0u, 0u);
            STS128(dst + 16, 0u, 0u, 0u, 0u);
            STS128(dst + CX_LO, 0u, 0u, 0u, 0u);
            STS128(dst + CX_LO + 16, 0u, 0u, 0u, 0u);
        }
    }
    // ---- stage weights (coalesced from pre-split globals) ----
    for (int t = tid; t < KD * 8; t += 256) {
        int row = t >> 3, seg = t & 7;
        int gsrc = wOff + row * NF + f0 + seg * 8;
        uint4 h = *(const uint4*)(g_wsp_hi + gsrc);
        uint4 l = *(const uint4*)(g_wsp_lo + gsrc);
        uint32_t d = sb + CX_W + (uint32_t)(row * 144 + seg * 16);
        STS128(d, h.x, h.y, h.z, h.w);
        STS128(d + (WLO - CX_W), l.x, l.y, l.z, l.w);
    }
    __syncthreads();

    // ---- MMA mainloop ----
    float C[3][8][4];
    #pragma unroll
    for (int mi = 0; mi < 3; mi++)
        #pragma unroll
        for (int nf = 0; nf < 8; nf++)
            #pragma unroll
            for (int q = 0; q < 4; q++) C[mi][nf][q] = 0.f;

    const uint32_t xb = sb + (uint32_t)(wid * 2688 + (lane & 15) * 48 + (lane >> 4) * 16);
    const uint32_t bb = sb + CX_W + (uint32_t)((lane & 15) * 144 + (lane >> 4) * 16);

    #pragma unroll
    for (int k = 0; k < W; ++k) {
        uint32_t ah[3][4], al[3][4];
        #pragma unroll
        for (int mi = 0; mi < 3; mi++) {
            ldsm4(xb + (uint32_t)((mi * 16 + k) * 48), ah[mi]);
            ldsm4(xb + (uint32_t)((mi * 16 + k) * 48) + CX_LO, al[mi]);
        }
        uint32_t bh[8][2], bl[8][2];
        #pragma unroll
        for (int ng = 0; ng < 4; ng++) {
            uint32_t t4[4];
            ldsm4t(bb + (uint32_t)(k * 16 * 144 + ng * 32), t4);
            bh[2*ng][0] = t4[0]; bh[2*ng][1] = t4[1];
            bh[2*ng+1][0] = t4[2]; bh[2*ng+1][1] = t4[3];
            ldsm4t(bb + (WLO - CX_W) + (uint32_t)(k * 16 * 144 + ng * 32), t4);
            bl[2*ng][0] = t4[0]; bl[2*ng][1] = t4[1];
            bl[2*ng+1][0] = t4[2]; bl[2*ng+1][1] = t4[3];
        }
        #pragma unroll
        for (int mi = 0; mi < 3; mi++)
            #pragma unroll
            for (int nf = 0; nf < 8; nf++) {
                mma16816(C[mi][nf], ah[mi], bh[nf]);
                mma16816(C[mi][nf], ah[mi], bl[nf]);
                mma16816(C[mi][nf], al[mi], bh[nf]);
            }
    }

    // ---- maxpool (mask pos>=NPOS) + shfl reduce + bias + relu ----
    float m0[8], m1[8];
    #pragma unroll
    for (int nf = 0; nf < 8; nf++) { m0[nf] = -1e30f; m1[nf] = -1e30f; }
    const int r0 = lane >> 2;
    #pragma unroll
    for (int mi = 0; mi < 3; mi++) {
        bool v0 = (mi * 16 + r0) < NPOS;
        bool v1 = (mi * 16 + r0 + 8) < NPOS;
        #pragma unroll
        for (int nf = 0; nf < 8; nf++) {
            if (v0) { m0[nf] = fmaxf(m0[nf], C[mi][nf][0]);
                      m1[nf] = fmaxf(m1[nf], C[mi][nf][1]); }
            if (v1) { m0[nf] = fmaxf(m0[nf], C[mi][nf][2]);
                      m1[nf] = fmaxf(m1[nf], C[mi][nf][3]); }
        }
    }
    #pragma unroll
    for (int nf = 0; nf < 8; nf++) {
        #pragma unroll
        for (int off = 4; off < 32; off <<= 1) {
            m0[nf] = fmaxf(m0[nf], __shfl_xor_sync(0xffffffffu, m0[nf], off));
            m1[nf] = fmaxf(m1[nf], __shfl_xor_sync(0xffffffffu, m1[nf], off));
        }
    }
    if (lane < 4) {
        const int token = n0 + wid;
        float* orow = tout + (size_t)token * TOTF + colBase + f0;
        #pragma unroll
        for (int nf = 0; nf < 8; nf++) {
            int fl = nf * 8 + lane * 2;
            float2 o;
            o.x = fmaxf(m0[nf] + cb[f0 + fl], 0.f);
            o.y = fmaxf(m1[nf] + cb[f0 + fl + 1], 0.f);
            *(float2*)(orow + fl) = o;
        }
    }
}

// ===========================================================================
// bf16x3 GEMM on mma.sync (unchanged from round 3)
// ===========================================================================
#define ASTRIDE 40
#define BSTRIDE 136
#define AHI 0
#define ALO 10240
#define BHI 20480
#define BLO 29184
#define BUFB 37888
#define GEMM_SMEM (2 * BUFB)

template<bool HW>
__global__ __launch_bounds__(256, 1)
void gemm_kernel(const float* __restrict__ tin, const float* __restrict__ w,
                 const float* __restrict__ bias, float* __restrict__ outp)
{
    extern __shared__ char smg[];
    const uint32_t sb = smem_u32(smg);
    const int tid  = threadIdx.x;
    const int lane = tid & 31, wid = tid >> 5;
    const int wm = wid >> 2, wn = wid & 3;
    const int m0 = blockIdx.y * 128;
    const int bx = blockIdx.x;
    const int LDW = HW ? (2 * TOTF) : HID;

    const int arow = tid >> 1;
    const int acs  = (tid & 1) * 16;
    const float* aptr = tin + (size_t)(m0 + arow) * TOTF + acs;
    const int bkr = tid >> 3;
    const int bsg = tid & 7;
    int bcol;
    if (HW) bcol = (bsg < 4) ? bx * 64 + bsg * 16 : TOTF + bx * 64 + (bsg - 4) * 16;
    else    bcol = bx * 128 + bsg * 16;
    const float* bptr = w + (size_t)bkr * LDW + bcol;

    const uint32_t adst = (uint32_t)((arow * ASTRIDE + acs) * 2);
    const uint32_t bdst = (uint32_t)((bkr * BSTRIDE + bsg * 16) * 2);

    float C[4][4][4];
    #pragma unroll
    for (int mi = 0; mi < 4; mi++)
        #pragma unroll
        for (int ni = 0; ni < 4; ni++)
            #pragma unroll
            for (int q = 0; q < 4; q++) C[mi][ni][q] = 0.f;

    float ar[16], br[16];

    auto GLOAD = [&](int k0) {
        #pragma unroll
        for (int i = 0; i < 4; ++i) {
            float4 v = *(const float4*)(aptr + k0 + i * 4);
            ar[i * 4 + 0] = v.x; ar[i * 4 + 1] = v.y;
            ar[i * 4 + 2] = v.z; ar[i * 4 + 3] = v.w;
        }
        const float* bp = bptr + (size_t)k0 * LDW;
        #pragma unroll
        for (int i = 0; i < 4; ++i) {
            float4 v = *(const float4*)(bp + i * 4);
            br[i * 4 + 0] = v.x; br[i * 4 + 1] = v.y;
            br[i * 4 + 2] = v.z; br[i * 4 + 3] = v.w;
        }
    };
    auto CVTSTS = [&](int b) {
        const uint32_t base = sb + (uint32_t)b * BUFB;
        uint32_t hp[8], lp[8];
        #pragma unroll
        for (int j = 0; j < 8; ++j) split2(ar[2 * j], ar[2 * j + 1], hp[j], lp[j]);
        STS128(base + AHI + adst,      hp[0], hp[1], hp[2], hp[3]);
        STS128(base + AHI + adst + 16, hp[4], hp[5], hp[6], hp[7]);
        STS128(base + ALO + adst,      lp[0], lp[1], lp[2], lp[3]);
        STS128(base + ALO + adst + 16, lp[4], lp[5], lp[6], lp[7]);
        #pragma unroll
        for (int j = 0; j < 8; ++j) split2(br[2 * j], br[2 * j + 1], hp[j], lp[j]);
        STS128(base + BHI + bdst,      hp[0], hp[1], hp[2], hp[3]);
        STS128(base + BHI + bdst + 16, hp[4], hp[5], hp[6], hp[7]);
        STS128(base + BLO + bdst,      lp[0], lp[1], lp[2], lp[3]);
        STS128(base + BLO + bdst + 16, lp[4], lp[5], lp[6], lp[7]);
    };

    const uint32_t a_ln = (uint32_t)(((wm * 64 + (lane & 15)) * ASTRIDE + (lane >> 4) * 8) * 2);
    const uint32_t b_ln = (uint32_t)(((lane & 15) * BSTRIDE + wn * 32 + (lane >> 4) * 8) * 2);

    GLOAD(0);
    CVTSTS(0);
    GLOAD(32);

    const int NCH = TOTF / 32;
    for (int ci = 0; ci < NCH; ++ci) {
        __syncthreads();
        if (ci + 1 < NCH) CVTSTS((ci + 1) & 1);
        if (ci + 2 < NCH) GLOAD((ci + 2) * 32);

        const uint32_t base = sb + (uint32_t)(ci & 1) * BUFB;
        #pragma unroll
        for (int ks = 0; ks < 2; ++ks) {
            uint32_t ahi[4][4], alo[4][4], bhi[4][2], blo[4][2];
            const uint32_t aad = base + AHI + a_ln + (uint32_t)(ks * 32);
            #pragma unroll
            for (int mi = 0; mi < 4; mi++) {
                ldsm4(aad + mi * (16 * ASTRIDE * 2), ahi[mi]);
                ldsm4(aad + (ALO - AHI) + mi * (16 * ASTRIDE * 2), alo[mi]);
            }
            const uint32_t bad = base + BHI + b_ln + (uint32_t)(ks * 16 * BSTRIDE * 2);
            #pragma unroll
            for (int ng = 0; ng < 2; ng++) {
                uint32_t t[4];
                ldsm4t(bad + ng * 32, t);
                bhi[2 * ng][0] = t[0]; bhi[2 * ng][1] = t[1];
                bhi[2 * ng + 1][0] = t[2]; bhi[2 * ng + 1][1] = t[3];
                ldsm4t(bad + (BLO - BHI) + ng * 32, t);
                blo[2 * ng][0] = t[0]; blo[2 * ng][1] = t[1];
                blo[2 * ng + 1][0] = t[2]; blo[2 * ng + 1][1] = t[3];
            }
            #pragma unroll
            for (int mi = 0; mi < 4; mi++)
                #pragma unroll
                for (int ni = 0; ni < 4; ni++) {
                    mma16816(C[mi][ni], ahi[mi], bhi[ni]);
                    mma16816(C[mi][ni], ahi[mi], blo[ni]);
                    mma16816(C[mi][ni], alo[mi], bhi[ni]);
                }
        }
    }

    __syncthreads();
    const int crow  = wm * 64 + (lane >> 2);
    const int ccol0 = wn * 32 + (lane & 3) * 2;
    #pragma unroll
    for (int mi = 0; mi < 4; mi++)
        #pragma unroll
        for (int ni = 0; ni < 4; ni++) {
            uint32_t o0 = sb + (uint32_t)(((crow + mi * 16) * 132 + ccol0 + ni * 8) * 4);
            STS64F(o0, C[mi][ni][0], C[mi][ni][1]);
            STS64F(o0 + (uint32_t)(8 * 132 * 4), C[mi][ni][2], C[mi][ni][3]);
        }
    __syncthreads();

    const float* Cs = (const float*)smg;
    if (HW) {
        const int j0h = bx * 64;
        #pragma unroll 4
        for (int t = 0; t < 32; ++t) {
            int idx = t * 256 + tid;
            int m = idx >> 6, u = idx & 63;
            float nl = fmaxf(Cs[m * 132 + u] + bias[j0h + u], 0.f);
            float gv = Cs[m * 132 + 64 + u] + bias[TOTF + j0h + u];
            float g  = 1.f / (1.f + __expf(-gv));
            float tv = tin[(size_t)(m0 + m) * TOTF + j0h + u];
            outp[(size_t)(m0 + m) * TOTF + j0h + u] = g * tv + (1.f - g) * nl;
        }
    } else {
        const int j0 = bx * 128;
        #pragma unroll 4
        for (int t = 0; t < 64; ++t) {
            int idx = t * 256 + tid;
            int m = idx >> 7, n = idx & 127;
            outp[(size_t)(m0 + m) * HID + j0 + n] = Cs[m * 132 + n] + bias[j0 + n];
        }
    }
}

// ---------------------------------------------------------------------------
template<int W, int FILT, int TX, int TY, int MI, int MJ>
static void launch_conv(const int* ids, const float* emb, const float* cw,
                        const float* cb, float* tout, int colBase, int tiles)
{
    size_t smem = (size_t)(800 * 32 + 16 * W * FILT) * sizeof(float);
    cudaFuncSetAttribute(conv_kernel<W, FILT, TX, TY, MI, MJ>,
                         cudaFuncAttributeMaxDynamicSharedMemorySize, (int)smem);
    conv_kernel<W, FILT, TX, TY, MI, MJ>
        <<<dim3(N_TOK / 32, tiles), 256, smem>>>(ids, emb, cw, cb, tout, colBase);
}

template<int W, int NF>
static void launch_conv_mma(const int* ids, const float* cw, const float* cb,
                            float* tout, int colBase, int wOff)
{
    int nprep = 16 * W * NF;
    prep_w_kernel<W, NF><<<(nprep + 255) / 256, 256>>>(cw, wOff);
    size_t smem = CX_W + (size_t)(16 * W) * 144 * 2;
    cudaFuncSetAttribute(conv_mma_kernel<W, NF>,
                         cudaFuncAttributeMaxDynamicSharedMemorySize, (int)smem);
    conv_mma_kernel<W, NF>
        <<<dim3(N_TOK / 8, NF / 64), 256, smem>>>(ids, cb, tout, colBase, wOff);
}

extern "C" void kernel_launch(void* const* d_in, const int* in_sizes, int n_in,
                              void* d_out, int out_size)
{
    const int*   ids = (const int*)  d_in[0];
    const float* emb = (const float*)d_in[1];
    const float* cw[7]; const float* cb[7];
    for (int i = 0; i < 7; i++) {
        cw[i] = (const float*)d_in[2 + 2 * i];
        cb[i] = (const float*)d_in[3 + 2 * i];
    }
    const float* hw_w0 = (const float*)d_in[16];
    const float* hw_b0 = (const float*)d_in[17];
    const float* hw_w1 = (const float*)d_in[18];
    const float* hw_b1 = (const float*)d_in[19];
    const float* pw    = (const float*)d_in[20];
    const float* pb    = (const float*)d_in[21];
    float* out = (float*)d_out;

    float *pT = nullptr, *pT2 = nullptr;
    cudaGetSymbolAddress((void**)&pT,  g_T);
    cudaGetSymbolAddress((void**)&pT2, g_T2);

    // prep
    prep_emb_kernel<<<(VOCABN * 16 + 255) / 256, 256>>>(emb);

    // convs: w1,w2 fp32 SIMT; w3..w7 HMMA
    launch_conv<1, 32, 8, 32, 1, 4>(ids, emb, cw[0], cb[0], pT,  0, 1);
    launch_conv<2, 32, 8, 32, 1, 4>(ids, emb, cw[1], cb[1], pT, 32, 1);
    launch_conv_mma<3,   64>(ids, cw[2], cb[2], pT,   64,     0);
    launch_conv_mma<4,  128>(ids, cw[3], cb[3], pT,  128,  3072);
    launch_conv_mma<5,  256>(ids, cw[4], cb[4], pT,  256, 11264);
    launch_conv_mma<6,  512>(ids, cw[5], cb[5], pT,  512, 31744);
    launch_conv_mma<7, 1024>(ids, cw[6], cb[6], pT, 1024, 80896);

    // GEMMs (bf16x3 HMMA)
    cudaFuncSetAttribute(gemm_kernel<true>,
                         cudaFuncAttributeMaxDynamicSharedMemorySize, GEMM_SMEM);
    cudaFuncSetAttribute(gemm_kernel<false>,
                         cudaFuncAttributeMaxDynamicSharedMemorySize, GEMM_SMEM);
    gemm_kernel<true><<<dim3(32, 32), 256, GEMM_SMEM>>>(pT,  hw_w0, hw_b0, pT2);
    gemm_kernel<true><<<dim3(32, 32), 256, GEMM_SMEM>>>(pT2, hw_w1, hw_b1, pT);
    gemm_kernel<false><<<dim3(6, 32), 256, GEMM_SMEM>>>(pT, pw, pb, out);
}

// round 6
// speedup vs baseline: 2.2342x; 1.0844x over previous
#include <cuda_runtime.h>
#include <cuda_bf16.h>
#include <math.h>
#include <stdint.h>

#define N_TOK 4096
#define TOTF  2048
#define HID   768
#define VOCABN 264

__device__ float g_T [N_TOK * TOTF];
__device__ float g_T2[N_TOK * TOTF];

// activation bf16 hi/lo plane sets (P0: convs & hw2 out; P1: hw1 out)
__device__ __align__(16) __nv_bfloat16 g_p0hi[N_TOK * TOTF];
__device__ __align__(16) __nv_bfloat16 g_p0lo[N_TOK * TOTF];
__device__ __align__(16) __nv_bfloat16 g_p1hi[N_TOK * TOTF];
__device__ __align__(16) __nv_bfloat16 g_p1lo[N_TOK * TOTF];
// weight planes
__device__ __align__(16) __nv_bfloat16 g_w0hi[TOTF * 2 * TOTF];
__device__ __align__(16) __nv_bfloat16 g_w0lo[TOTF * 2 * TOTF];
__device__ __align__(16) __nv_bfloat16 g_w1hi[TOTF * 2 * TOTF];
__device__ __align__(16) __nv_bfloat16 g_w1lo[TOTF * 2 * TOTF];
__device__ __align__(16) __nv_bfloat16 g_pwhi[TOTF * HID];
__device__ __align__(16) __nv_bfloat16 g_pwlo[TOTF * HID];
// embedding + conv-weight planes
__device__ __align__(16) __nv_bfloat16 g_ehi[VOCABN * 16];
__device__ __align__(16) __nv_bfloat16 g_elo[VOCABN * 16];
#define WSP_TOT 195584
__device__ __align__(16) __nv_bfloat16 g_wsp_hi[WSP_TOT];
__device__ __align__(16) __nv_bfloat16 g_wsp_lo[WSP_TOT];

// ---------------------------------------------------------------------------
__device__ __forceinline__ uint32_t smem_u32(const void* p) {
    uint32_t a;
    asm("{ .reg .u64 t; cvta.to.shared.u64 t, %1; cvt.u32.u64 %0, t; }"
        : "=r"(a) : "l"(p));
    return a;
}
#define STS128(addr, a, b, c, d) \
    asm volatile("st.shared.v4.b32 [%0], {%1,%2,%3,%4};" \
                 :: "r"(addr), "r"(a), "r"(b), "r"(c), "r"(d) : "memory")
#define STS64F(addr, x, y) \
    asm volatile("st.shared.v2.f32 [%0], {%1,%2};" \
                 :: "r"(addr), "f"(x), "f"(y) : "memory")
#define CPASYNC16(dst, src) \
    asm volatile("cp.async.cg.shared.global [%0], [%1], 16;" \
                 :: "r"(dst), "l"(src) : "memory")
#define CPCOMMIT() asm volatile("cp.async.commit_group;" ::: "memory")
#define CPWAIT0()  asm volatile("cp.async.wait_group 0;" ::: "memory")

__device__ __forceinline__ void ldsm4(uint32_t a, uint32_t* r) {
    asm volatile("ldmatrix.sync.aligned.m8n8.x4.shared.b16 {%0,%1,%2,%3}, [%4];"
                 : "=r"(r[0]), "=r"(r[1]), "=r"(r[2]), "=r"(r[3]) : "r"(a));
}
__device__ __forceinline__ void ldsm4t(uint32_t a, uint32_t* r) {
    asm volatile("ldmatrix.sync.aligned.m8n8.x4.trans.shared.b16 {%0,%1,%2,%3}, [%4];"
                 : "=r"(r[0]), "=r"(r[1]), "=r"(r[2]), "=r"(r[3]) : "r"(a));
}
__device__ __forceinline__ void mma16816(float* c, const uint32_t* a, const uint32_t* b) {
    asm volatile("mma.sync.aligned.m16n8k16.row.col.f32.bf16.bf16.f32 "
                 "{%0,%1,%2,%3}, {%4,%5,%6,%7}, {%8,%9}, {%0,%1,%2,%3};"
                 : "+f"(c[0]), "+f"(c[1]), "+f"(c[2]), "+f"(c[3])
                 : "r"(a[0]), "r"(a[1]), "r"(a[2]), "r"(a[3]), "r"(b[0]), "r"(b[1]));
}
__device__ __forceinline__ void split2(float x0, float x1, uint32_t& hp, uint32_t& lp) {
    asm("cvt.rn.bf16x2.f32 %0, %1, %2;" : "=r"(hp) : "f"(x1), "f"(x0));
    float h0 = __uint_as_float(hp << 16);
    float h1 = __uint_as_float(hp & 0xFFFF0000u);
    float r0 = x0 - h0, r1 = x1 - h1;
    asm("cvt.rn.bf16x2.f32 %0, %1, %2;" : "=r"(lp) : "f"(r1), "f"(r0));
}
__device__ __forceinline__ void split1(float x, __nv_bfloat16& h, __nv_bfloat16& l) {
    h = __float2bfloat16(x);
    l = __float2bfloat16(x - __bfloat162float(h));
}

// ===========================================================================
// Prep kernels
// ===========================================================================
__global__ void prep_emb_kernel(const float* __restrict__ emb) {
    int i = blockIdx.x * 256 + threadIdx.x;
    if (i < VOCABN * 16) {
        float v = emb[i];
        split1(v, g_ehi[i], g_elo[i]);
    }
}
template<int W, int NF>
__global__ void prep_w_kernel(const float* __restrict__ cw, int off) {
    int i = blockIdx.x * 256 + threadIdx.x;
    if (i < 16 * W * NF) {
        int row = i / NF, f = i - row * NF;
        int c = row & 15, k = row >> 4;
        float v = cw[(f * 16 + c) * W + k];
        split1(v, g_wsp_hi[off + i], g_wsp_lo[off + i]);
    }
}
#define HWW (TOTF * 2 * TOTF)
#define PWW (TOTF * HID)
__global__ void prep_big_kernel(const float* __restrict__ w0,
                                const float* __restrict__ w1,
                                const float* __restrict__ pw) {
    size_t i4 = ((size_t)blockIdx.x * 256 + threadIdx.x) * 4;
    const float* src;
    __nv_bfloat16 *dh, *dl;
    size_t off;
    if (i4 < HWW)            { src = w0; dh = g_w0hi; dl = g_w0lo; off = i4; }
    else if (i4 < 2 * HWW)   { src = w1; dh = g_w1hi; dl = g_w1lo; off = i4 - HWW; }
    else if (i4 < 2 * HWW + PWW) { src = pw; dh = g_pwhi; dl = g_pwlo; off = i4 - 2 * HWW; }
    else return;
    float4 v = *(const float4*)(src + off);
    uint32_t h0, l0, h1, l1;
    split2(v.x, v.y, h0, l0);
    split2(v.z, v.w, h1, l1);
    *(uint32_t*)(dh + off)     = h0;
    *(uint32_t*)(dh + off + 2) = h1;
    *(uint32_t*)(dl + off)     = l0;
    *(uint32_t*)(dl + off + 2) = l1;
}

// ===========================================================================
// fp32 SIMT conv (w=1,2) — also emits bf16 planes
// ===========================================================================
template<int W, int FILT, int TX, int TY, int MI, int MJ>
__global__ __launch_bounds__(256)
void conv_kernel(const int* __restrict__ ids, const float* __restrict__ emb,
                 const float* __restrict__ cw, const float* __restrict__ cb,
                 float* __restrict__ tout, int colBase)
{
    constexpr int TOK  = 32;
    constexpr int KDIM = 16 * W;
    extern __shared__ float sm[];
    float* Xs = sm;
    float* Ws = sm + 800 * TOK;

    const int n0  = blockIdx.x * TOK;
    const int f0  = blockIdx.y * FILT;
    const int tid = threadIdx.x;

    for (int i = tid; i < FILT * KDIM; i += 256) {
        int fl = i % FILT;
        int rc = i / FILT;
        int k = rc >> 4, c = rc & 15;
        Ws[i] = cw[((f0 + fl) * 16 + c) * W + k];
    }
    {
        int tok  = tid >> 3;
        int lane = tid & 7;
        const int* idrow = ids + (n0 + tok) * 50;
        for (int i4 = lane; i4 < 200; i4 += 8) {
            int l  = i4 >> 2;
            int cg = (i4 & 3) << 2;
            int id = idrow[l];
            float4 ev = *(const float4*)(emb + id * 16 + cg);
            int r = i4 << 2;
            Xs[(r + 0) * TOK + tok] = ev.x;
            Xs[(r + 1) * TOK + tok] = ev.y;
            Xs[(r + 2) * TOK + tok] = ev.z;
            Xs[(r + 3) * TOK + tok] = ev.w;
        }
    }
    __syncthreads();

    const int tx = tid % TX;
    const int ty = tid / TX;
    const int trow = ty * MI;
    const int tcol = tx * MJ;

    float mx[MI][MJ];
    #pragma unroll
    for (int i = 0; i < MI; i++)
        #pragma unroll
        for (int j = 0; j < MJ; j++) mx[i][j] = -1e30f;

    const int NPOS = 51 - W;
    for (int l = 0; l < NPOS; ++l) {
        float acc[MI][MJ];
        #pragma unroll
        for (int i = 0; i < MI; i++)
            #pragma unroll
            for (int j = 0; j < MJ; j++) acc[i][j] = 0.f;

        const float* xb = Xs + l * 16 * TOK + trow;
        const float* wb = Ws + tcol;
        #pragma unroll 16
        for (int kk = 0; kk < KDIM; ++kk) {
            float a[MI], b[MJ];
            #pragma unroll
            for (int i = 0; i < MI; i++) a[i] = xb[kk * TOK + i];
            #pragma unroll
            for (int j = 0; j < MJ; j++) b[j] = wb[kk * FILT + j];
            #pragma unroll
            for (int i = 0; i < MI; i++)
                #pragma unroll
                for (int j = 0; j < MJ; j++) acc[i][j] += a[i] * b[j];
        }
        #pragma unroll
        for (int i = 0; i < MI; i++)
            #pragma unroll
            for (int j = 0; j < MJ; j++) mx[i][j] = fmaxf(mx[i][j], acc[i][j]);
    }

    #pragma unroll
    for (int i = 0; i < MI; i++) {
        int row = n0 + trow + i;
        #pragma unroll
        for (int j = 0; j < MJ; j++) {
            float v = mx[i][j] + cb[f0 + tcol + j];
            v = fmaxf(v, 0.f);
            size_t idx = (size_t)row * TOTF + colBase + f0 + tcol + j;
            tout[idx] = v;
            split1(v, g_p0hi[idx], g_p0lo[idx]);
        }
    }
}

// ===========================================================================
// HMMA conv (w=3..7) — emits fp32 + bf16 planes
// ===========================================================================
#define CX_LO 21504u
#define CX_W  43008u

template<int W, int NF>
__global__ __launch_bounds__(256)
void conv_mma_kernel(const int* __restrict__ ids, const float* __restrict__ cb,
                     float* __restrict__ tout, int colBase, int wOff)
{
    constexpr int KD = 16 * W;
    constexpr int NPOS = 51 - W;
    extern __shared__ char smc[];
    const uint32_t sb = smem_u32(smc);
    const uint32_t WLO = CX_W + (uint32_t)KD * 144u;
    const int tid = threadIdx.x;
    const int lane = tid & 31, wid = tid >> 5;
    const int n0 = blockIdx.x * 8;
    const int f0 = blockIdx.y * 64;

    for (int t = tid; t < 448; t += 256) {
        int tok = t / 56, r = t - tok * 56;
        uint32_t dst = sb + (uint32_t)(tok * 2688 + r * 48);
        if (r < 50) {
            int id = ids[(n0 + tok) * 50 + r];
            const uint4* eh = (const uint4*)(g_ehi + id * 16);
            const uint4* el = (const uint4*)(g_elo + id * 16);
            uint4 h0 = eh[0], h1 = eh[1];
            uint4 l0 = el[0], l1 = el[1];
            STS128(dst,          h0.x, h0.y, h0.z, h0.w);
            STS128(dst + 16,     h1.x, h1.y, h1.z, h1.w);
            STS128(dst + CX_LO,      l0.x, l0.y, l0.z, l0.w);
            STS128(dst + CX_LO + 16, l1.x, l1.y, l1.z, l1.w);
        } else {
            STS128(dst, 0u, 0u, 0u, 0u);
            STS128(dst + 16, 0u, 0u, 0u, 0u);
            STS128(dst + CX_LO, 0u, 0u, 0u, 0u);
            STS128(dst + CX_LO + 16, 0u, 0u, 0u, 0u);
        }
    }
    for (int t = tid; t < KD * 8; t += 256) {
        int row = t >> 3, seg = t & 7;
        int gsrc = wOff + row * NF + f0 + seg * 8;
        uint4 h = *(const uint4*)(g_wsp_hi + gsrc);
        uint4 l = *(const uint4*)(g_wsp_lo + gsrc);
        uint32_t d = sb + CX_W + (uint32_t)(row * 144 + seg * 16);
        STS128(d, h.x, h.y, h.z, h.w);
        STS128(d + (WLO - CX_W), l.x, l.y, l.z, l.w);
    }
    __syncthreads();

    float C[3][8][4];
    #pragma unroll
    for (int mi = 0; mi < 3; mi++)
        #pragma unroll
        for (int nf = 0; nf < 8; nf++)
            #pragma unroll
            for (int q = 0; q < 4; q++) C[mi][nf][q] = 0.f;

    const uint32_t xb = sb + (uint32_t)(wid * 2688 + (lane & 15) * 48 + (lane >> 4) * 16);
    const uint32_t bb = sb + CX_W + (uint32_t)((lane & 15) * 144 + (lane >> 4) * 16);

    #pragma unroll
    for (int k = 0; k < W; ++k) {
        uint32_t ah[3][4], al[3][4];
        #pragma unroll
        for (int mi = 0; mi < 3; mi++) {
            ldsm4(xb + (uint32_t)((mi * 16 + k) * 48), ah[mi]);
            ldsm4(xb + (uint32_t)((mi * 16 + k) * 48) + CX_LO, al[mi]);
        }
        uint32_t bh[8][2], bl[8][2];
        #pragma unroll
        for (int ng = 0; ng < 4; ng++) {
            uint32_t t4[4];
            ldsm4t(bb + (uint32_t)(k * 16 * 144 + ng * 32), t4);
            bh[2*ng][0] = t4[0]; bh[2*ng][1] = t4[1];
            bh[2*ng+1][0] = t4[2]; bh[2*ng+1][1] = t4[3];
            ldsm4t(bb + (WLO - CX_W) + (uint32_t)(k * 16 * 144 + ng * 32), t4);
            bl[2*ng][0] = t4[0]; bl[2*ng][1] = t4[1];
            bl[2*ng+1][0] = t4[2]; bl[2*ng+1][1] = t4[3];
        }
        #pragma unroll
        for (int mi = 0; mi < 3; mi++)
            #pragma unroll
            for (int nf = 0; nf < 8; nf++) {
                mma16816(C[mi][nf], ah[mi], bh[nf]);
                mma16816(C[mi][nf], ah[mi], bl[nf]);
                mma16816(C[mi][nf], al[mi], bh[nf]);
            }
    }

    float m0[8], m1[8];
    #pragma unroll
    for (int nf = 0; nf < 8; nf++) { m0[nf] = -1e30f; m1[nf] = -1e30f; }
    const int r0 = lane >> 2;
    #pragma unroll
    for (int mi = 0; mi < 3; mi++) {
        bool v0 = (mi * 16 + r0) < NPOS;
        bool v1 = (mi * 16 + r0 + 8) < NPOS;
        #pragma unroll
        for (int nf = 0; nf < 8; nf++) {
            if (v0) { m0[nf] = fmaxf(m0[nf], C[mi][nf][0]);
                      m1[nf] = fmaxf(m1[nf], C[mi][nf][1]); }
            if (v1) { m0[nf] = fmaxf(m0[nf], C[mi][nf][2]);
                      m1[nf] = fmaxf(m1[nf], C[mi][nf][3]); }
        }
    }
    #pragma unroll
    for (int nf = 0; nf < 8; nf++) {
        #pragma unroll
        for (int off = 4; off < 32; off <<= 1) {
            m0[nf] = fmaxf(m0[nf], __shfl_xor_sync(0xffffffffu, m0[nf], off));
            m1[nf] = fmaxf(m1[nf], __shfl_xor_sync(0xffffffffu, m1[nf], off));
        }
    }
    if (lane < 4) {
        const int token = n0 + wid;
        const size_t base = (size_t)token * TOTF + colBase + f0;
        float* orow = tout + base;
        #pragma unroll
        for (int nf = 0; nf < 8; nf++) {
            int fl = nf * 8 + lane * 2;
            float2 o;
            o.x = fmaxf(m0[nf] + cb[f0 + fl], 0.f);
            o.y = fmaxf(m1[nf] + cb[f0 + fl + 1], 0.f);
            *(float2*)(orow + fl) = o;
            uint32_t hp, lp;
            split2(o.x, o.y, hp, lp);
            *(uint32_t*)(g_p0hi + base + fl) = hp;
            *(uint32_t*)(g_p0lo + base + fl) = lp;
        }
    }
}

// ===========================================================================
// bf16x3 GEMM, pre-split operands, cp.async staging.
// ===========================================================================
#define ASTRIDE 40
#define BSTRIDE 136
#define OFF_ALO 10240
#define OFF_BHI 20480
#define OFF_BLO 29184
#define BUFB 37888
#define GEMM_SMEM (2 * BUFB)

template<bool HW>
__global__ __launch_bounds__(256, 1)
void gemm_kernel(const __nv_bfloat16* __restrict__ Ahi,
                 const __nv_bfloat16* __restrict__ Alo,
                 const __nv_bfloat16* __restrict__ Bhi,
                 const __nv_bfloat16* __restrict__ Blo,
                 const float* __restrict__ tin,
                 const float* __restrict__ bias,
                 float* __restrict__ outp,
                 __nv_bfloat16* __restrict__ OutHi,
                 __nv_bfloat16* __restrict__ OutLo)
{
    extern __shared__ char smg[];
    const uint32_t sb = smem_u32(smg);
    const int tid  = threadIdx.x;
    const int lane = tid & 31, wid = tid >> 5;
    const int wm = wid >> 2, wn = wid & 3;
    const int m0 = blockIdx.y * 128;
    const int bx = blockIdx.x;
    const int LDWB = HW ? (2 * TOTF) : HID;

    const int brow = tid >> 3;
    const int bseg = tid & 7;
    int bcol;
    if (HW) bcol = (bseg < 4) ? bx * 64 + bseg * 16 : TOTF + bx * 64 + (bseg - 4) * 16;
    else    bcol = bx * 128 + bseg * 16;

    const int ar0 = tid >> 1;
    const int as0 = (tid & 1) * 2;

    auto STAGE = [&](int b, int k0) {
        const uint32_t base = sb + (uint32_t)b * BUFB;
        // A hi/lo: 2 x 16B per plane
        {
            const size_t arow_off = (size_t)(m0 + ar0) * TOTF + k0;
            uint32_t d = base + (uint32_t)(ar0 * ASTRIDE * 2);
            #pragma unroll
            for (int s = 0; s < 2; ++s) {
                int seg = as0 + s;
                CPASYNC16(d + seg * 16, (const void*)(Ahi + arow_off + seg * 8));
                CPASYNC16(d + OFF_ALO + seg * 16, (const void*)(Alo + arow_off + seg * 8));
            }
        }
        // B hi/lo: each 16-col segment is 32B -> 2 x 16B per plane
        {
            const size_t bsrc = (size_t)(k0 + brow) * LDWB + bcol;
            uint32_t d = base + OFF_BHI + (uint32_t)(brow * BSTRIDE * 2 + bseg * 32);
            CPASYNC16(d,      (const void*)(Bhi + bsrc));
            CPASYNC16(d + 16, (const void*)(Bhi + bsrc + 8));
            CPASYNC16(d + (OFF_BLO - OFF_BHI),      (const void*)(Blo + bsrc));
            CPASYNC16(d + (OFF_BLO - OFF_BHI) + 16, (const void*)(Blo + bsrc + 8));
        }
    };

    float C[4][4][4];
    #pragma unroll
    for (int mi = 0; mi < 4; mi++)
        #pragma unroll
        for (int ni = 0; ni < 4; ni++)
            #pragma unroll
            for (int q = 0; q < 4; q++) C[mi][ni][q] = 0.f;

    const uint32_t a_ln = (uint32_t)(((wm * 64 + (lane & 15)) * ASTRIDE + (lane >> 4) * 8) * 2);
    const uint32_t b_ln = (uint32_t)(((lane & 15) * BSTRIDE + wn * 32 + (lane >> 4) * 8) * 2);

    STAGE(0, 0);
    CPCOMMIT();

    const int NCH = TOTF / 32;
    for (int ci = 0; ci < NCH; ++ci) {
        CPWAIT0();
        __syncthreads();
        if (ci + 1 < NCH) { STAGE((ci + 1) & 1, (ci + 1) * 32); CPCOMMIT(); }

        const uint32_t base = sb + (uint32_t)(ci & 1) * BUFB;
        #pragma unroll
        for (int ks = 0; ks < 2; ++ks) {
            uint32_t ahi[4][4], alo[4][4], bhi[4][2], blo[4][2];
            const uint32_t aad = base + a_ln + (uint32_t)(ks * 32);
            #pragma unroll
            for (int mi = 0; mi < 4; mi++) {
                ldsm4(aad + mi * (16 * ASTRIDE * 2), ahi[mi]);
                ldsm4(aad + OFF_ALO + mi * (16 * ASTRIDE * 2), alo[mi]);
            }
            const uint32_t bad = base + OFF_BHI + b_ln + (uint32_t)(ks * 16 * BSTRIDE * 2);
            #pragma unroll
            for (int ng = 0; ng < 2; ng++) {
                uint32_t t[4];
                ldsm4t(bad + ng * 32, t);
                bhi[2 * ng][0] = t[0]; bhi[2 * ng][1] = t[1];
                bhi[2 * ng + 1][0] = t[2]; bhi[2 * ng + 1][1] = t[3];
                ldsm4t(bad + (OFF_BLO - OFF_BHI) + ng * 32, t);
                blo[2 * ng][0] = t[0]; blo[2 * ng][1] = t[1];
                blo[2 * ng + 1][0] = t[2]; blo[2 * ng + 1][1] = t[3];
            }
            #pragma unroll
            for (int mi = 0; mi < 4; mi++)
                #pragma unroll
                for (int ni = 0; ni < 4; ni++) {
                    mma16816(C[mi][ni], ahi[mi], bhi[ni]);
                    mma16816(C[mi][ni], ahi[mi], blo[ni]);
                    mma16816(C[mi][ni], alo[mi], bhi[ni]);
                }
        }
        __syncthreads();
    }

    const int crow  = wm * 64 + (lane >> 2);
    const int ccol0 = wn * 32 + (lane & 3) * 2;
    #pragma unroll
    for (int mi = 0; mi < 4; mi++)
        #pragma unroll
        for (int ni = 0; ni < 4; ni++) {
            uint32_t o0 = sb + (uint32_t)(((crow + mi * 16) * 132 + ccol0 + ni * 8) * 4);
            STS64F(o0, C[mi][ni][0], C[mi][ni][1]);
            STS64F(o0 + (uint32_t)(8 * 132 * 4), C[mi][ni][2], C[mi][ni][3]);
        }
    __syncthreads();

    const float* Cs = (const float*)smg;
    if (HW) {
        const int j0h = bx * 64;
        #pragma unroll 4
        for (int t = 0; t < 32; ++t) {
            int idx = t * 256 + tid;
            int m = idx >> 6, u = idx & 63;
            float nl = fmaxf(Cs[m * 132 + u] + bias[j0h + u], 0.f);
            float gv = Cs[m * 132 + 64 + u] + bias[TOTF + j0h + u];
            float g  = 1.f / (1.f + __expf(-gv));
            size_t o = (size_t)(m0 + m) * TOTF + j0h + u;
            float tv = tin[o];
            float vo = g * tv + (1.f - g) * nl;
            outp[o] = vo;
            split1(vo, OutHi[o], OutLo[o]);
        }
    } else {
        const int j0 = bx * 128;
        #pragma unroll 4
        for (int t = 0; t < 64; ++t) {
            int idx = t * 256 + tid;
            int m = idx >> 7, n = idx & 127;
            outp[(size_t)(m0 + m) * HID + j0 + n] = Cs[m * 132 + n] + bias[j0 + n];
        }
    }
}

// ---------------------------------------------------------------------------
template<int W, int FILT, int TX, int TY, int MI, int MJ>
static void launch_conv(const int* ids, const float* emb, const float* cw,
                        const float* cb, float* tout, int colBase, int tiles)
{
    size_t smem = (size_t)(800 * 32 + 16 * W * FILT) * sizeof(float);
    cudaFuncSetAttribute(conv_kernel<W, FILT, TX, TY, MI, MJ>,
                         cudaFuncAttributeMaxDynamicSharedMemorySize, (int)smem);
    conv_kernel<W, FILT, TX, TY, MI, MJ>
        <<<dim3(N_TOK / 32, tiles), 256, smem>>>(ids, emb, cw, cb, tout, colBase);
}

template<int W, int NF>
static void launch_conv_mma(const int* ids, const float* cw, const float* cb,
                            float* tout, int colBase, int wOff)
{
    int nprep = 16 * W * NF;
    prep_w_kernel<W, NF><<<(nprep + 255) / 256, 256>>>(cw, wOff);
    size_t smem = CX_W + (size_t)(16 * W) * 144 * 2;
    cudaFuncSetAttribute(conv_mma_kernel<W, NF>,
                         cudaFuncAttributeMaxDynamicSharedMemorySize, (int)smem);
    conv_mma_kernel<W, NF>
        <<<dim3(N_TOK / 8, NF / 64), 256, smem>>>(ids, cb, tout, colBase, wOff);
}

extern "C" void kernel_launch(void* const* d_in, const int* in_sizes, int n_in,
                              void* d_out, int out_size)
{
    const int*   ids = (const int*)  d_in[0];
    const float* emb = (const float*)d_in[1];
    const float* cw[7]; const float* cb[7];
    for (int i = 0; i < 7; i++) {
        cw[i] = (const float*)d_in[2 + 2 * i];
        cb[i] = (const float*)d_in[3 + 2 * i];
    }
    const float* hw_w0 = (const float*)d_in[16];
    const float* hw_b0 = (const float*)d_in[17];
    const float* hw_w1 = (const float*)d_in[18];
    const float* hw_b1 = (const float*)d_in[19];
    const float* pw    = (const float*)d_in[20];
    const float* pb    = (const float*)d_in[21];
    float* out = (float*)d_out;

    float *pT, *pT2;
    cudaGetSymbolAddress((void**)&pT,  g_T);
    cudaGetSymbolAddress((void**)&pT2, g_T2);
    __nv_bfloat16 *p0hi, *p0lo, *p1hi, *p1lo;
    __nv_bfloat16 *w0hi, *w0lo, *w1hi, *w1lo, *pwhi, *pwlo;
    cudaGetSymbolAddress((void**)&p0hi, g_p0hi);
    cudaGetSymbolAddress((void**)&p0lo, g_p0lo);
    cudaGetSymbolAddress((void**)&p1hi, g_p1hi);
    cudaGetSymbolAddress((void**)&p1lo, g_p1lo);
    cudaGetSymbolAddress((void**)&w0hi, g_w0hi);
    cudaGetSymbolAddress((void**)&w0lo, g_w0lo);
    cudaGetSymbolAddress((void**)&w1hi, g_w1hi);
    cudaGetSymbolAddress((void**)&w1lo, g_w1lo);
    cudaGetSymbolAddress((void**)&pwhi, g_pwhi);
    cudaGetSymbolAddress((void**)&pwlo, g_pwlo);

    prep_emb_kernel<<<(VOCABN * 16 + 255) / 256, 256>>>(emb);
    {
        size_t tot = 2ULL * HWW + PWW;
        int blocks = (int)((tot / 4 + 255) / 256);
        prep_big_kernel<<<blocks, 256>>>(hw_w0, hw_w1, pw);
    }

    launch_conv<1, 32, 8, 32, 1, 4>(ids, emb, cw[0], cb[0], pT,  0, 1);
    launch_conv<2, 32, 8, 32, 1, 4>(ids, emb, cw[1], cb[1], pT, 32, 1);
    launch_conv_mma<3,   64>(ids, cw[2], cb[2], pT,   64,     0);
    launch_conv_mma<4,  128>(ids, cw[3], cb[3], pT,  128,  3072);
    launch_conv_mma<5,  256>(ids, cw[4], cb[4], pT,  256, 11264);
    launch_conv_mma<6,  512>(ids, cw[5], cb[5], pT,  512, 31744);
    launch_conv_mma<7, 1024>(ids, cw[6], cb[6], pT, 1024, 80896);

    cudaFuncSetAttribute(gemm_kernel<true>,
                         cudaFuncAttributeMaxDynamicSharedMemorySize, GEMM_SMEM);
    cudaFuncSetAttribute(gemm_kernel<false>,
                         cudaFuncAttributeMaxDynamicSharedMemorySize, GEMM_SMEM);
    gemm_kernel<true><<<dim3(32, 32), 256, GEMM_SMEM>>>(
        p0hi, p0lo, w0hi, w0lo, pT, hw_b0, pT2, p1hi, p1lo);
    gemm_kernel<true><<<dim3(32, 32), 256, GEMM_SMEM>>>(
        p1hi, p1lo, w1hi, w1lo, pT2, hw_b1, pT, p0hi, p0lo);
    gemm_kernel<false><<<dim3(6, 32), 256, GEMM_SMEM>>>(
        p0hi, p0lo, pwhi, pwlo, nullptr, pb, out, nullptr, nullptr);
}

// round 7
// speedup vs baseline: 3.1647x; 1.4165x over previous
#include <cuda_runtime.h>
#include <cuda_bf16.h>
#include <cuda_fp16.h>
#include <math.h>
#include <stdint.h>

#define N_TOK 4096
#define TOTF  2048
#define HID   768
#define VOCABN 264

__device__ float g_T [N_TOK * TOTF];
__device__ float g_T2[N_TOK * TOTF];

// fp16 activation plane sets (P0: convs & hw2 out; P1: hw1 out)
__device__ __align__(16) __half g_p0hi[N_TOK * TOTF];
__device__ __align__(16) __half g_p0lo[N_TOK * TOTF];
__device__ __align__(16) __half g_p1hi[N_TOK * TOTF];
__device__ __align__(16) __half g_p1lo[N_TOK * TOTF];
// fp16 weight planes (hi only — B operand is single-fp16)
#define HWW (TOTF * 2 * TOTF)
#define PWW (TOTF * HID)
__device__ __align__(16) __half g_w0h[HWW];
__device__ __align__(16) __half g_w1h[HWW];
__device__ __align__(16) __half g_pwh[PWW];
// bf16 conv tables (conv path stays bf16 3-term)
__device__ __align__(16) __nv_bfloat16 g_ehi[VOCABN * 16];
__device__ __align__(16) __nv_bfloat16 g_elo[VOCABN * 16];
#define WSP_TOT 195584
__device__ __align__(16) __nv_bfloat16 g_wsp_hi[WSP_TOT];
__device__ __align__(16) __nv_bfloat16 g_wsp_lo[WSP_TOT];

// ---------------------------------------------------------------------------
__device__ __forceinline__ uint32_t smem_u32(const void* p) {
    uint32_t a;
    asm("{ .reg .u64 t; cvta.to.shared.u64 t, %1; cvt.u32.u64 %0, t; }"
        : "=r"(a) : "l"(p));
    return a;
}
#define STS128(addr, a, b, c, d) \
    asm volatile("st.shared.v4.b32 [%0], {%1,%2,%3,%4};" \
                 :: "r"(addr), "r"(a), "r"(b), "r"(c), "r"(d) : "memory")
#define STS64F(addr, x, y) \
    asm volatile("st.shared.v2.f32 [%0], {%1,%2};" \
                 :: "r"(addr), "f"(x), "f"(y) : "memory")
#define CPASYNC16(dst, src) \
    asm volatile("cp.async.cg.shared.global [%0], [%1], 16;" \
                 :: "r"(dst), "l"(src) : "memory")
#define CPCOMMIT() asm volatile("cp.async.commit_group;" ::: "memory")
#define CPWAIT0()  asm volatile("cp.async.wait_group 0;" ::: "memory")

__device__ __forceinline__ void ldsm4(uint32_t a, uint32_t* r) {
    asm volatile("ldmatrix.sync.aligned.m8n8.x4.shared.b16 {%0,%1,%2,%3}, [%4];"
                 : "=r"(r[0]), "=r"(r[1]), "=r"(r[2]), "=r"(r[3]) : "r"(a));
}
__device__ __forceinline__ void ldsm4t(uint32_t a, uint32_t* r) {
    asm volatile("ldmatrix.sync.aligned.m8n8.x4.trans.shared.b16 {%0,%1,%2,%3}, [%4];"
                 : "=r"(r[0]), "=r"(r[1]), "=r"(r[2]), "=r"(r[3]) : "r"(a));
}
__device__ __forceinline__ void mma_bf(float* c, const uint32_t* a, const uint32_t* b) {
    asm volatile("mma.sync.aligned.m16n8k16.row.col.f32.bf16.bf16.f32 "
                 "{%0,%1,%2,%3}, {%4,%5,%6,%7}, {%8,%9}, {%0,%1,%2,%3};"
                 : "+f"(c[0]), "+f"(c[1]), "+f"(c[2]), "+f"(c[3])
                 : "r"(a[0]), "r"(a[1]), "r"(a[2]), "r"(a[3]), "r"(b[0]), "r"(b[1]));
}
__device__ __forceinline__ void mma_fp(float* c, const uint32_t* a, const uint32_t* b) {
    asm volatile("mma.sync.aligned.m16n8k16.row.col.f32.f16.f16.f32 "
                 "{%0,%1,%2,%3}, {%4,%5,%6,%7}, {%8,%9}, {%0,%1,%2,%3};"
                 : "+f"(c[0]), "+f"(c[1]), "+f"(c[2]), "+f"(c[3])
                 : "r"(a[0]), "r"(a[1]), "r"(a[2]), "r"(a[3]), "r"(b[0]), "r"(b[1]));
}
// bf16 split (conv path)
__device__ __forceinline__ void split2b(float x0, float x1, uint32_t& hp, uint32_t& lp) {
    asm("cvt.rn.bf16x2.f32 %0, %1, %2;" : "=r"(hp) : "f"(x1), "f"(x0));
    float h0 = __uint_as_float(hp << 16);
    float h1 = __uint_as_float(hp & 0xFFFF0000u);
    float r0 = x0 - h0, r1 = x1 - h1;
    asm("cvt.rn.bf16x2.f32 %0, %1, %2;" : "=r"(lp) : "f"(r1), "f"(r0));
}
__device__ __forceinline__ void split1b(float x, __nv_bfloat16& h, __nv_bfloat16& l) {
    h = __float2bfloat16(x);
    l = __float2bfloat16(x - __bfloat162float(h));
}
// fp16 split (GEMM activation planes)
__device__ __forceinline__ void split2h(float x0, float x1, __half2& hp, __half2& lp) {
    __half h0 = __float2half_rn(x0), h1 = __float2half_rn(x1);
    float r0 = x0 - __half2float(h0);
    float r1 = x1 - __half2float(h1);
    hp = __halves2half2(h0, h1);
    lp = __halves2half2(__float2half_rn(r0), __float2half_rn(r1));
}
__device__ __forceinline__ void split1h(float x, __half& h, __half& l) {
    h = __float2half_rn(x);
    l = __float2half_rn(x - __half2float(h));
}

// ===========================================================================
// Prep kernels
// ===========================================================================
__global__ void prep_emb_kernel(const float* __restrict__ emb) {
    int i = blockIdx.x * 256 + threadIdx.x;
    if (i < VOCABN * 16) {
        float v = emb[i];
        split1b(v, g_ehi[i], g_elo[i]);
    }
}
template<int W, int NF>
__global__ void prep_w_kernel(const float* __restrict__ cw, int off) {
    int i = blockIdx.x * 256 + threadIdx.x;
    if (i < 16 * W * NF) {
        int row = i / NF, f = i - row * NF;
        int c = row & 15, k = row >> 4;
        float v = cw[(f * 16 + c) * W + k];
        split1b(v, g_wsp_hi[off + i], g_wsp_lo[off + i]);
    }
}
__global__ void prep_big_kernel(const float* __restrict__ w0,
                                const float* __restrict__ w1,
                                const float* __restrict__ pw) {
    size_t i4 = ((size_t)blockIdx.x * 256 + threadIdx.x) * 4;
    const float* src;
    __half* dh;
    size_t off;
    if (i4 < HWW)                { src = w0; dh = g_w0h; off = i4; }
    else if (i4 < 2 * HWW)       { src = w1; dh = g_w1h; off = i4 - HWW; }
    else if (i4 < 2 * HWW + PWW) { src = pw; dh = g_pwh; off = i4 - 2 * HWW; }
    else return;
    float4 v = *(const float4*)(src + off);
    *(half2*)(dh + off)     = __halves2half2(__float2half_rn(v.x), __float2half_rn(v.y));
    *(half2*)(dh + off + 2) = __halves2half2(__float2half_rn(v.z), __float2half_rn(v.w));
}

// ===========================================================================
// fp32 SIMT conv (w=1,2) — TOK tokens/block, emits fp16 planes
// ===========================================================================
template<int TOK, int W, int FILT, int TX, int TY, int MI, int MJ>
__global__ __launch_bounds__(256)
void conv_kernel(const int* __restrict__ ids, const float* __restrict__ emb,
                 const float* __restrict__ cw, const float* __restrict__ cb,
                 float* __restrict__ tout, int colBase)
{
    constexpr int KDIM = 16 * W;
    constexpr int LNS  = 256 / TOK;
    extern __shared__ float sm[];
    float* Xs = sm;
    float* Ws = sm + 800 * TOK;

    const int n0  = blockIdx.x * TOK;
    const int f0  = blockIdx.y * FILT;
    const int tid = threadIdx.x;

    for (int i = tid; i < FILT * KDIM; i += 256) {
        int fl = i % FILT;
        int rc = i / FILT;
        int k = rc >> 4, c = rc & 15;
        Ws[i] = cw[((f0 + fl) * 16 + c) * W + k];
    }
    {
        int tok  = tid / LNS;
        int lane = tid % LNS;
        const int* idrow = ids + (n0 + tok) * 50;
        for (int i4 = lane; i4 < 200; i4 += LNS) {
            int l  = i4 >> 2;
            int cg = (i4 & 3) << 2;
            int id = idrow[l];
            float4 ev = *(const float4*)(emb + id * 16 + cg);
            int r = i4 << 2;
            Xs[(r + 0) * TOK + tok] = ev.x;
            Xs[(r + 1) * TOK + tok] = ev.y;
            Xs[(r + 2) * TOK + tok] = ev.z;
            Xs[(r + 3) * TOK + tok] = ev.w;
        }
    }
    __syncthreads();

    const int tx = tid % TX;
    const int ty = tid / TX;
    const int trow = ty * MI;
    const int tcol = tx * MJ;

    float mx[MI][MJ];
    #pragma unroll
    for (int i = 0; i < MI; i++)
        #pragma unroll
        for (int j = 0; j < MJ; j++) mx[i][j] = -1e30f;

    const int NPOS = 51 - W;
    for (int l = 0; l < NPOS; ++l) {
        float acc[MI][MJ];
        #pragma unroll
        for (int i = 0; i < MI; i++)
            #pragma unroll
            for (int j = 0; j < MJ; j++) acc[i][j] = 0.f;

        const float* xb = Xs + l * 16 * TOK + trow;
        const float* wb = Ws + tcol;
        #pragma unroll 16
        for (int kk = 0; kk < KDIM; ++kk) {
            float a[MI], b[MJ];
            #pragma unroll
            for (int i = 0; i < MI; i++) a[i] = xb[kk * TOK + i];
            #pragma unroll
            for (int j = 0; j < MJ; j++) b[j] = wb[kk * FILT + j];
            #pragma unroll
            for (int i = 0; i < MI; i++)
                #pragma unroll
                for (int j = 0; j < MJ; j++) acc[i][j] += a[i] * b[j];
        }
        #pragma unroll
        for (int i = 0; i < MI; i++)
            #pragma unroll
            for (int j = 0; j < MJ; j++) mx[i][j] = fmaxf(mx[i][j], acc[i][j]);
    }

    #pragma unroll
    for (int i = 0; i < MI; i++) {
        int row = n0 + trow + i;
        #pragma unroll
        for (int j = 0; j < MJ; j++) {
            float v = mx[i][j] + cb[f0 + tcol + j];
            v = fmaxf(v, 0.f);
            size_t idx = (size_t)row * TOTF + colBase + f0 + tcol + j;
            tout[idx] = v;
            split1h(v, g_p0hi[idx], g_p0lo[idx]);
        }
    }
}

// ===========================================================================
// HMMA conv (w=3..7, bf16 3-term) — NT filter tiles per block, X staged once
// ===========================================================================
#define CX_LO 21504u
#define CX_W  43008u

template<int W, int NF, int NT>
__global__ __launch_bounds__(256)
void conv_mma_kernel(const int* __restrict__ ids, const float* __restrict__ cb,
                     float* __restrict__ tout, int colBase, int wOff)
{
    constexpr int KD = 16 * W;
    constexpr int NPOS = 51 - W;
    extern __shared__ char smc[];
    const uint32_t sb = smem_u32(smc);
    const uint32_t WLO = CX_W + (uint32_t)KD * 144u;
    const int tid = threadIdx.x;
    const int lane = tid & 31, wid = tid >> 5;
    const int n0 = blockIdx.x * 8;

    // ---- stage X once ----
    for (int t = tid; t < 448; t += 256) {
        int tok = t / 56, r = t - tok * 56;
        uint32_t dst = sb + (uint32_t)(tok * 2688 + r * 48);
        if (r < 50) {
            int id = ids[(n0 + tok) * 50 + r];
            const uint4* eh = (const uint4*)(g_ehi + id * 16);
            const uint4* el = (const uint4*)(g_elo + id * 16);
            uint4 h0 = eh[0], h1 = eh[1];
            uint4 l0 = el[0], l1 = el[1];
            STS128(dst,          h0.x, h0.y, h0.z, h0.w);
            STS128(dst + 16,     h1.x, h1.y, h1.z, h1.w);
            STS128(dst + CX_LO,      l0.x, l0.y, l0.z, l0.w);
            STS128(dst + CX_LO + 16, l1.x, l1.y, l1.z, l1.w);
        } else {
            STS128(dst, 0u, 0u, 0u, 0u);
            STS128(dst + 16, 0u, 0u, 0u, 0u);
            STS128(dst + CX_LO, 0u, 0u, 0u, 0u);
            STS128(dst + CX_LO + 16, 0u, 0u, 0u, 0u);
        }
    }

    const uint32_t xb = sb + (uint32_t)(wid * 2688 + (lane & 15) * 48 + (lane >> 4) * 16);
    const uint32_t bb = sb + CX_W + (uint32_t)((lane & 15) * 144 + (lane >> 4) * 16);

    for (int ft = 0; ft < NT; ++ft) {
        const int f0 = (blockIdx.y * NT + ft) * 64;
        __syncthreads();      // X ready / previous tile's ldsm done
        for (int t = tid; t < KD * 8; t += 256) {
            int row = t >> 3, seg = t & 7;
            int gsrc = wOff + row * NF + f0 + seg * 8;
            uint4 h = *(const uint4*)(g_wsp_hi + gsrc);
            uint4 l = *(const uint4*)(g_wsp_lo + gsrc);
            uint32_t d = sb + CX_W + (uint32_t)(row * 144 + seg * 16);
            STS128(d, h.x, h.y, h.z, h.w);
            STS128(d + (WLO - CX_W), l.x, l.y, l.z, l.w);
        }
        __syncthreads();

        float C[3][8][4];
        #pragma unroll
        for (int mi = 0; mi < 3; mi++)
            #pragma unroll
            for (int nf = 0; nf < 8; nf++)
                #pragma unroll
                for (int q = 0; q < 4; q++) C[mi][nf][q] = 0.f;

        #pragma unroll
        for (int k = 0; k < W; ++k) {
            uint32_t ah[3][4], al[3][4];
            #pragma unroll
            for (int mi = 0; mi < 3; mi++) {
                ldsm4(xb + (uint32_t)((mi * 16 + k) * 48), ah[mi]);
                ldsm4(xb + (uint32_t)((mi * 16 + k) * 48) + CX_LO, al[mi]);
            }
            uint32_t bh[8][2], bl[8][2];
            #pragma unroll
            for (int ng = 0; ng < 4; ng++) {
                uint32_t t4[4];
                ldsm4t(bb + (uint32_t)(k * 16 * 144 + ng * 32), t4);
                bh[2*ng][0] = t4[0]; bh[2*ng][1] = t4[1];
                bh[2*ng+1][0] = t4[2]; bh[2*ng+1][1] = t4[3];
                ldsm4t(bb + (WLO - CX_W) + (uint32_t)(k * 16 * 144 + ng * 32), t4);
                bl[2*ng][0] = t4[0]; bl[2*ng][1] = t4[1];
                bl[2*ng+1][0] = t4[2]; bl[2*ng+1][1] = t4[3];
            }
            #pragma unroll
            for (int mi = 0; mi < 3; mi++)
                #pragma unroll
                for (int nf = 0; nf < 8; nf++) {
                    mma_bf(C[mi][nf], ah[mi], bh[nf]);
                    mma_bf(C[mi][nf], ah[mi], bl[nf]);
                    mma_bf(C[mi][nf], al[mi], bh[nf]);
                }
        }

        float m0[8], m1[8];
        #pragma unroll
        for (int nf = 0; nf < 8; nf++) { m0[nf] = -1e30f; m1[nf] = -1e30f; }
        const int r0 = lane >> 2;
        #pragma unroll
        for (int mi = 0; mi < 3; mi++) {
            bool v0 = (mi * 16 + r0) < NPOS;
            bool v1 = (mi * 16 + r0 + 8) < NPOS;
            #pragma unroll
            for (int nf = 0; nf < 8; nf++) {
                if (v0) { m0[nf] = fmaxf(m0[nf], C[mi][nf][0]);
                          m1[nf] = fmaxf(m1[nf], C[mi][nf][1]); }
                if (v1) { m0[nf] = fmaxf(m0[nf], C[mi][nf][2]);
                          m1[nf] = fmaxf(m1[nf], C[mi][nf][3]); }
            }
        }
        #pragma unroll
        for (int nf = 0; nf < 8; nf++) {
            #pragma unroll
            for (int off = 4; off < 32; off <<= 1) {
                m0[nf] = fmaxf(m0[nf], __shfl_xor_sync(0xffffffffu, m0[nf], off));
                m1[nf] = fmaxf(m1[nf], __shfl_xor_sync(0xffffffffu, m1[nf], off));
            }
        }
        if (lane < 4) {
            const int token = n0 + wid;
            const size_t base = (size_t)token * TOTF + colBase + f0;
            float* orow = tout + base;
            #pragma unroll
            for (int nf = 0; nf < 8; nf++) {
                int fl = nf * 8 + lane * 2;
                float2 o;
                o.x = fmaxf(m0[nf] + cb[f0 + fl], 0.f);
                o.y = fmaxf(m1[nf] + cb[f0 + fl + 1], 0.f);
                *(float2*)(orow + fl) = o;
                __half2 hp, lp;
                split2h(o.x, o.y, hp, lp);
                *(__half2*)(g_p0hi + base + fl) = hp;
                *(__half2*)(g_p0lo + base + fl) = lp;
            }
        }
    }
}

// ===========================================================================
// fp16 2-term GEMM: C = (Ahi + Alo) @ fp16(B).  cp.async staging, 2 CTAs/SM.
// ===========================================================================
#define ASTRIDE 40
#define BSTRIDE 136
#define OFF_ALO 10240
#define OFF_B   20480
#define BUFB 29184
#define GEMM_SMEM 67584   // max(2*BUFB=58368, C smem 128*132*4=67584)

template<bool HW>
__global__ __launch_bounds__(256, 2)
void gemm_kernel(const __half* __restrict__ Ahi,
                 const __half* __restrict__ Alo,
                 const __half* __restrict__ Bh,
                 const float* __restrict__ tin,
                 const float* __restrict__ bias,
                 float* __restrict__ outp,
                 __half* __restrict__ OutHi,
                 __half* __restrict__ OutLo)
{
    extern __shared__ char smg[];
    const uint32_t sb = smem_u32(smg);
    const int tid  = threadIdx.x;
    const int lane = tid & 31, wid = tid >> 5;
    const int wm = wid >> 2, wn = wid & 3;
    const int m0 = blockIdx.y * 128;
    const int bx = blockIdx.x;
    const int LDWB = HW ? (2 * TOTF) : HID;

    const int brow = tid >> 3;
    const int bseg = tid & 7;
    int bcol;
    if (HW) bcol = (bseg < 4) ? bx * 64 + bseg * 16 : TOTF + bx * 64 + (bseg - 4) * 16;
    else    bcol = bx * 128 + bseg * 16;

    const int ar0 = tid >> 1;
    const int as0 = (tid & 1) * 2;

    auto STAGE = [&](int b, int k0) {
        const uint32_t base = sb + (uint32_t)b * BUFB;
        {
            const size_t arow_off = (size_t)(m0 + ar0) * TOTF + k0;
            uint32_t d = base + (uint32_t)(ar0 * ASTRIDE * 2);
            #pragma unroll
            for (int s = 0; s < 2; ++s) {
                int seg = as0 + s;
                CPASYNC16(d + seg * 16, (const void*)(Ahi + arow_off + seg * 8));
                CPASYNC16(d + OFF_ALO + seg * 16, (const void*)(Alo + arow_off + seg * 8));
            }
        }
        {
            const size_t bsrc = (size_t)(k0 + brow) * LDWB + bcol;
            uint32_t d = base + OFF_B + (uint32_t)(brow * BSTRIDE * 2 + bseg * 32);
            CPASYNC16(d,      (const void*)(Bh + bsrc));
            CPASYNC16(d + 16, (const void*)(Bh + bsrc + 8));
        }
    };

    float C[4][4][4];
    #pragma unroll
    for (int mi = 0; mi < 4; mi++)
        #pragma unroll
        for (int ni = 0; ni < 4; ni++)
            #pragma unroll
            for (int q = 0; q < 4; q++) C[mi][ni][q] = 0.f;

    const uint32_t a_ln = (uint32_t)(((wm * 64 + (lane & 15)) * ASTRIDE + (lane >> 4) * 8) * 2);
    const uint32_t b_ln = (uint32_t)(((lane & 15) * BSTRIDE + wn * 32 + (lane >> 4) * 8) * 2);

    STAGE(0, 0);
    CPCOMMIT();

    const int NCH = TOTF / 32;
    for (int ci = 0; ci < NCH; ++ci) {
        CPWAIT0();
        __syncthreads();
        if (ci + 1 < NCH) { STAGE((ci + 1) & 1, (ci + 1) * 32); CPCOMMIT(); }

        const uint32_t base = sb + (uint32_t)(ci & 1) * BUFB;
        #pragma unroll
        for (int ks = 0; ks < 2; ++ks) {
            uint32_t ahi[4][4], alo[4][4], bf[4][2];
            const uint32_t aad = base + a_ln + (uint32_t)(ks * 32);
            #pragma unroll
            for (int mi = 0; mi < 4; mi++) {
                ldsm4(aad + mi * (16 * ASTRIDE * 2), ahi[mi]);
                ldsm4(aad + OFF_ALO + mi * (16 * ASTRIDE * 2), alo[mi]);
            }
            const uint32_t bad = base + OFF_B + b_ln + (uint32_t)(ks * 16 * BSTRIDE * 2);
            #pragma unroll
            for (int ng = 0; ng < 2; ng++) {
                uint32_t t[4];
                ldsm4t(bad + ng * 32, t);
                bf[2 * ng][0] = t[0]; bf[2 * ng][1] = t[1];
                bf[2 * ng + 1][0] = t[2]; bf[2 * ng + 1][1] = t[3];
            }
            #pragma unroll
            for (int mi = 0; mi < 4; mi++)
                #pragma unroll
                for (int ni = 0; ni < 4; ni++) {
                    mma_fp(C[mi][ni], ahi[mi], bf[ni]);
                    mma_fp(C[mi][ni], alo[mi], bf[ni]);
                }
        }
        __syncthreads();
    }

    const int crow  = wm * 64 + (lane >> 2);
    const int ccol0 = wn * 32 + (lane & 3) * 2;
    #pragma unroll
    for (int mi = 0; mi < 4; mi++)
        #pragma unroll
        for (int ni = 0; ni < 4; ni++) {
            uint32_t o0 = sb + (uint32_t)(((crow + mi * 16) * 132 + ccol0 + ni * 8) * 4);
            STS64F(o0, C[mi][ni][0], C[mi][ni][1]);
            STS64F(o0 + (uint32_t)(8 * 132 * 4), C[mi][ni][2], C[mi][ni][3]);
        }
    __syncthreads();

    const float* Cs = (const float*)smg;
    if (HW) {
        const int j0h = bx * 64;
        #pragma unroll 4
        for (int t = 0; t < 32; ++t) {
            int idx = t * 256 + tid;
            int m = idx >> 6, u = idx & 63;
            float nl = fmaxf(Cs[m * 132 + u] + bias[j0h + u], 0.f);
            float gv = Cs[m * 132 + 64 + u] + bias[TOTF + j0h + u];
            float g  = 1.f / (1.f + __expf(-gv));
            size_t o = (size_t)(m0 + m) * TOTF + j0h + u;
            float tv = tin[o];
            float vo = g * tv + (1.f - g) * nl;
            outp[o] = vo;
            split1h(vo, OutHi[o], OutLo[o]);
        }
    } else {
        const int j0 = bx * 128;
        #pragma unroll 4
        for (int t = 0; t < 64; ++t) {
            int idx = t * 256 + tid;
            int m = idx >> 7, n = idx & 127;
            outp[(size_t)(m0 + m) * HID + j0 + n] = Cs[m * 132 + n] + bias[j0 + n];
        }
    }
}

// ---------------------------------------------------------------------------
template<int TOK, int W, int FILT, int TX, int TY, int MI, int MJ>
static void launch_conv(const int* ids, const float* emb, const float* cw,
                        const float* cb, float* tout, int colBase)
{
    size_t smem = (size_t)(800 * TOK + 16 * W * FILT) * sizeof(float);
    cudaFuncSetAttribute(conv_kernel<TOK, W, FILT, TX, TY, MI, MJ>,
                         cudaFuncAttributeMaxDynamicSharedMemorySize, (int)smem);
    conv_kernel<TOK, W, FILT, TX, TY, MI, MJ>
        <<<dim3(N_TOK / TOK, 1), 256, smem>>>(ids, emb, cw, cb, tout, colBase);
}

template<int W, int NF, int NT>
static void launch_conv_mma(const int* ids, const float* cw, const float* cb,
                            float* tout, int colBase, int wOff)
{
    int nprep = 16 * W * NF;
    prep_w_kernel<W, NF><<<(nprep + 255) / 256, 256>>>(cw, wOff);
    size_t smem = CX_W + (size_t)(16 * W) * 144 * 2;
    cudaFuncSetAttribute(conv_mma_kernel<W, NF, NT>,
                         cudaFuncAttributeMaxDynamicSharedMemorySize, (int)smem);
    conv_mma_kernel<W, NF, NT>
        <<<dim3(N_TOK / 8, NF / 64 / NT), 256, smem>>>(ids, cb, tout, colBase, wOff);
}

extern "C" void kernel_launch(void* const* d_in, const int* in_sizes, int n_in,
                              void* d_out, int out_size)
{
    const int*   ids = (const int*)  d_in[0];
    const float* emb = (const float*)d_in[1];
    const float* cw[7]; const float* cb[7];
    for (int i = 0; i < 7; i++) {
        cw[i] = (const float*)d_in[2 + 2 * i];
        cb[i] = (const float*)d_in[3 + 2 * i];
    }
    const float* hw_w0 = (const float*)d_in[16];
    const float* hw_b0 = (const float*)d_in[17];
    const float* hw_w1 = (const float*)d_in[18];
    const float* hw_b1 = (const float*)d_in[19];
    const float* pw    = (const float*)d_in[20];
    const float* pb    = (const float*)d_in[21];
    float* out = (float*)d_out;

    float *pT, *pT2;
    cudaGetSymbolAddress((void**)&pT,  g_T);
    cudaGetSymbolAddress((void**)&pT2, g_T2);
    __half *p0hi, *p0lo, *p1hi, *p1lo, *w0h, *w1h, *pwh;
    cudaGetSymbolAddress((void**)&p0hi, g_p0hi);
    cudaGetSymbolAddress((void**)&p0lo, g_p0lo);
    cudaGetSymbolAddress((void**)&p1hi, g_p1hi);
    cudaGetSymbolAddress((void**)&p1lo, g_p1lo);
    cudaGetSymbolAddress((void**)&w0h, g_w0h);
    cudaGetSymbolAddress((void**)&w1h, g_w1h);
    cudaGetSymbolAddress((void**)&pwh, g_pwh);

    prep_emb_kernel<<<(VOCABN * 16 + 255) / 256, 256>>>(emb);
    {
        size_t tot = 2ULL * HWW + PWW;
        int blocks = (int)((tot / 4 + 255) / 256);
        prep_big_kernel<<<blocks, 256>>>(hw_w0, hw_w1, pw);
    }

    launch_conv<16, 1, 32, 16, 16, 1, 2>(ids, emb, cw[0], cb[0], pT,  0);
    launch_conv<16, 2, 32, 16, 16, 1, 2>(ids, emb, cw[1], cb[1], pT, 32);
    launch_conv_mma<3,   64, 1>(ids, cw[2], cb[2], pT,   64,     0);
    launch_conv_mma<4,  128, 2>(ids, cw[3], cb[3], pT,  128,  3072);
    launch_conv_mma<5,  256, 2>(ids, cw[4], cb[4], pT,  256, 11264);
    launch_conv_mma<6,  512, 2>(ids, cw[5], cb[5], pT,  512, 31744);
    launch_conv_mma<7, 1024, 2>(ids, cw[6], cb[6], pT, 1024, 80896);

    cudaFuncSetAttribute(gemm_kernel<true>,
                         cudaFuncAttributeMaxDynamicSharedMemorySize, GEMM_SMEM);
    cudaFuncSetAttribute(gemm_kernel<false>,
                         cudaFuncAttributeMaxDynamicSharedMemorySize, GEMM_SMEM);
    gemm_kernel<true><<<dim3(32, 32), 256, GEMM_SMEM>>>(
        p0hi, p0lo, w0h, pT, hw_b0, pT2, p1hi, p1lo);
    gemm_kernel<true><<<dim3(32, 32), 256, GEMM_SMEM>>>(
        p1hi, p1lo, w1h, pT2, hw_b1, pT, p0hi, p0lo);
    gemm_kernel<false><<<dim3(6, 32), 256, GEMM_SMEM>>>(
        p0hi, p0lo, pwh, nullptr, pb, out, nullptr, nullptr);
}

// round 8
// speedup vs baseline: 3.8637x; 1.2209x over previous
#include <cuda_runtime.h>
#include <cuda_fp16.h>
#include <math.h>
#include <stdint.h>

#define N_TOK 4096
#define TOTF  2048
#define HID   768
#define VOCABN 264

__device__ float g_T [N_TOK * TOTF];
__device__ float g_T2[N_TOK * TOTF];

// fp16 activation plane sets
__device__ __align__(16) __half g_p0hi[N_TOK * TOTF];
__device__ __align__(16) __half g_p0lo[N_TOK * TOTF];
__device__ __align__(16) __half g_p1hi[N_TOK * TOTF];
__device__ __align__(16) __half g_p1lo[N_TOK * TOTF];
// fp16 weight planes (single)
#define HWW (TOTF * 2 * TOTF)
#define PWW (TOTF * HID)
__device__ __align__(16) __half g_w0h[HWW];
__device__ __align__(16) __half g_w1h[HWW];
__device__ __align__(16) __half g_pwh[PWW];
// fp16 conv tables: emb hi/lo (A split), conv weights single fp16
__device__ __align__(16) __half g_ehi[VOCABN * 16];
__device__ __align__(16) __half g_elo[VOCABN * 16];
// offsets: w1:0 w2:512 w3:1536 w4:4608 w5:12800 w6:33280 w7:82432
#define WSP_TOT 197120
__device__ __align__(16) __half g_wsp[WSP_TOT];

// ---------------------------------------------------------------------------
__device__ __forceinline__ uint32_t smem_u32(const void* p) {
    uint32_t a;
    asm("{ .reg .u64 t; cvta.to.shared.u64 t, %1; cvt.u32.u64 %0, t; }"
        : "=r"(a) : "l"(p));
    return a;
}
#define STS128(addr, a, b, c, d) \
    asm volatile("st.shared.v4.b32 [%0], {%1,%2,%3,%4};" \
                 :: "r"(addr), "r"(a), "r"(b), "r"(c), "r"(d) : "memory")
#define STS64F(addr, x, y) \
    asm volatile("st.shared.v2.f32 [%0], {%1,%2};" \
                 :: "r"(addr), "f"(x), "f"(y) : "memory")
#define CPASYNC16(dst, src) \
    asm volatile("cp.async.cg.shared.global [%0], [%1], 16;" \
                 :: "r"(dst), "l"(src) : "memory")
#define CPCOMMIT() asm volatile("cp.async.commit_group;" ::: "memory")
#define CPWAIT0()  asm volatile("cp.async.wait_group 0;" ::: "memory")

__device__ __forceinline__ void ldsm4(uint32_t a, uint32_t* r) {
    asm volatile("ldmatrix.sync.aligned.m8n8.x4.shared.b16 {%0,%1,%2,%3}, [%4];"
                 : "=r"(r[0]), "=r"(r[1]), "=r"(r[2]), "=r"(r[3]) : "r"(a));
}
__device__ __forceinline__ void ldsm4t(uint32_t a, uint32_t* r) {
    asm volatile("ldmatrix.sync.aligned.m8n8.x4.trans.shared.b16 {%0,%1,%2,%3}, [%4];"
                 : "=r"(r[0]), "=r"(r[1]), "=r"(r[2]), "=r"(r[3]) : "r"(a));
}
__device__ __forceinline__ void mma_fp(float* c, const uint32_t* a, const uint32_t* b) {
    asm volatile("mma.sync.aligned.m16n8k16.row.col.f32.f16.f16.f32 "
                 "{%0,%1,%2,%3}, {%4,%5,%6,%7}, {%8,%9}, {%0,%1,%2,%3};"
                 : "+f"(c[0]), "+f"(c[1]), "+f"(c[2]), "+f"(c[3])
                 : "r"(a[0]), "r"(a[1]), "r"(a[2]), "r"(a[3]), "r"(b[0]), "r"(b[1]));
}
__device__ __forceinline__ void split2h(float x0, float x1, __half2& hp, __half2& lp) {
    __half h0 = __float2half_rn(x0), h1 = __float2half_rn(x1);
    float r0 = x0 - __half2float(h0);
    float r1 = x1 - __half2float(h1);
    hp = __halves2half2(h0, h1);
    lp = __halves2half2(__float2half_rn(r0), __float2half_rn(r1));
}
__device__ __forceinline__ void split1h(float x, __half& h, __half& l) {
    h = __float2half_rn(x);
    l = __float2half_rn(x - __half2float(h));
}

// ===========================================================================
// Prep kernels
// ===========================================================================
__global__ void prep_emb_kernel(const float* __restrict__ emb) {
    int i = blockIdx.x * 256 + threadIdx.x;
    if (i < VOCABN * 16) {
        float v = emb[i];
        split1h(v, g_ehi[i], g_elo[i]);
    }
}
// all conv weights -> g_wsp ([k*16+c][f] per width)
__global__ void prep_cw_kernel(const float* __restrict__ c0, const float* __restrict__ c1,
                               const float* __restrict__ c2, const float* __restrict__ c3,
                               const float* __restrict__ c4, const float* __restrict__ c5,
                               const float* __restrict__ c6) {
    int i = blockIdx.x * 256 + threadIdx.x;
    if (i >= WSP_TOT) return;
    const float* cw; int base, NF, W;
    if      (i <   512) { cw = c0; base = 0;     NF =   32; W = 1; }
    else if (i <  1536) { cw = c1; base = 512;   NF =   32; W = 2; }
    else if (i <  4608) { cw = c2; base = 1536;  NF =   64; W = 3; }
    else if (i < 12800) { cw = c3; base = 4608;  NF =  128; W = 4; }
    else if (i < 33280) { cw = c4; base = 12800; NF =  256; W = 5; }
    else if (i < 82432) { cw = c5; base = 33280; NF =  512; W = 6; }
    else                { cw = c6; base = 82432; NF = 1024; W = 7; }
    int local = i - base;
    int row = local / NF, f = local - row * NF;
    int c = row & 15, k = row >> 4;
    g_wsp[i] = __float2half_rn(cw[(f * 16 + c) * W + k]);
}
__global__ void prep_big_kernel(const float* __restrict__ w0,
                                const float* __restrict__ w1,
                                const float* __restrict__ pw) {
    size_t i4 = ((size_t)blockIdx.x * 256 + threadIdx.x) * 4;
    const float* src;
    __half* dh;
    size_t off;
    if (i4 < HWW)                { src = w0; dh = g_w0h; off = i4; }
    else if (i4 < 2 * HWW)       { src = w1; dh = g_w1h; off = i4 - HWW; }
    else if (i4 < 2 * HWW + PWW) { src = pw; dh = g_pwh; off = i4 - 2 * HWW; }
    else return;
    float4 v = *(const float4*)(src + off);
    *(half2*)(dh + off)     = __halves2half2(__float2half_rn(v.x), __float2half_rn(v.y));
    *(half2*)(dh + off + 2) = __halves2half2(__float2half_rn(v.z), __float2half_rn(v.w));
}

// ===========================================================================
// HMMA conv (w=3..7, fp16 2-term): NT filter tiles/block, X staged once
// ===========================================================================
#define CX_LO 21504u           // 8 tok * 56 rows * 48B
#define CX_W  43008u

template<int W, int NF, int NT>
__global__ __launch_bounds__(256)
void conv_mma_kernel(const int* __restrict__ ids, const float* __restrict__ cb,
                     float* __restrict__ tout, int colBase, int wOff)
{
    constexpr int KD = 16 * W;
    constexpr int NPOS = 51 - W;
    extern __shared__ char smc[];
    const uint32_t sb = smem_u32(smc);
    const int tid = threadIdx.x;
    const int lane = tid & 31, wid = tid >> 5;
    const int n0 = blockIdx.x * 8;

    for (int t = tid; t < 448; t += 256) {
        int tok = t / 56, r = t - tok * 56;
        uint32_t dst = sb + (uint32_t)(tok * 2688 + r * 48);
        if (r < 50) {
            int id = ids[(n0 + tok) * 50 + r];
            const uint4* eh = (const uint4*)(g_ehi + id * 16);
            const uint4* el = (const uint4*)(g_elo + id * 16);
            uint4 h0 = eh[0], h1 = eh[1];
            uint4 l0 = el[0], l1 = el[1];
            STS128(dst,          h0.x, h0.y, h0.z, h0.w);
            STS128(dst + 16,     h1.x, h1.y, h1.z, h1.w);
            STS128(dst + CX_LO,      l0.x, l0.y, l0.z, l0.w);
            STS128(dst + CX_LO + 16, l1.x, l1.y, l1.z, l1.w);
        } else {
            STS128(dst, 0u, 0u, 0u, 0u);
            STS128(dst + 16, 0u, 0u, 0u, 0u);
            STS128(dst + CX_LO, 0u, 0u, 0u, 0u);
            STS128(dst + CX_LO + 16, 0u, 0u, 0u, 0u);
        }
    }

    const uint32_t xb = sb + (uint32_t)(wid * 2688 + (lane & 15) * 48 + (lane >> 4) * 16);
    const uint32_t bb = sb + CX_W + (uint32_t)((lane & 15) * 144 + (lane >> 4) * 16);

    for (int ft = 0; ft < NT; ++ft) {
        const int f0 = (blockIdx.y * NT + ft) * 64;
        __syncthreads();
        for (int t = tid; t < KD * 8; t += 256) {
            int row = t >> 3, seg = t & 7;
            int gsrc = wOff + row * NF + f0 + seg * 8;
            uint4 h = *(const uint4*)(g_wsp + gsrc);
            uint32_t d = sb + CX_W + (uint32_t)(row * 144 + seg * 16);
            STS128(d, h.x, h.y, h.z, h.w);
        }
        __syncthreads();

        float C[3][8][4];
        #pragma unroll
        for (int mi = 0; mi < 3; mi++)
            #pragma unroll
            for (int nf = 0; nf < 8; nf++)
                #pragma unroll
                for (int q = 0; q < 4; q++) C[mi][nf][q] = 0.f;

        #pragma unroll
        for (int k = 0; k < W; ++k) {
            uint32_t ah[3][4], al[3][4];
            #pragma unroll
            for (int mi = 0; mi < 3; mi++) {
                ldsm4(xb + (uint32_t)((mi * 16 + k) * 48), ah[mi]);
                ldsm4(xb + (uint32_t)((mi * 16 + k) * 48) + CX_LO, al[mi]);
            }
            uint32_t bf[8][2];
            #pragma unroll
            for (int ng = 0; ng < 4; ng++) {
                uint32_t t4[4];
                ldsm4t(bb + (uint32_t)(k * 16 * 144 + ng * 32), t4);
                bf[2*ng][0] = t4[0]; bf[2*ng][1] = t4[1];
                bf[2*ng+1][0] = t4[2]; bf[2*ng+1][1] = t4[3];
            }
            #pragma unroll
            for (int mi = 0; mi < 3; mi++)
                #pragma unroll
                for (int nf = 0; nf < 8; nf++) {
                    mma_fp(C[mi][nf], ah[mi], bf[nf]);
                    mma_fp(C[mi][nf], al[mi], bf[nf]);
                }
        }

        float m0[8], m1[8];
        #pragma unroll
        for (int nf = 0; nf < 8; nf++) { m0[nf] = -1e30f; m1[nf] = -1e30f; }
        const int r0 = lane >> 2;
        #pragma unroll
        for (int mi = 0; mi < 3; mi++) {
            bool v0 = (mi * 16 + r0) < NPOS;
            bool v1 = (mi * 16 + r0 + 8) < NPOS;
            #pragma unroll
            for (int nf = 0; nf < 8; nf++) {
                if (v0) { m0[nf] = fmaxf(m0[nf], C[mi][nf][0]);
                          m1[nf] = fmaxf(m1[nf], C[mi][nf][1]); }
                if (v1) { m0[nf] = fmaxf(m0[nf], C[mi][nf][2]);
                          m1[nf] = fmaxf(m1[nf], C[mi][nf][3]); }
            }
        }
        #pragma unroll
        for (int nf = 0; nf < 8; nf++) {
            #pragma unroll
            for (int off = 4; off < 32; off <<= 1) {
                m0[nf] = fmaxf(m0[nf], __shfl_xor_sync(0xffffffffu, m0[nf], off));
                m1[nf] = fmaxf(m1[nf], __shfl_xor_sync(0xffffffffu, m1[nf], off));
            }
        }
        if (lane < 4) {
            const int token = n0 + wid;
            const size_t base = (size_t)token * TOTF + colBase + f0;
            float* orow = tout + base;
            #pragma unroll
            for (int nf = 0; nf < 8; nf++) {
                int fl = nf * 8 + lane * 2;
                float2 o;
                o.x = fmaxf(m0[nf] + cb[f0 + fl], 0.f);
                o.y = fmaxf(m1[nf] + cb[f0 + fl + 1], 0.f);
                *(float2*)(orow + fl) = o;
                __half2 hp, lp;
                split2h(o.x, o.y, hp, lp);
                *(__half2*)(g_p0hi + base + fl) = hp;
                *(__half2*)(g_p0lo + base + fl) = lp;
            }
        }
    }
}

// ===========================================================================
// Merged w1+w2 HMMA conv: B cols 0-31 = w1 (k=1 rows zero), 32-63 = w2.
// 4 m-tiles (64 positions); X staged 72 rows/token.
// ===========================================================================
#define M_XLO 27648u           // 8 tok * 72 rows * 48B
#define M_XW  55296u
#define M_SMEM (55296 + 32 * 144)

__global__ __launch_bounds__(256)
void conv_w12_kernel(const int* __restrict__ ids,
                     const float* __restrict__ cb1, const float* __restrict__ cb2,
                     float* __restrict__ tout)
{
    extern __shared__ char smc[];
    const uint32_t sb = smem_u32(smc);
    const int tid = threadIdx.x;
    const int lane = tid & 31, wid = tid >> 5;
    const int n0 = blockIdx.x * 8;

    // X: 72 rows/token (50 real + zeros)
    for (int t = tid; t < 576; t += 256) {
        int tok = t / 72, r = t - tok * 72;
        uint32_t dst = sb + (uint32_t)(tok * 3456 + r * 48);
        if (r < 50) {
            int id = ids[(n0 + tok) * 50 + r];
            const uint4* eh = (const uint4*)(g_ehi + id * 16);
            const uint4* el = (const uint4*)(g_elo + id * 16);
            uint4 h0 = eh[0], h1 = eh[1];
            uint4 l0 = el[0], l1 = el[1];
            STS128(dst,          h0.x, h0.y, h0.z, h0.w);
            STS128(dst + 16,     h1.x, h1.y, h1.z, h1.w);
            STS128(dst + M_XLO,      l0.x, l0.y, l0.z, l0.w);
            STS128(dst + M_XLO + 16, l1.x, l1.y, l1.z, l1.w);
        } else {
            STS128(dst, 0u, 0u, 0u, 0u);
            STS128(dst + 16, 0u, 0u, 0u, 0u);
            STS128(dst + M_XLO, 0u, 0u, 0u, 0u);
            STS128(dst + M_XLO + 16, 0u, 0u, 0u, 0u);
        }
    }
    // B: 32 rows x 64 cols; cols 0-31 w1 (rows 16+ zero), cols 32-63 w2
    {
        int t = tid;   // 256 = 32 rows * 8 segs
        int row = t >> 3, seg = t & 7;
        uint32_t d = sb + M_XW + (uint32_t)(row * 144 + seg * 16);
        if (seg < 4) {
            if (row < 16) {
                uint4 h = *(const uint4*)(g_wsp + 0 + row * 32 + seg * 8);
                STS128(d, h.x, h.y, h.z, h.w);
            } else {
                STS128(d, 0u, 0u, 0u, 0u);
            }
        } else {
            uint4 h = *(const uint4*)(g_wsp + 512 + row * 32 + (seg - 4) * 8);
            STS128(d, h.x, h.y, h.z, h.w);
        }
    }
    __syncthreads();

    const uint32_t xb = sb + (uint32_t)(wid * 3456 + (lane & 15) * 48 + (lane >> 4) * 16);
    const uint32_t bb = sb + M_XW + (uint32_t)((lane & 15) * 144 + (lane >> 4) * 16);

    float C[4][8][4];
    #pragma unroll
    for (int mi = 0; mi < 4; mi++)
        #pragma unroll
        for (int nf = 0; nf < 8; nf++)
            #pragma unroll
            for (int q = 0; q < 4; q++) C[mi][nf][q] = 0.f;

    #pragma unroll
    for (int k = 0; k < 2; ++k) {
        uint32_t ah[4][4], al[4][4];
        #pragma unroll
        for (int mi = 0; mi < 4; mi++) {
            ldsm4(xb + (uint32_t)((mi * 16 + k) * 48), ah[mi]);
            ldsm4(xb + (uint32_t)((mi * 16 + k) * 48) + M_XLO, al[mi]);
        }
        uint32_t bf[8][2];
        #pragma unroll
        for (int ng = 0; ng < 4; ng++) {
            uint32_t t4[4];
            ldsm4t(bb + (uint32_t)(k * 16 * 144 + ng * 32), t4);
            bf[2*ng][0] = t4[0]; bf[2*ng][1] = t4[1];
            bf[2*ng+1][0] = t4[2]; bf[2*ng+1][1] = t4[3];
        }
        #pragma unroll
        for (int mi = 0; mi < 4; mi++)
            #pragma unroll
            for (int nf = 0; nf < 8; nf++) {
                mma_fp(C[mi][nf], ah[mi], bf[nf]);
                mma_fp(C[mi][nf], al[mi], bf[nf]);
            }
    }

    float m0[8], m1[8];
    #pragma unroll
    for (int nf = 0; nf < 8; nf++) { m0[nf] = -1e30f; m1[nf] = -1e30f; }
    const int r0 = lane >> 2;
    #pragma unroll
    for (int mi = 0; mi < 4; mi++) {
        #pragma unroll
        for (int nf = 0; nf < 8; nf++) {
            int lim = (nf < 4) ? 50 : 49;     // w1 NPOS=50, w2 NPOS=49
            bool v0 = (mi * 16 + r0) < lim;
            bool v1 = (mi * 16 + r0 + 8) < lim;
            if (v0) { m0[nf] = fmaxf(m0[nf], C[mi][nf][0]);
                      m1[nf] = fmaxf(m1[nf], C[mi][nf][1]); }
            if (v1) { m0[nf] = fmaxf(m0[nf], C[mi][nf][2]);
                      m1[nf] = fmaxf(m1[nf], C[mi][nf][3]); }
        }
    }
    #pragma unroll
    for (int nf = 0; nf < 8; nf++) {
        #pragma unroll
        for (int off = 4; off < 32; off <<= 1) {
            m0[nf] = fmaxf(m0[nf], __shfl_xor_sync(0xffffffffu, m0[nf], off));
            m1[nf] = fmaxf(m1[nf], __shfl_xor_sync(0xffffffffu, m1[nf], off));
        }
    }
    if (lane < 4) {
        const int token = n0 + wid;
        const size_t base = (size_t)token * TOTF;   // cols 0..63
        float* orow = tout + base;
        #pragma unroll
        for (int nf = 0; nf < 8; nf++) {
            int fl = nf * 8 + lane * 2;
            float b0 = (fl < 32) ? cb1[fl] : cb2[fl - 32];
            float b1 = (fl < 32) ? cb1[fl + 1] : cb2[fl - 31];
            float2 o;
            o.x = fmaxf(m0[nf] + b0, 0.f);
            o.y = fmaxf(m1[nf] + b1, 0.f);
            *(float2*)(orow + fl) = o;
            __half2 hp, lp;
            split2h(o.x, o.y, hp, lp);
            *(__half2*)(g_p0hi + base + fl) = hp;
            *(__half2*)(g_p0lo + base + fl) = lp;
        }
    }
}

// ===========================================================================
// fp16 2-term GEMM (unchanged from round 7)
// ===========================================================================
#define ASTRIDE 40
#define BSTRIDE 136
#define OFF_ALO 10240
#define OFF_B   20480
#define BUFB 29184
#define GEMM_SMEM 67584

template<bool HW>
__global__ __launch_bounds__(256, 2)
void gemm_kernel(const __half* __restrict__ Ahi,
                 const __half* __restrict__ Alo,
                 const __half* __restrict__ Bh,
                 const float* __restrict__ tin,
                 const float* __restrict__ bias,
                 float* __restrict__ outp,
                 __half* __restrict__ OutHi,
                 __half* __restrict__ OutLo)
{
    extern __shared__ char smg[];
    const uint32_t sb = smem_u32(smg);
    const int tid  = threadIdx.x;
    const int lane = tid & 31, wid = tid >> 5;
    const int wm = wid >> 2, wn = wid & 3;
    const int m0 = blockIdx.y * 128;
    const int bx = blockIdx.x;
    const int LDWB = HW ? (2 * TOTF) : HID;

    const int brow = tid >> 3;
    const int bseg = tid & 7;
    int bcol;
    if (HW) bcol = (bseg < 4) ? bx * 64 + bseg * 16 : TOTF + bx * 64 + (bseg - 4) * 16;
    else    bcol = bx * 128 + bseg * 16;

    const int ar0 = tid >> 1;
    const int as0 = (tid & 1) * 2;

    auto STAGE = [&](int b, int k0) {
        const uint32_t base = sb + (uint32_t)b * BUFB;
        {
            const size_t arow_off = (size_t)(m0 + ar0) * TOTF + k0;
            uint32_t d = base + (uint32_t)(ar0 * ASTRIDE * 2);
            #pragma unroll
            for (int s = 0; s < 2; ++s) {
                int seg = as0 + s;
                CPASYNC16(d + seg * 16, (const void*)(Ahi + arow_off + seg * 8));
                CPASYNC16(d + OFF_ALO + seg * 16, (const void*)(Alo + arow_off + seg * 8));
            }
        }
        {
            const size_t bsrc = (size_t)(k0 + brow) * LDWB + bcol;
            uint32_t d = base + OFF_B + (uint32_t)(brow * BSTRIDE * 2 + bseg * 32);
            CPASYNC16(d,      (const void*)(Bh + bsrc));
            CPASYNC16(d + 16, (const void*)(Bh + bsrc + 8));
        }
    };

    float C[4][4][4];
    #pragma unroll
    for (int mi = 0; mi < 4; mi++)
        #pragma unroll
        for (int ni = 0; ni < 4; ni++)
            #pragma unroll
            for (int q = 0; q < 4; q++) C[mi][ni][q] = 0.f;

    const uint32_t a_ln = (uint32_t)(((wm * 64 + (lane & 15)) * ASTRIDE + (lane >> 4) * 8) * 2);
    const uint32_t b_ln = (uint32_t)(((lane & 15) * BSTRIDE + wn * 32 + (lane >> 4) * 8) * 2);

    STAGE(0, 0);
    CPCOMMIT();

    const int NCH = TOTF / 32;
    for (int ci = 0; ci < NCH; ++ci) {
        CPWAIT0();
        __syncthreads();
        if (ci + 1 < NCH) { STAGE((ci + 1) & 1, (ci + 1) * 32); CPCOMMIT(); }

        const uint32_t base = sb + (uint32_t)(ci & 1) * BUFB;
        #pragma unroll
        for (int ks = 0; ks < 2; ++ks) {
            uint32_t ahi[4][4], alo[4][4], bf[4][2];
            const uint32_t aad = base + a_ln + (uint32_t)(ks * 32);
            #pragma unroll
            for (int mi = 0; mi < 4; mi++) {
                ldsm4(aad + mi * (16 * ASTRIDE * 2), ahi[mi]);
                ldsm4(aad + OFF_ALO + mi * (16 * ASTRIDE * 2), alo[mi]);
            }
            const uint32_t bad = base + OFF_B + b_ln + (uint32_t)(ks * 16 * BSTRIDE * 2);
            #pragma unroll
            for (int ng = 0; ng < 2; ng++) {
                uint32_t t[4];
                ldsm4t(bad + ng * 32, t);
                bf[2 * ng][0] = t[0]; bf[2 * ng][1] = t[1];
                bf[2 * ng + 1][0] = t[2]; bf[2 * ng + 1][1] = t[3];
            }
            #pragma unroll
            for (int mi = 0; mi < 4; mi++)
                #pragma unroll
                for (int ni = 0; ni < 4; ni++) {
                    mma_fp(C[mi][ni], ahi[mi], bf[ni]);
                    mma_fp(C[mi][ni], alo[mi], bf[ni]);
                }
        }
        __syncthreads();
    }

    const int crow  = wm * 64 + (lane >> 2);
    const int ccol0 = wn * 32 + (lane & 3) * 2;
    #pragma unroll
    for (int mi = 0; mi < 4; mi++)
        #pragma unroll
        for (int ni = 0; ni < 4; ni++) {
            uint32_t o0 = sb + (uint32_t)(((crow + mi * 16) * 132 + ccol0 + ni * 8) * 4);
            STS64F(o0, C[mi][ni][0], C[mi][ni][1]);
            STS64F(o0 + (uint32_t)(8 * 132 * 4), C[mi][ni][2], C[mi][ni][3]);
        }
    __syncthreads();

    const float* Cs = (const float*)smg;
    if (HW) {
        const int j0h = bx * 64;
        #pragma unroll 4
        for (int t = 0; t < 32; ++t) {
            int idx = t * 256 + tid;
            int m = idx >> 6, u = idx & 63;
            float nl = fmaxf(Cs[m * 132 + u] + bias[j0h + u], 0.f);
            float gv = Cs[m * 132 + 64 + u] + bias[TOTF + j0h + u];
            float g  = 1.f / (1.f + __expf(-gv));
            size_t o = (size_t)(m0 + m) * TOTF + j0h + u;
            float tv = tin[o];
            float vo = g * tv + (1.f - g) * nl;
            outp[o] = vo;
            split1h(vo, OutHi[o], OutLo[o]);
        }
    } else {
        const int j0 = bx * 128;
        #pragma unroll 4
        for (int t = 0; t < 64; ++t) {
            int idx = t * 256 + tid;
            int m = idx >> 7, n = idx & 127;
            outp[(size_t)(m0 + m) * HID + j0 + n] = Cs[m * 132 + n] + bias[j0 + n];
        }
    }
}

// ---------------------------------------------------------------------------
template<int W, int NF, int NT>
static void launch_conv_mma(const int* ids, const float* cb,
                            float* tout, int colBase, int wOff)
{
    size_t smem = CX_W + (size_t)(16 * W) * 144;
    cudaFuncSetAttribute(conv_mma_kernel<W, NF, NT>,
                         cudaFuncAttributeMaxDynamicSharedMemorySize, (int)smem);
    conv_mma_kernel<W, NF, NT>
        <<<dim3(N_TOK / 8, NF / 64 / NT), 256, smem>>>(ids, cb, tout, colBase, wOff);
}

extern "C" void kernel_launch(void* const* d_in, const int* in_sizes, int n_in,
                              void* d_out, int out_size)
{
    const int*   ids = (const int*)  d_in[0];
    const float* emb = (const float*)d_in[1];
    const float* cw[7]; const float* cb[7];
    for (int i = 0; i < 7; i++) {
        cw[i] = (const float*)d_in[2 + 2 * i];
        cb[i] = (const float*)d_in[3 + 2 * i];
    }
    const float* hw_w0 = (const float*)d_in[16];
    const float* hw_b0 = (const float*)d_in[17];
    const float* hw_w1 = (const float*)d_in[18];
    const float* hw_b1 = (const float*)d_in[19];
    const float* pw    = (const float*)d_in[20];
    const float* pb    = (const float*)d_in[21];
    float* out = (float*)d_out;

    float *pT, *pT2;
    cudaGetSymbolAddress((void**)&pT,  g_T);
    cudaGetSymbolAddress((void**)&pT2, g_T2);
    __half *p0hi, *p0lo, *p1hi, *p1lo, *w0h, *w1h, *pwh;
    cudaGetSymbolAddress((void**)&p0hi, g_p0hi);
    cudaGetSymbolAddress((void**)&p0lo, g_p0lo);
    cudaGetSymbolAddress((void**)&p1hi, g_p1hi);
    cudaGetSymbolAddress((void**)&p1lo, g_p1lo);
    cudaGetSymbolAddress((void**)&w0h, g_w0h);
    cudaGetSymbolAddress((void**)&w1h, g_w1h);
    cudaGetSymbolAddress((void**)&pwh, g_pwh);

    prep_emb_kernel<<<(VOCABN * 16 + 255) / 256, 256>>>(emb);
    prep_cw_kernel<<<(WSP_TOT + 255) / 256, 256>>>(
        cw[0], cw[1], cw[2], cw[3], cw[4], cw[5], cw[6]);
    {
        size_t tot = 2ULL * HWW + PWW;
        int blocks = (int)((tot / 4 + 255) / 256);
        prep_big_kernel<<<blocks, 256>>>(hw_w0, hw_w1, pw);
    }

    // merged w1+w2 HMMA
    cudaFuncSetAttribute(conv_w12_kernel,
                         cudaFuncAttributeMaxDynamicSharedMemorySize, M_SMEM);
    conv_w12_kernel<<<N_TOK / 8, 256, M_SMEM>>>(ids, cb[0], cb[1], pT);

    // w3..w7 HMMA (fp16 2-term)
    launch_conv_mma<3,   64, 1>(ids, cb[2], pT,   64,  1536);
    launch_conv_mma<4,  128, 2>(ids, cb[3], pT,  128,  4608);
    launch_conv_mma<5,  256, 2>(ids, cb[4], pT,  256, 12800);
    launch_conv_mma<6,  512, 2>(ids, cb[5], pT,  512, 33280);
    launch_conv_mma<7, 1024, 2>(ids, cb[6], pT, 1024, 82432);

    cudaFuncSetAttribute(gemm_kernel<true>,
                         cudaFuncAttributeMaxDynamicSharedMemorySize, GEMM_SMEM);
    cudaFuncSetAttribute(gemm_kernel<false>,
                         cudaFuncAttributeMaxDynamicSharedMemorySize, GEMM_SMEM);
    gemm_kernel<true><<<dim3(32, 32), 256, GEMM_SMEM>>>(
        p0hi, p0lo, w0h, pT, hw_b0, pT2, p1hi, p1lo);
    gemm_kernel<true><<<dim3(32, 32), 256, GEMM_SMEM>>>(
        p1hi, p1lo, w1h, pT2, hw_b1, pT, p0hi, p0lo);
    gemm_kernel<false><<<dim3(6, 32), 256, GEMM_SMEM>>>(
        p0hi, p0lo, pwh, nullptr, pb, out, nullptr, nullptr);
}

// round 9
// speedup vs baseline: 5.2063x; 1.3475x over previous
#include <cuda_runtime.h>
#include <cuda_fp16.h>
#include <math.h>
#include <stdint.h>

#define N_TOK 4096
#define TOTF  2048
#define HID   768
#define VOCABN 264

__device__ float g_T [N_TOK * TOTF];
__device__ float g_T2[N_TOK * TOTF];

// single fp16 activation planes (P0: convs & hw2 out; P1: hw1 out)
__device__ __align__(16) __half g_p0h[N_TOK * TOTF];
__device__ __align__(16) __half g_p1h[N_TOK * TOTF];
// fp16 weight planes
#define HWW (TOTF * 2 * TOTF)
#define PWW (TOTF * HID)
__device__ __align__(16) __half g_w0h[HWW];
__device__ __align__(16) __half g_w1h[HWW];
__device__ __align__(16) __half g_pwh[PWW];
// fp16 conv tables: emb hi/lo (2-term A), conv weights single fp16
__device__ __align__(16) __half g_ehi[VOCABN * 16];
__device__ __align__(16) __half g_elo[VOCABN * 16];
// offsets: w1:0 w2:512 w3:1536 w4:4608 w5:12800 w6:33280 w7:82432
#define WSP_TOT 197120
__device__ __align__(16) __half g_wsp[WSP_TOT];

// ---------------------------------------------------------------------------
__device__ __forceinline__ uint32_t smem_u32(const void* p) {
    uint32_t a;
    asm("{ .reg .u64 t; cvta.to.shared.u64 t, %1; cvt.u32.u64 %0, t; }"
        : "=r"(a) : "l"(p));
    return a;
}
#define STS128(addr, a, b, c, d) \
    asm volatile("st.shared.v4.b32 [%0], {%1,%2,%3,%4};" \
                 :: "r"(addr), "r"(a), "r"(b), "r"(c), "r"(d) : "memory")
#define STS64F(addr, x, y) \
    asm volatile("st.shared.v2.f32 [%0], {%1,%2};" \
                 :: "r"(addr), "f"(x), "f"(y) : "memory")
#define CPASYNC16(dst, src) \
    asm volatile("cp.async.cg.shared.global [%0], [%1], 16;" \
                 :: "r"(dst), "l"(src) : "memory")
#define CPCOMMIT() asm volatile("cp.async.commit_group;" ::: "memory")
#define CPWAIT0()  asm volatile("cp.async.wait_group 0;" ::: "memory")

__device__ __forceinline__ void ldsm4(uint32_t a, uint32_t* r) {
    asm volatile("ldmatrix.sync.aligned.m8n8.x4.shared.b16 {%0,%1,%2,%3}, [%4];"
                 : "=r"(r[0]), "=r"(r[1]), "=r"(r[2]), "=r"(r[3]) : "r"(a));
}
__device__ __forceinline__ void ldsm4t(uint32_t a, uint32_t* r) {
    asm volatile("ldmatrix.sync.aligned.m8n8.x4.trans.shared.b16 {%0,%1,%2,%3}, [%4];"
                 : "=r"(r[0]), "=r"(r[1]), "=r"(r[2]), "=r"(r[3]) : "r"(a));
}
__device__ __forceinline__ void mma_fp(float* c, const uint32_t* a, const uint32_t* b) {
    asm volatile("mma.sync.aligned.m16n8k16.row.col.f32.f16.f16.f32 "
                 "{%0,%1,%2,%3}, {%4,%5,%6,%7}, {%8,%9}, {%0,%1,%2,%3};"
                 : "+f"(c[0]), "+f"(c[1]), "+f"(c[2]), "+f"(c[3])
                 : "r"(a[0]), "r"(a[1]), "r"(a[2]), "r"(a[3]), "r"(b[0]), "r"(b[1]));
}
__device__ __forceinline__ void split1h(float x, __half& h, __half& l) {
    h = __float2half_rn(x);
    l = __float2half_rn(x - __half2float(h));
}

// ===========================================================================
// Prep kernels
// ===========================================================================
__global__ void prep_emb_kernel(const float* __restrict__ emb) {
    int i = blockIdx.x * 256 + threadIdx.x;
    if (i < VOCABN * 16) {
        float v = emb[i];
        split1h(v, g_ehi[i], g_elo[i]);
    }
}
__global__ void prep_cw_kernel(const float* __restrict__ c0, const float* __restrict__ c1,
                               const float* __restrict__ c2, const float* __restrict__ c3,
                               const float* __restrict__ c4, const float* __restrict__ c5,
                               const float* __restrict__ c6) {
    int i = blockIdx.x * 256 + threadIdx.x;
    if (i >= WSP_TOT) return;
    const float* cw; int base, NF, W;
    if      (i <   512) { cw = c0; base = 0;     NF =   32; W = 1; }
    else if (i <  1536) { cw = c1; base = 512;   NF =   32; W = 2; }
    else if (i <  4608) { cw = c2; base = 1536;  NF =   64; W = 3; }
    else if (i < 12800) { cw = c3; base = 4608;  NF =  128; W = 4; }
    else if (i < 33280) { cw = c4; base = 12800; NF =  256; W = 5; }
    else if (i < 82432) { cw = c5; base = 33280; NF =  512; W = 6; }
    else                { cw = c6; base = 82432; NF = 1024; W = 7; }
    int local = i - base;
    int row = local / NF, f = local - row * NF;
    int c = row & 15, k = row >> 4;
    g_wsp[i] = __float2half_rn(cw[(f * 16 + c) * W + k]);
}
__global__ void prep_big_kernel(const float* __restrict__ w0,
                                const float* __restrict__ w1,
                                const float* __restrict__ pw) {
    size_t i4 = ((size_t)blockIdx.x * 256 + threadIdx.x) * 4;
    const float* src;
    __half* dh;
    size_t off;
    if (i4 < HWW)                { src = w0; dh = g_w0h; off = i4; }
    else if (i4 < 2 * HWW)       { src = w1; dh = g_w1h; off = i4 - HWW; }
    else if (i4 < 2 * HWW + PWW) { src = pw; dh = g_pwh; off = i4 - 2 * HWW; }
    else return;
    float4 v = *(const float4*)(src + off);
    *(half2*)(dh + off)     = __halves2half2(__float2half_rn(v.x), __float2half_rn(v.y));
    *(half2*)(dh + off + 2) = __halves2half2(__float2half_rn(v.z), __float2half_rn(v.w));
}

// ===========================================================================
// HMMA conv (w=3..7, fp16 2-term A): NT filter tiles/block, X staged once
// ===========================================================================
#define CX_LO 21504u
#define CX_W  43008u

template<int W, int NF, int NT>
__global__ __launch_bounds__(256)
void conv_mma_kernel(const int* __restrict__ ids, const float* __restrict__ cb,
                     float* __restrict__ tout, int colBase, int wOff)
{
    constexpr int KD = 16 * W;
    constexpr int NPOS = 51 - W;
    extern __shared__ char smc[];
    const uint32_t sb = smem_u32(smc);
    const int tid = threadIdx.x;
    const int lane = tid & 31, wid = tid >> 5;
    const int n0 = blockIdx.x * 8;

    for (int t = tid; t < 448; t += 256) {
        int tok = t / 56, r = t - tok * 56;
        uint32_t dst = sb + (uint32_t)(tok * 2688 + r * 48);
        if (r < 50) {
            int id = ids[(n0 + tok) * 50 + r];
            const uint4* eh = (const uint4*)(g_ehi + id * 16);
            const uint4* el = (const uint4*)(g_elo + id * 16);
            uint4 h0 = eh[0], h1 = eh[1];
            uint4 l0 = el[0], l1 = el[1];
            STS128(dst,          h0.x, h0.y, h0.z, h0.w);
            STS128(dst + 16,     h1.x, h1.y, h1.z, h1.w);
            STS128(dst + CX_LO,      l0.x, l0.y, l0.z, l0.w);
            STS128(dst + CX_LO + 16, l1.x, l1.y, l1.z, l1.w);
        } else {
            STS128(dst, 0u, 0u, 0u, 0u);
            STS128(dst + 16, 0u, 0u, 0u, 0u);
            STS128(dst + CX_LO, 0u, 0u, 0u, 0u);
            STS128(dst + CX_LO + 16, 0u, 0u, 0u, 0u);
        }
    }

    const uint32_t xb = sb + (uint32_t)(wid * 2688 + (lane & 15) * 48 + (lane >> 4) * 16);
    const uint32_t bb = sb + CX_W + (uint32_t)((lane & 15) * 144 + (lane >> 4) * 16);

    for (int ft = 0; ft < NT; ++ft) {
        const int f0 = (blockIdx.y * NT + ft) * 64;
        __syncthreads();
        for (int t = tid; t < KD * 8; t += 256) {
            int row = t >> 3, seg = t & 7;
            int gsrc = wOff + row * NF + f0 + seg * 8;
            uint4 h = *(const uint4*)(g_wsp + gsrc);
            uint32_t d = sb + CX_W + (uint32_t)(row * 144 + seg * 16);
            STS128(d, h.x, h.y, h.z, h.w);
        }
        __syncthreads();

        float C[3][8][4];
        #pragma unroll
        for (int mi = 0; mi < 3; mi++)
            #pragma unroll
            for (int nf = 0; nf < 8; nf++)
                #pragma unroll
                for (int q = 0; q < 4; q++) C[mi][nf][q] = 0.f;

        #pragma unroll
        for (int k = 0; k < W; ++k) {
            uint32_t ah[3][4], al[3][4];
            #pragma unroll
            for (int mi = 0; mi < 3; mi++) {
                ldsm4(xb + (uint32_t)((mi * 16 + k) * 48), ah[mi]);
                ldsm4(xb + (uint32_t)((mi * 16 + k) * 48) + CX_LO, al[mi]);
            }
            uint32_t bf[8][2];
            #pragma unroll
            for (int ng = 0; ng < 4; ng++) {
                uint32_t t4[4];
                ldsm4t(bb + (uint32_t)(k * 16 * 144 + ng * 32), t4);
                bf[2*ng][0] = t4[0]; bf[2*ng][1] = t4[1];
                bf[2*ng+1][0] = t4[2]; bf[2*ng+1][1] = t4[3];
            }
            #pragma unroll
            for (int mi = 0; mi < 3; mi++)
                #pragma unroll
                for (int nf = 0; nf < 8; nf++) {
                    mma_fp(C[mi][nf], ah[mi], bf[nf]);
                    mma_fp(C[mi][nf], al[mi], bf[nf]);
                }
        }

        float m0[8], m1[8];
        #pragma unroll
        for (int nf = 0; nf < 8; nf++) { m0[nf] = -1e30f; m1[nf] = -1e30f; }
        const int r0 = lane >> 2;
        #pragma unroll
        for (int mi = 0; mi < 3; mi++) {
            bool v0 = (mi * 16 + r0) < NPOS;
            bool v1 = (mi * 16 + r0 + 8) < NPOS;
            #pragma unroll
            for (int nf = 0; nf < 8; nf++) {
                if (v0) { m0[nf] = fmaxf(m0[nf], C[mi][nf][0]);
                          m1[nf] = fmaxf(m1[nf], C[mi][nf][1]); }
                if (v1) { m0[nf] = fmaxf(m0[nf], C[mi][nf][2]);
                          m1[nf] = fmaxf(m1[nf], C[mi][nf][3]); }
            }
        }
        #pragma unroll
        for (int nf = 0; nf < 8; nf++) {
            #pragma unroll
            for (int off = 4; off < 32; off <<= 1) {
                m0[nf] = fmaxf(m0[nf], __shfl_xor_sync(0xffffffffu, m0[nf], off));
                m1[nf] = fmaxf(m1[nf], __shfl_xor_sync(0xffffffffu, m1[nf], off));
            }
        }
        if (lane < 4) {
            const int token = n0 + wid;
            const size_t base = (size_t)token * TOTF + colBase + f0;
            float* orow = tout + base;
            #pragma unroll
            for (int nf = 0; nf < 8; nf++) {
                int fl = nf * 8 + lane * 2;
                float2 o;
                o.x = fmaxf(m0[nf] + cb[f0 + fl], 0.f);
                o.y = fmaxf(m1[nf] + cb[f0 + fl + 1], 0.f);
                *(float2*)(orow + fl) = o;
                *(__half2*)(g_p0h + base + fl) =
                    __halves2half2(__float2half_rn(o.x), __float2half_rn(o.y));
            }
        }
    }
}

// ===========================================================================
// Merged w1+w2 HMMA conv
// ===========================================================================
#define M_XLO 27648u
#define M_XW  55296u
#define M_SMEM (55296 + 32 * 144)

__global__ __launch_bounds__(256)
void conv_w12_kernel(const int* __restrict__ ids,
                     const float* __restrict__ cb1, const float* __restrict__ cb2,
                     float* __restrict__ tout)
{
    extern __shared__ char smc[];
    const uint32_t sb = smem_u32(smc);
    const int tid = threadIdx.x;
    const int lane = tid & 31, wid = tid >> 5;
    const int n0 = blockIdx.x * 8;

    for (int t = tid; t < 576; t += 256) {
        int tok = t / 72, r = t - tok * 72;
        uint32_t dst = sb + (uint32_t)(tok * 3456 + r * 48);
        if (r < 50) {
            int id = ids[(n0 + tok) * 50 + r];
            const uint4* eh = (const uint4*)(g_ehi + id * 16);
            const uint4* el = (const uint4*)(g_elo + id * 16);
            uint4 h0 = eh[0], h1 = eh[1];
            uint4 l0 = el[0], l1 = el[1];
            STS128(dst,          h0.x, h0.y, h0.z, h0.w);
            STS128(dst + 16,     h1.x, h1.y, h1.z, h1.w);
            STS128(dst + M_XLO,      l0.x, l0.y, l0.z, l0.w);
            STS128(dst + M_XLO + 16, l1.x, l1.y, l1.z, l1.w);
        } else {
            STS128(dst, 0u, 0u, 0u, 0u);
            STS128(dst + 16, 0u, 0u, 0u, 0u);
            STS128(dst + M_XLO, 0u, 0u, 0u, 0u);
            STS128(dst + M_XLO + 16, 0u, 0u, 0u, 0u);
        }
    }
    {
        int t = tid;
        int row = t >> 3, seg = t & 7;
        uint32_t d = sb + M_XW + (uint32_t)(row * 144 + seg * 16);
        if (seg < 4) {
            if (row < 16) {
                uint4 h = *(const uint4*)(g_wsp + 0 + row * 32 + seg * 8);
                STS128(d, h.x, h.y, h.z, h.w);
            } else {
                STS128(d, 0u, 0u, 0u, 0u);
            }
        } else {
            uint4 h = *(const uint4*)(g_wsp + 512 + row * 32 + (seg - 4) * 8);
            STS128(d, h.x, h.y, h.z, h.w);
        }
    }
    __syncthreads();

    const uint32_t xb = sb + (uint32_t)(wid * 3456 + (lane & 15) * 48 + (lane >> 4) * 16);
    const uint32_t bb = sb + M_XW + (uint32_t)((lane & 15) * 144 + (lane >> 4) * 16);

    float C[4][8][4];
    #pragma unroll
    for (int mi = 0; mi < 4; mi++)
        #pragma unroll
        for (int nf = 0; nf < 8; nf++)
            #pragma unroll
            for (int q = 0; q < 4; q++) C[mi][nf][q] = 0.f;

    #pragma unroll
    for (int k = 0; k < 2; ++k) {
        uint32_t ah[4][4], al[4][4];
        #pragma unroll
        for (int mi = 0; mi < 4; mi++) {
            ldsm4(xb + (uint32_t)((mi * 16 + k) * 48), ah[mi]);
            ldsm4(xb + (uint32_t)((mi * 16 + k) * 48) + M_XLO, al[mi]);
        }
        uint32_t bf[8][2];
        #pragma unroll
        for (int ng = 0; ng < 4; ng++) {
            uint32_t t4[4];
            ldsm4t(bb + (uint32_t)(k * 16 * 144 + ng * 32), t4);
            bf[2*ng][0] = t4[0]; bf[2*ng][1] = t4[1];
            bf[2*ng+1][0] = t4[2]; bf[2*ng+1][1] = t4[3];
        }
        #pragma unroll
        for (int mi = 0; mi < 4; mi++)
            #pragma unroll
            for (int nf = 0; nf < 8; nf++) {
                mma_fp(C[mi][nf], ah[mi], bf[nf]);
                mma_fp(C[mi][nf], al[mi], bf[nf]);
            }
    }

    float m0[8], m1[8];
    #pragma unroll
    for (int nf = 0; nf < 8; nf++) { m0[nf] = -1e30f; m1[nf] = -1e30f; }
    const int r0 = lane >> 2;
    #pragma unroll
    for (int mi = 0; mi < 4; mi++) {
        #pragma unroll
        for (int nf = 0; nf < 8; nf++) {
            int lim = (nf < 4) ? 50 : 49;
            bool v0 = (mi * 16 + r0) < lim;
            bool v1 = (mi * 16 + r0 + 8) < lim;
            if (v0) { m0[nf] = fmaxf(m0[nf], C[mi][nf][0]);
                      m1[nf] = fmaxf(m1[nf], C[mi][nf][1]); }
            if (v1) { m0[nf] = fmaxf(m0[nf], C[mi][nf][2]);
                      m1[nf] = fmaxf(m1[nf], C[mi][nf][3]); }
        }
    }
    #pragma unroll
    for (int nf = 0; nf < 8; nf++) {
        #pragma unroll
        for (int off = 4; off < 32; off <<= 1) {
            m0[nf] = fmaxf(m0[nf], __shfl_xor_sync(0xffffffffu, m0[nf], off));
            m1[nf] = fmaxf(m1[nf], __shfl_xor_sync(0xffffffffu, m1[nf], off));
        }
    }
    if (lane < 4) {
        const int token = n0 + wid;
        const size_t base = (size_t)token * TOTF;
        float* orow = tout + base;
        #pragma unroll
        for (int nf = 0; nf < 8; nf++) {
            int fl = nf * 8 + lane * 2;
            float b0 = (fl < 32) ? cb1[fl] : cb2[fl - 32];
            float b1 = (fl < 32) ? cb1[fl + 1] : cb2[fl - 31];
            float2 o;
            o.x = fmaxf(m0[nf] + b0, 0.f);
            o.y = fmaxf(m1[nf] + b1, 0.f);
            *(float2*)(orow + fl) = o;
            *(__half2*)(g_p0h + base + fl) =
                __halves2half2(__float2half_rn(o.x), __float2half_rn(o.y));
        }
    }
}

// ===========================================================================
// Single-term fp16 GEMM: C = fp16(A) @ fp16(B).  cp.async, 2 CTAs/SM.
// ===========================================================================
#define ASTRIDE 40
#define BSTRIDE 136
#define OFF_B   10240
#define BUFB 18944
#define GEMM_SMEM 67584   // epilogue C smem 128*132*4 dominates

template<bool HW>
__global__ __launch_bounds__(256, 2)
void gemm_kernel(const __half* __restrict__ Ah,
                 const __half* __restrict__ Bh,
                 const float* __restrict__ tin,
                 const float* __restrict__ bias,
                 float* __restrict__ outp,
                 __half* __restrict__ OutH)
{
    extern __shared__ char smg[];
    const uint32_t sb = smem_u32(smg);
    const int tid  = threadIdx.x;
    const int lane = tid & 31, wid = tid >> 5;
    const int wm = wid >> 2, wn = wid & 3;
    const int m0 = blockIdx.y * 128;
    const int bx = blockIdx.x;
    const int LDWB = HW ? (2 * TOTF) : HID;

    const int brow = tid >> 3;
    const int bseg = tid & 7;
    int bcol;
    if (HW) bcol = (bseg < 4) ? bx * 64 + bseg * 16 : TOTF + bx * 64 + (bseg - 4) * 16;
    else    bcol = bx * 128 + bseg * 16;

    const int ar0 = tid >> 1;
    const int as0 = (tid & 1) * 2;

    auto STAGE = [&](int b, int k0) {
        const uint32_t base = sb + (uint32_t)b * BUFB;
        {
            const size_t arow_off = (size_t)(m0 + ar0) * TOTF + k0;
            uint32_t d = base + (uint32_t)(ar0 * ASTRIDE * 2);
            #pragma unroll
            for (int s = 0; s < 2; ++s) {
                int seg = as0 + s;
                CPASYNC16(d + seg * 16, (const void*)(Ah + arow_off + seg * 8));
            }
        }
        {
            const size_t bsrc = (size_t)(k0 + brow) * LDWB + bcol;
            uint32_t d = base + OFF_B + (uint32_t)(brow * BSTRIDE * 2 + bseg * 32);
            CPASYNC16(d,      (const void*)(Bh + bsrc));
            CPASYNC16(d + 16, (const void*)(Bh + bsrc + 8));
        }
    };

    float C[4][4][4];
    #pragma unroll
    for (int mi = 0; mi < 4; mi++)
        #pragma unroll
        for (int ni = 0; ni < 4; ni++)
            #pragma unroll
            for (int q = 0; q < 4; q++) C[mi][ni][q] = 0.f;

    const uint32_t a_ln = (uint32_t)(((wm * 64 + (lane & 15)) * ASTRIDE + (lane >> 4) * 8) * 2);
    const uint32_t b_ln = (uint32_t)(((lane & 15) * BSTRIDE + wn * 32 + (lane >> 4) * 8) * 2);

    STAGE(0, 0);
    CPCOMMIT();

    const int NCH = TOTF / 32;
    for (int ci = 0; ci < NCH; ++ci) {
        CPWAIT0();
        __syncthreads();
        if (ci + 1 < NCH) { STAGE((ci + 1) & 1, (ci + 1) * 32); CPCOMMIT(); }

        const uint32_t base = sb + (uint32_t)(ci & 1) * BUFB;
        #pragma unroll
        for (int ks = 0; ks < 2; ++ks) {
            uint32_t ah[4][4], bf[4][2];
            const uint32_t aad = base + a_ln + (uint32_t)(ks * 32);
            #pragma unroll
            for (int mi = 0; mi < 4; mi++)
                ldsm4(aad + mi * (16 * ASTRIDE * 2), ah[mi]);
            const uint32_t bad = base + OFF_B + b_ln + (uint32_t)(ks * 16 * BSTRIDE * 2);
            #pragma unroll
            for (int ng = 0; ng < 2; ng++) {
                uint32_t t[4];
                ldsm4t(bad + ng * 32, t);
                bf[2 * ng][0] = t[0]; bf[2 * ng][1] = t[1];
                bf[2 * ng + 1][0] = t[2]; bf[2 * ng + 1][1] = t[3];
            }
            #pragma unroll
            for (int mi = 0; mi < 4; mi++)
                #pragma unroll
                for (int ni = 0; ni < 4; ni++)
                    mma_fp(C[mi][ni], ah[mi], bf[ni]);
        }
        __syncthreads();
    }

    const int crow  = wm * 64 + (lane >> 2);
    const int ccol0 = wn * 32 + (lane & 3) * 2;
    #pragma unroll
    for (int mi = 0; mi < 4; mi++)
        #pragma unroll
        for (int ni = 0; ni < 4; ni++) {
            uint32_t o0 = sb + (uint32_t)(((crow + mi * 16) * 132 + ccol0 + ni * 8) * 4);
            STS64F(o0, C[mi][ni][0], C[mi][ni][1]);
            STS64F(o0 + (uint32_t)(8 * 132 * 4), C[mi][ni][2], C[mi][ni][3]);
        }
    __syncthreads();

    const float* Cs = (const float*)smg;
    if (HW) {
        const int j0h = bx * 64;
        #pragma unroll 4
        for (int t = 0; t < 32; ++t) {
            int idx = t * 256 + tid;
            int m = idx >> 6, u = idx & 63;
            float nl = fmaxf(Cs[m * 132 + u] + bias[j0h + u], 0.f);
            float gv = Cs[m * 132 + 64 + u] + bias[TOTF + j0h + u];
            float g  = 1.f / (1.f + __expf(-gv));
            size_t o = (size_t)(m0 + m) * TOTF + j0h + u;
            float tv = tin[o];
            float vo = g * tv + (1.f - g) * nl;
            outp[o] = vo;
            OutH[o] = __float2half_rn(vo);
        }
    } else {
        const int j0 = bx * 128;
        #pragma unroll 4
        for (int t = 0; t < 64; ++t) {
            int idx = t * 256 + tid;
            int m = idx >> 7, n = idx & 127;
            outp[(size_t)(m0 + m) * HID + j0 + n] = Cs[m * 132 + n] + bias[j0 + n];
        }
    }
}

// ---------------------------------------------------------------------------
template<int W, int NF, int NT>
static void launch_conv_mma(const int* ids, const float* cb,
                            float* tout, int colBase, int wOff)
{
    size_t smem = CX_W + (size_t)(16 * W) * 144;
    cudaFuncSetAttribute(conv_mma_kernel<W, NF, NT>,
                         cudaFuncAttributeMaxDynamicSharedMemorySize, (int)smem);
    conv_mma_kernel<W, NF, NT>
        <<<dim3(N_TOK / 8, NF / 64 / NT), 256, smem>>>(ids, cb, tout, colBase, wOff);
}

extern "C" void kernel_launch(void* const* d_in, const int* in_sizes, int n_in,
                              void* d_out, int out_size)
{
    const int*   ids = (const int*)  d_in[0];
    const float* emb = (const float*)d_in[1];
    const float* cw[7]; const float* cb[7];
    for (int i = 0; i < 7; i++) {
        cw[i] = (const float*)d_in[2 + 2 * i];
        cb[i] = (const float*)d_in[3 + 2 * i];
    }
    const float* hw_w0 = (const float*)d_in[16];
    const float* hw_b0 = (const float*)d_in[17];
    const float* hw_w1 = (const float*)d_in[18];
    const float* hw_b1 = (const float*)d_in[19];
    const float* pw    = (const float*)d_in[20];
    const float* pb    = (const float*)d_in[21];
    float* out = (float*)d_out;

    float *pT, *pT2;
    cudaGetSymbolAddress((void**)&pT,  g_T);
    cudaGetSymbolAddress((void**)&pT2, g_T2);
    __half *p0h, *p1h, *w0h, *w1h, *pwh;
    cudaGetSymbolAddress((void**)&p0h, g_p0h);
    cudaGetSymbolAddress((void**)&p1h, g_p1h);
    cudaGetSymbolAddress((void**)&w0h, g_w0h);
    cudaGetSymbolAddress((void**)&w1h, g_w1h);
    cudaGetSymbolAddress((void**)&pwh, g_pwh);

    prep_emb_kernel<<<(VOCABN * 16 + 255) / 256, 256>>>(emb);
    prep_cw_kernel<<<(WSP_TOT + 255) / 256, 256>>>(
        cw[0], cw[1], cw[2], cw[3], cw[4], cw[5], cw[6]);
    {
        size_t tot = 2ULL * HWW + PWW;
        int blocks = (int)((tot / 4 + 255) / 256);
        prep_big_kernel<<<blocks, 256>>>(hw_w0, hw_w1, pw);
    }

    cudaFuncSetAttribute(conv_w12_kernel,
                         cudaFuncAttributeMaxDynamicSharedMemorySize, M_SMEM);
    conv_w12_kernel<<<N_TOK / 8, 256, M_SMEM>>>(ids, cb[0], cb[1], pT);

    launch_conv_mma<3,   64, 1>(ids, cb[2], pT,   64,  1536);
    launch_conv_mma<4,  128, 2>(ids, cb[3], pT,  128,  4608);
    launch_conv_mma<5,  256, 2>(ids, cb[4], pT,  256, 12800);
    launch_conv_mma<6,  512, 2>(ids, cb[5], pT,  512, 33280);
    launch_conv_mma<7, 1024, 2>(ids, cb[6], pT, 1024, 82432);

    cudaFuncSetAttribute(gemm_kernel<true>,
                         cudaFuncAttributeMaxDynamicSharedMemorySize, GEMM_SMEM);
    cudaFuncSetAttribute(gemm_kernel<false>,
                         cudaFuncAttributeMaxDynamicSharedMemorySize, GEMM_SMEM);
    gemm_kernel<true><<<dim3(32, 32), 256, GEMM_SMEM>>>(
        p0h, w0h, pT, hw_b0, pT2, p1h);
    gemm_kernel<true><<<dim3(32, 32), 256, GEMM_SMEM>>>(
        p1h, w1h, pT2, hw_b1, pT, p0h);
    gemm_kernel<false><<<dim3(6, 32), 256, GEMM_SMEM>>>(
        p0h, pwh, nullptr, pb, out, nullptr);
}

// round 10
// speedup vs baseline: 5.4704x; 1.0507x over previous
#include <cuda_runtime.h>
#include <cuda_fp16.h>
#include <math.h>
#include <stdint.h>

#define N_TOK 4096
#define TOTF  2048
#define HID   768
#define VOCABN 264

__device__ float g_T [N_TOK * TOTF];
__device__ float g_T2[N_TOK * TOTF];

// single fp16 activation planes (P0: convs & hw2 out; P1: hw1 out)
__device__ __align__(16) __half g_p0h[N_TOK * TOTF];
__device__ __align__(16) __half g_p1h[N_TOK * TOTF];
// fp16 weight planes
#define HWW (TOTF * 2 * TOTF)
#define PWW (TOTF * HID)
__device__ __align__(16) __half g_w0h[HWW];
__device__ __align__(16) __half g_w1h[HWW];
__device__ __align__(16) __half g_pwh[PWW];
// fp16 conv tables (single-term now)
__device__ __align__(16) __half g_eh[VOCABN * 16];
// offsets: w1:0 w2:512 w3:1536 w4:4608 w5:12800 w6:33280 w7:82432
#define WSP_TOT 197120
__device__ __align__(16) __half g_wsp[WSP_TOT];

// ---------------------------------------------------------------------------
__device__ __forceinline__ uint32_t smem_u32(const void* p) {
    uint32_t a;
    asm("{ .reg .u64 t; cvta.to.shared.u64 t, %1; cvt.u32.u64 %0, t; }"
        : "=r"(a) : "l"(p));
    return a;
}
#define STS128(addr, a, b, c, d) \
    asm volatile("st.shared.v4.b32 [%0], {%1,%2,%3,%4};" \
                 :: "r"(addr), "r"(a), "r"(b), "r"(c), "r"(d) : "memory")
#define STS64F(addr, x, y) \
    asm volatile("st.shared.v2.f32 [%0], {%1,%2};" \
                 :: "r"(addr), "f"(x), "f"(y) : "memory")
#define CPASYNC16(dst, src) \
    asm volatile("cp.async.cg.shared.global [%0], [%1], 16;" \
                 :: "r"(dst), "l"(src) : "memory")
#define CPCOMMIT() asm volatile("cp.async.commit_group;" ::: "memory")
#define CPWAIT0()  asm volatile("cp.async.wait_group 0;" ::: "memory")

__device__ __forceinline__ void ldsm4(uint32_t a, uint32_t* r) {
    asm volatile("ldmatrix.sync.aligned.m8n8.x4.shared.b16 {%0,%1,%2,%3}, [%4];"
                 : "=r"(r[0]), "=r"(r[1]), "=r"(r[2]), "=r"(r[3]) : "r"(a));
}
__device__ __forceinline__ void ldsm4t(uint32_t a, uint32_t* r) {
    asm volatile("ldmatrix.sync.aligned.m8n8.x4.trans.shared.b16 {%0,%1,%2,%3}, [%4];"
                 : "=r"(r[0]), "=r"(r[1]), "=r"(r[2]), "=r"(r[3]) : "r"(a));
}
__device__ __forceinline__ void mma_fp(float* c, const uint32_t* a, const uint32_t* b) {
    asm volatile("mma.sync.aligned.m16n8k16.row.col.f32.f16.f16.f32 "
                 "{%0,%1,%2,%3}, {%4,%5,%6,%7}, {%8,%9}, {%0,%1,%2,%3};"
                 : "+f"(c[0]), "+f"(c[1]), "+f"(c[2]), "+f"(c[3])
                 : "r"(a[0]), "r"(a[1]), "r"(a[2]), "r"(a[3]), "r"(b[0]), "r"(b[1]));
}

// ===========================================================================
// Prep kernels
// ===========================================================================
__global__ void prep_emb_kernel(const float* __restrict__ emb) {
    int i = blockIdx.x * 256 + threadIdx.x;
    if (i < VOCABN * 16) g_eh[i] = __float2half_rn(emb[i]);
}
__global__ void prep_cw_kernel(const float* __restrict__ c0, const float* __restrict__ c1,
                               const float* __restrict__ c2, const float* __restrict__ c3,
                               const float* __restrict__ c4, const float* __restrict__ c5,
                               const float* __restrict__ c6) {
    int i = blockIdx.x * 256 + threadIdx.x;
    if (i >= WSP_TOT) return;
    const float* cw; int base, NF, W;
    if      (i <   512) { cw = c0; base = 0;     NF =   32; W = 1; }
    else if (i <  1536) { cw = c1; base = 512;   NF =   32; W = 2; }
    else if (i <  4608) { cw = c2; base = 1536;  NF =   64; W = 3; }
    else if (i < 12800) { cw = c3; base = 4608;  NF =  128; W = 4; }
    else if (i < 33280) { cw = c4; base = 12800; NF =  256; W = 5; }
    else if (i < 82432) { cw = c5; base = 33280; NF =  512; W = 6; }
    else                { cw = c6; base = 82432; NF = 1024; W = 7; }
    int local = i - base;
    int row = local / NF, f = local - row * NF;
    int c = row & 15, k = row >> 4;
    g_wsp[i] = __float2half_rn(cw[(f * 16 + c) * W + k]);
}
__global__ void prep_big_kernel(const float* __restrict__ w0,
                                const float* __restrict__ w1,
                                const float* __restrict__ pw) {
    size_t i4 = ((size_t)blockIdx.x * 256 + threadIdx.x) * 4;
    const float* src;
    __half* dh;
    size_t off;
    if (i4 < HWW)                { src = w0; dh = g_w0h; off = i4; }
    else if (i4 < 2 * HWW)       { src = w1; dh = g_w1h; off = i4 - HWW; }
    else if (i4 < 2 * HWW + PWW) { src = pw; dh = g_pwh; off = i4 - 2 * HWW; }
    else return;
    float4 v = *(const float4*)(src + off);
    *(half2*)(dh + off)     = __halves2half2(__float2half_rn(v.x), __float2half_rn(v.y));
    *(half2*)(dh + off + 2) = __halves2half2(__float2half_rn(v.z), __float2half_rn(v.w));
}

// ===========================================================================
// HMMA conv (w=3..7, single-term fp16): NT filter tiles/block, X staged once
// ===========================================================================
#define CX_W  21504u      // 8 tok * 56 rows * 48B

template<int W, int NF, int NT>
__global__ __launch_bounds__(256)
void conv_mma_kernel(const int* __restrict__ ids, const float* __restrict__ cb,
                     float* __restrict__ tout, int colBase, int wOff)
{
    constexpr int KD = 16 * W;
    constexpr int NPOS = 51 - W;
    extern __shared__ char smc[];
    const uint32_t sb = smem_u32(smc);
    const int tid = threadIdx.x;
    const int lane = tid & 31, wid = tid >> 5;
    const int n0 = blockIdx.x * 8;

    for (int t = tid; t < 448; t += 256) {
        int tok = t / 56, r = t - tok * 56;
        uint32_t dst = sb + (uint32_t)(tok * 2688 + r * 48);
        if (r < 50) {
            int id = ids[(n0 + tok) * 50 + r];
            const uint4* eh = (const uint4*)(g_eh + id * 16);
            uint4 h0 = eh[0], h1 = eh[1];
            STS128(dst,      h0.x, h0.y, h0.z, h0.w);
            STS128(dst + 16, h1.x, h1.y, h1.z, h1.w);
        } else {
            STS128(dst, 0u, 0u, 0u, 0u);
            STS128(dst + 16, 0u, 0u, 0u, 0u);
        }
    }

    const uint32_t xb = sb + (uint32_t)(wid * 2688 + (lane & 15) * 48 + (lane >> 4) * 16);
    const uint32_t bb = sb + CX_W + (uint32_t)((lane & 15) * 144 + (lane >> 4) * 16);

    for (int ft = 0; ft < NT; ++ft) {
        const int f0 = (blockIdx.y * NT + ft) * 64;
        __syncthreads();
        for (int t = tid; t < KD * 8; t += 256) {
            int row = t >> 3, seg = t & 7;
            int gsrc = wOff + row * NF + f0 + seg * 8;
            uint4 h = *(const uint4*)(g_wsp + gsrc);
            uint32_t d = sb + CX_W + (uint32_t)(row * 144 + seg * 16);
            STS128(d, h.x, h.y, h.z, h.w);
        }
        __syncthreads();

        float C[3][8][4];
        #pragma unroll
        for (int mi = 0; mi < 3; mi++)
            #pragma unroll
            for (int nf = 0; nf < 8; nf++)
                #pragma unroll
                for (int q = 0; q < 4; q++) C[mi][nf][q] = 0.f;

        #pragma unroll
        for (int k = 0; k < W; ++k) {
            uint32_t ah[3][4];
            #pragma unroll
            for (int mi = 0; mi < 3; mi++)
                ldsm4(xb + (uint32_t)((mi * 16 + k) * 48), ah[mi]);
            uint32_t bf[8][2];
            #pragma unroll
            for (int ng = 0; ng < 4; ng++) {
                uint32_t t4[4];
                ldsm4t(bb + (uint32_t)(k * 16 * 144 + ng * 32), t4);
                bf[2*ng][0] = t4[0]; bf[2*ng][1] = t4[1];
                bf[2*ng+1][0] = t4[2]; bf[2*ng+1][1] = t4[3];
            }
            #pragma unroll
            for (int mi = 0; mi < 3; mi++)
                #pragma unroll
                for (int nf = 0; nf < 8; nf++)
                    mma_fp(C[mi][nf], ah[mi], bf[nf]);
        }

        float m0[8], m1[8];
        #pragma unroll
        for (int nf = 0; nf < 8; nf++) { m0[nf] = -1e30f; m1[nf] = -1e30f; }
        const int r0 = lane >> 2;
        #pragma unroll
        for (int mi = 0; mi < 3; mi++) {
            bool v0 = (mi * 16 + r0) < NPOS;
            bool v1 = (mi * 16 + r0 + 8) < NPOS;
            #pragma unroll
            for (int nf = 0; nf < 8; nf++) {
                if (v0) { m0[nf] = fmaxf(m0[nf], C[mi][nf][0]);
                          m1[nf] = fmaxf(m1[nf], C[mi][nf][1]); }
                if (v1) { m0[nf] = fmaxf(m0[nf], C[mi][nf][2]);
                          m1[nf] = fmaxf(m1[nf], C[mi][nf][3]); }
            }
        }
        #pragma unroll
        for (int nf = 0; nf < 8; nf++) {
            #pragma unroll
            for (int off = 4; off < 32; off <<= 1) {
                m0[nf] = fmaxf(m0[nf], __shfl_xor_sync(0xffffffffu, m0[nf], off));
                m1[nf] = fmaxf(m1[nf], __shfl_xor_sync(0xffffffffu, m1[nf], off));
            }
        }
        if (lane < 4) {
            const int token = n0 + wid;
            const size_t base = (size_t)token * TOTF + colBase + f0;
            float* orow = tout + base;
            #pragma unroll
            for (int nf = 0; nf < 8; nf++) {
                int fl = nf * 8 + lane * 2;
                float2 o;
                o.x = fmaxf(m0[nf] + cb[f0 + fl], 0.f);
                o.y = fmaxf(m1[nf] + cb[f0 + fl + 1], 0.f);
                *(float2*)(orow + fl) = o;
                *(__half2*)(g_p0h + base + fl) =
                    __halves2half2(__float2half_rn(o.x), __float2half_rn(o.y));
            }
        }
    }
}

// ===========================================================================
// Merged w1+w2 HMMA conv (single-term fp16)
// ===========================================================================
#define M_XW  27648u      // 8 tok * 72 rows * 48B
#define M_SMEM (27648 + 32 * 144)

__global__ __launch_bounds__(256)
void conv_w12_kernel(const int* __restrict__ ids,
                     const float* __restrict__ cb1, const float* __restrict__ cb2,
                     float* __restrict__ tout)
{
    extern __shared__ char smc[];
    const uint32_t sb = smem_u32(smc);
    const int tid = threadIdx.x;
    const int lane = tid & 31, wid = tid >> 5;
    const int n0 = blockIdx.x * 8;

    for (int t = tid; t < 576; t += 256) {
        int tok = t / 72, r = t - tok * 72;
        uint32_t dst = sb + (uint32_t)(tok * 3456 + r * 48);
        if (r < 50) {
            int id = ids[(n0 + tok) * 50 + r];
            const uint4* eh = (const uint4*)(g_eh + id * 16);
            uint4 h0 = eh[0], h1 = eh[1];
            STS128(dst,      h0.x, h0.y, h0.z, h0.w);
            STS128(dst + 16, h1.x, h1.y, h1.z, h1.w);
        } else {
            STS128(dst, 0u, 0u, 0u, 0u);
            STS128(dst + 16, 0u, 0u, 0u, 0u);
        }
    }
    {
        int t = tid;
        int row = t >> 3, seg = t & 7;
        uint32_t d = sb + M_XW + (uint32_t)(row * 144 + seg * 16);
        if (seg < 4) {
            if (row < 16) {
                uint4 h = *(const uint4*)(g_wsp + 0 + row * 32 + seg * 8);
                STS128(d, h.x, h.y, h.z, h.w);
            } else {
                STS128(d, 0u, 0u, 0u, 0u);
            }
        } else {
            uint4 h = *(const uint4*)(g_wsp + 512 + row * 32 + (seg - 4) * 8);
            STS128(d, h.x, h.y, h.z, h.w);
        }
    }
    __syncthreads();

    const uint32_t xb = sb + (uint32_t)(wid * 3456 + (lane & 15) * 48 + (lane >> 4) * 16);
    const uint32_t bb = sb + M_XW + (uint32_t)((lane & 15) * 144 + (lane >> 4) * 16);

    float C[4][8][4];
    #pragma unroll
    for (int mi = 0; mi < 4; mi++)
        #pragma unroll
        for (int nf = 0; nf < 8; nf++)
            #pragma unroll
            for (int q = 0; q < 4; q++) C[mi][nf][q] = 0.f;

    #pragma unroll
    for (int k = 0; k < 2; ++k) {
        uint32_t ah[4][4];
        #pragma unroll
        for (int mi = 0; mi < 4; mi++)
            ldsm4(xb + (uint32_t)((mi * 16 + k) * 48), ah[mi]);
        uint32_t bf[8][2];
        #pragma unroll
        for (int ng = 0; ng < 4; ng++) {
            uint32_t t4[4];
            ldsm4t(bb + (uint32_t)(k * 16 * 144 + ng * 32), t4);
            bf[2*ng][0] = t4[0]; bf[2*ng][1] = t4[1];
            bf[2*ng+1][0] = t4[2]; bf[2*ng+1][1] = t4[3];
        }
        #pragma unroll
        for (int mi = 0; mi < 4; mi++)
            #pragma unroll
            for (int nf = 0; nf < 8; nf++)
                mma_fp(C[mi][nf], ah[mi], bf[nf]);
    }

    float m0[8], m1[8];
    #pragma unroll
    for (int nf = 0; nf < 8; nf++) { m0[nf] = -1e30f; m1[nf] = -1e30f; }
    const int r0 = lane >> 2;
    #pragma unroll
    for (int mi = 0; mi < 4; mi++) {
        #pragma unroll
        for (int nf = 0; nf < 8; nf++) {
            int lim = (nf < 4) ? 50 : 49;
            bool v0 = (mi * 16 + r0) < lim;
            bool v1 = (mi * 16 + r0 + 8) < lim;
            if (v0) { m0[nf] = fmaxf(m0[nf], C[mi][nf][0]);
                      m1[nf] = fmaxf(m1[nf], C[mi][nf][1]); }
            if (v1) { m0[nf] = fmaxf(m0[nf], C[mi][nf][2]);
                      m1[nf] = fmaxf(m1[nf], C[mi][nf][3]); }
        }
    }
    #pragma unroll
    for (int nf = 0; nf < 8; nf++) {
        #pragma unroll
        for (int off = 4; off < 32; off <<= 1) {
            m0[nf] = fmaxf(m0[nf], __shfl_xor_sync(0xffffffffu, m0[nf], off));
            m1[nf] = fmaxf(m1[nf], __shfl_xor_sync(0xffffffffu, m1[nf], off));
        }
    }
    if (lane < 4) {
        const int token = n0 + wid;
        const size_t base = (size_t)token * TOTF;
        float* orow = tout + base;
        #pragma unroll
        for (int nf = 0; nf < 8; nf++) {
            int fl = nf * 8 + lane * 2;
            float b0 = (fl < 32) ? cb1[fl] : cb2[fl - 32];
            float b1 = (fl < 32) ? cb1[fl + 1] : cb2[fl - 31];
            float2 o;
            o.x = fmaxf(m0[nf] + b0, 0.f);
            o.y = fmaxf(m1[nf] + b1, 0.f);
            *(float2*)(orow + fl) = o;
            *(__half2*)(g_p0h + base + fl) =
                __halves2half2(__float2half_rn(o.x), __float2half_rn(o.y));
        }
    }
}

// ===========================================================================
// Single-term fp16 GEMM, K-chunk 64, cp.async, 2 CTAs/SM.
// ===========================================================================
#define ASTRIDE 72        // 64 + 8 pad (fp16 elems per A row)
#define BSTRIDE 136
#define OFF_B   18432     // 128 * 72 * 2
#define BUFB    35840     // + 64 * 136 * 2
#define GEMM_SMEM (2 * BUFB)   // 71680 (>= C epilogue 67584)

template<bool HW>
__global__ __launch_bounds__(256, 2)
void gemm_kernel(const __half* __restrict__ Ah,
                 const __half* __restrict__ Bh,
                 const float* __restrict__ tin,
                 const float* __restrict__ bias,
                 float* __restrict__ outp,
                 __half* __restrict__ OutH)
{
    extern __shared__ char smg[];
    const uint32_t sb = smem_u32(smg);
    const int tid  = threadIdx.x;
    const int lane = tid & 31, wid = tid >> 5;
    const int wm = wid >> 2, wn = wid & 3;
    const int m0 = blockIdx.y * 128;
    const int bx = blockIdx.x;
    const int LDWB = HW ? (2 * TOTF) : HID;

    // B staging: 64 rows x 8 col-segs(16 cols); thread does 2 segs
    const int brow = tid >> 2;
    const int bs0  = (tid & 3) * 2;
    int bcolv[2];
    #pragma unroll
    for (int s = 0; s < 2; ++s) {
        int seg = bs0 + s;
        if (HW) bcolv[s] = (seg < 4) ? bx * 64 + seg * 16 : TOTF + bx * 64 + (seg - 4) * 16;
        else    bcolv[s] = bx * 128 + seg * 16;
    }
    // A staging: 128 rows x 8 segs(8 cols); thread: row=tid>>1, 4 segs
    const int ar0 = tid >> 1;
    const int as0 = (tid & 1) * 4;

    auto STAGE = [&](int b, int k0) {
        const uint32_t base = sb + (uint32_t)b * BUFB;
        {
            const size_t arow_off = (size_t)(m0 + ar0) * TOTF + k0;
            uint32_t d = base + (uint32_t)(ar0 * ASTRIDE * 2);
            #pragma unroll
            for (int s = 0; s < 4; ++s) {
                int seg = as0 + s;
                CPASYNC16(d + seg * 16, (const void*)(Ah + arow_off + seg * 8));
            }
        }
        {
            #pragma unroll
            for (int s = 0; s < 2; ++s) {
                int seg = bs0 + s;
                const size_t bsrc = (size_t)(k0 + brow) * LDWB + bcolv[s];
                uint32_t d = base + OFF_B + (uint32_t)(brow * BSTRIDE * 2 + seg * 32);
                CPASYNC16(d,      (const void*)(Bh + bsrc));
                CPASYNC16(d + 16, (const void*)(Bh + bsrc + 8));
            }
        }
    };

    float C[4][4][4];
    #pragma unroll
    for (int mi = 0; mi < 4; mi++)
        #pragma unroll
        for (int ni = 0; ni < 4; ni++)
            #pragma unroll
            for (int q = 0; q < 4; q++) C[mi][ni][q] = 0.f;

    const uint32_t a_ln = (uint32_t)(((wm * 64 + (lane & 15)) * ASTRIDE + (lane >> 4) * 8) * 2);
    const uint32_t b_ln = (uint32_t)(((lane & 15) * BSTRIDE + wn * 32 + (lane >> 4) * 8) * 2);

    STAGE(0, 0);
    CPCOMMIT();

    const int NCH = TOTF / 64;   // 32
    for (int ci = 0; ci < NCH; ++ci) {
        CPWAIT0();
        __syncthreads();
        if (ci + 1 < NCH) { STAGE((ci + 1) & 1, (ci + 1) * 64); CPCOMMIT(); }

        const uint32_t base = sb + (uint32_t)(ci & 1) * BUFB;
        #pragma unroll
        for (int ks = 0; ks < 4; ++ks) {
            uint32_t ah[4][4], bf[4][2];
            const uint32_t aad = base + a_ln + (uint32_t)(ks * 32);
            #pragma unroll
            for (int mi = 0; mi < 4; mi++)
                ldsm4(aad + mi * (16 * ASTRIDE * 2), ah[mi]);
            const uint32_t bad = base + OFF_B + b_ln + (uint32_t)(ks * 16 * BSTRIDE * 2);
            #pragma unroll
            for (int ng = 0; ng < 2; ng++) {
                uint32_t t[4];
                ldsm4t(bad + ng * 32, t);
                bf[2 * ng][0] = t[0]; bf[2 * ng][1] = t[1];
                bf[2 * ng + 1][0] = t[2]; bf[2 * ng + 1][1] = t[3];
            }
            #pragma unroll
            for (int mi = 0; mi < 4; mi++)
                #pragma unroll
                for (int ni = 0; ni < 4; ni++)
                    mma_fp(C[mi][ni], ah[mi], bf[ni]);
        }
        __syncthreads();
    }

    const int crow  = wm * 64 + (lane >> 2);
    const int ccol0 = wn * 32 + (lane & 3) * 2;
    #pragma unroll
    for (int mi = 0; mi < 4; mi++)
        #pragma unroll
        for (int ni = 0; ni < 4; ni++) {
            uint32_t o0 = sb + (uint32_t)(((crow + mi * 16) * 132 + ccol0 + ni * 8) * 4);
            STS64F(o0, C[mi][ni][0], C[mi][ni][1]);
            STS64F(o0 + (uint32_t)(8 * 132 * 4), C[mi][ni][2], C[mi][ni][3]);
        }
    __syncthreads();

    const float* Cs = (const float*)smg;
    if (HW) {
        const int j0h = bx * 64;
        #pragma unroll 4
        for (int t = 0; t < 32; ++t) {
            int idx = t * 256 + tid;
            int m = idx >> 6, u = idx & 63;
            float nl = fmaxf(Cs[m * 132 + u] + bias[j0h + u], 0.f);
            float gv = Cs[m * 132 + 64 + u] + bias[TOTF + j0h + u];
            float g  = 1.f / (1.f + __expf(-gv));
            size_t o = (size_t)(m0 + m) * TOTF + j0h + u;
            float tv = tin[o];
            float vo = g * tv + (1.f - g) * nl;
            outp[o] = vo;
            OutH[o] = __float2half_rn(vo);
        }
    } else {
        const int j0 = bx * 128;
        #pragma unroll 4
        for (int t = 0; t < 64; ++t) {
            int idx = t * 256 + tid;
            int m = idx >> 7, n = idx & 127;
            outp[(size_t)(m0 + m) * HID + j0 + n] = Cs[m * 132 + n] + bias[j0 + n];
        }
    }
}

// ---------------------------------------------------------------------------
template<int W, int NF, int NT>
static void launch_conv_mma(const int* ids, const float* cb,
                            float* tout, int colBase, int wOff)
{
    size_t smem = CX_W + (size_t)(16 * W) * 144;
    cudaFuncSetAttribute(conv_mma_kernel<W, NF, NT>,
                         cudaFuncAttributeMaxDynamicSharedMemorySize, (int)smem);
    conv_mma_kernel<W, NF, NT>
        <<<dim3(N_TOK / 8, NF / 64 / NT), 256, smem>>>(ids, cb, tout, colBase, wOff);
}

extern "C" void kernel_launch(void* const* d_in, const int* in_sizes, int n_in,
                              void* d_out, int out_size)
{
    const int*   ids = (const int*)  d_in[0];
    const float* emb = (const float*)d_in[1];
    const float* cw[7]; const float* cb[7];
    for (int i = 0; i < 7; i++) {
        cw[i] = (const float*)d_in[2 + 2 * i];
        cb[i] = (const float*)d_in[3 + 2 * i];
    }
    const float* hw_w0 = (const float*)d_in[16];
    const float* hw_b0 = (const float*)d_in[17];
    const float* hw_w1 = (const float*)d_in[18];
    const float* hw_b1 = (const float*)d_in[19];
    const float* pw    = (const float*)d_in[20];
    const float* pb    = (const float*)d_in[21];
    float* out = (float*)d_out;

    float *pT, *pT2;
    cudaGetSymbolAddress((void**)&pT,  g_T);
    cudaGetSymbolAddress((void**)&pT2, g_T2);
    __half *p0h, *p1h, *w0h, *w1h, *pwh;
    cudaGetSymbolAddress((void**)&p0h, g_p0h);
    cudaGetSymbolAddress((void**)&p1h, g_p1h);
    cudaGetSymbolAddress((void**)&w0h, g_w0h);
    cudaGetSymbolAddress((void**)&w1h, g_w1h);
    cudaGetSymbolAddress((void**)&pwh, g_pwh);

    prep_emb_kernel<<<(VOCABN * 16 + 255) / 256, 256>>>(emb);
    prep_cw_kernel<<<(WSP_TOT + 255) / 256, 256>>>(
        cw[0], cw[1], cw[2], cw[3], cw[4], cw[5], cw[6]);
    {
        size_t tot = 2ULL * HWW + PWW;
        int blocks = (int)((tot / 4 + 255) / 256);
        prep_big_kernel<<<blocks, 256>>>(hw_w0, hw_w1, pw);
    }

    cudaFuncSetAttribute(conv_w12_kernel,
                         cudaFuncAttributeMaxDynamicSharedMemorySize, M_SMEM);
    conv_w12_kernel<<<N_TOK / 8, 256, M_SMEM>>>(ids, cb[0], cb[1], pT);

    launch_conv_mma<3,   64, 1>(ids, cb[2], pT,   64,  1536);
    launch_conv_mma<4,  128, 2>(ids, cb[3], pT,  128,  4608);
    launch_conv_mma<5,  256, 2>(ids, cb[4], pT,  256, 12800);
    launch_conv_mma<6,  512, 2>(ids, cb[5], pT,  512, 33280);
    launch_conv_mma<7, 1024, 2>(ids, cb[6], pT, 1024, 82432);

    cudaFuncSetAttribute(gemm_kernel<true>,
                         cudaFuncAttributeMaxDynamicSharedMemorySize, GEMM_SMEM);
    cudaFuncSetAttribute(gemm_kernel<false>,
                         cudaFuncAttributeMaxDynamicSharedMemorySize, GEMM_SMEM);
    gemm_kernel<true><<<dim3(32, 32), 256, GEMM_SMEM>>>(
        p0h, w0h, pT, hw_b0, pT2, p1h);
    gemm_kernel<true><<<dim3(32, 32), 256, GEMM_SMEM>>>(
        p1h, w1h, pT2, hw_b1, pT, p0h);
    gemm_kernel<false><<<dim3(6, 32), 256, GEMM_SMEM>>>(
        p0h, pwh, nullptr, pb, out, nullptr);
}

// round 11
// speedup vs baseline: 5.7714x; 1.0550x over previous
#include <cuda_runtime.h>
#include <cuda_fp16.h>
#include <math.h>
#include <stdint.h>

#define N_TOK 4096
#define TOTF  2048
#define HID   768
#define VOCABN 264

// single fp16 activation planes (P0: convs & hw2 out; P1: hw1 out)
__device__ __align__(16) __half g_p0h[N_TOK * TOTF];
__device__ __align__(16) __half g_p1h[N_TOK * TOTF];
// fp16 weight planes
#define HWW (TOTF * 2 * TOTF)
#define PWW (TOTF * HID)
__device__ __align__(16) __half g_w0h[HWW];
__device__ __align__(16) __half g_w1h[HWW];
__device__ __align__(16) __half g_pwh[PWW];
// fp16 conv tables
__device__ __align__(16) __half g_eh[VOCABN * 16];
// offsets: w1:0 w2:512 w3:1536 w4:4608 w5:12800 w6:33280 w7:82432
#define WSP_TOT 197120
__device__ __align__(16) __half g_wsp[WSP_TOT];

// ---------------------------------------------------------------------------
__device__ __forceinline__ uint32_t smem_u32(const void* p) {
    uint32_t a;
    asm("{ .reg .u64 t; cvta.to.shared.u64 t, %1; cvt.u32.u64 %0, t; }"
        : "=r"(a) : "l"(p));
    return a;
}
#define STS128(addr, a, b, c, d) \
    asm volatile("st.shared.v4.b32 [%0], {%1,%2,%3,%4};" \
                 :: "r"(addr), "r"(a), "r"(b), "r"(c), "r"(d) : "memory")
#define STS64F(addr, x, y) \
    asm volatile("st.shared.v2.f32 [%0], {%1,%2};" \
                 :: "r"(addr), "f"(x), "f"(y) : "memory")
#define CPASYNC16(dst, src) \
    asm volatile("cp.async.cg.shared.global [%0], [%1], 16;" \
                 :: "r"(dst), "l"(src) : "memory")
#define CPCOMMIT() asm volatile("cp.async.commit_group;" ::: "memory")
#define CPWAIT0()  asm volatile("cp.async.wait_group 0;" ::: "memory")
#define CPWAIT1()  asm volatile("cp.async.wait_group 1;" ::: "memory")

__device__ __forceinline__ void ldsm4(uint32_t a, uint32_t* r) {
    asm volatile("ldmatrix.sync.aligned.m8n8.x4.shared.b16 {%0,%1,%2,%3}, [%4];"
                 : "=r"(r[0]), "=r"(r[1]), "=r"(r[2]), "=r"(r[3]) : "r"(a));
}
__device__ __forceinline__ void ldsm4t(uint32_t a, uint32_t* r) {
    asm volatile("ldmatrix.sync.aligned.m8n8.x4.trans.shared.b16 {%0,%1,%2,%3}, [%4];"
                 : "=r"(r[0]), "=r"(r[1]), "=r"(r[2]), "=r"(r[3]) : "r"(a));
}
__device__ __forceinline__ void mma_fp(float* c, const uint32_t* a, const uint32_t* b) {
    asm volatile("mma.sync.aligned.m16n8k16.row.col.f32.f16.f16.f32 "
                 "{%0,%1,%2,%3}, {%4,%5,%6,%7}, {%8,%9}, {%0,%1,%2,%3};"
                 : "+f"(c[0]), "+f"(c[1]), "+f"(c[2]), "+f"(c[3])
                 : "r"(a[0]), "r"(a[1]), "r"(a[2]), "r"(a[3]), "r"(b[0]), "r"(b[1]));
}

// ===========================================================================
// Merged prep: big weight planes + conv weights + embeddings in ONE launch
// ===========================================================================
#define BIGN 4587520   // (2*HWW + PWW) / 4
__global__ void prep_all_kernel(const float* __restrict__ w0,
                                const float* __restrict__ w1,
                                const float* __restrict__ pw,
                                const float* __restrict__ c0, const float* __restrict__ c1,
                                const float* __restrict__ c2, const float* __restrict__ c3,
                                const float* __restrict__ c4, const float* __restrict__ c5,
                                const float* __restrict__ c6,
                                const float* __restrict__ emb) {
    size_t t = (size_t)blockIdx.x * 256 + threadIdx.x;
    if (t < BIGN) {
        size_t i4 = t * 4;
        const float* src;
        __half* dh;
        size_t off;
        if (i4 < HWW)          { src = w0; dh = g_w0h; off = i4; }
        else if (i4 < 2 * HWW) { src = w1; dh = g_w1h; off = i4 - HWW; }
        else                   { src = pw; dh = g_pwh; off = i4 - 2 * HWW; }
        float4 v = *(const float4*)(src + off);
        *(half2*)(dh + off)     = __halves2half2(__float2half_rn(v.x), __float2half_rn(v.y));
        *(half2*)(dh + off + 2) = __halves2half2(__float2half_rn(v.z), __float2half_rn(v.w));
        return;
    }
    size_t u = t - BIGN;
    if (u < WSP_TOT) {
        int i = (int)u;
        const float* cw; int base, NF, W;
        if      (i <   512) { cw = c0; base = 0;     NF =   32; W = 1; }
        else if (i <  1536) { cw = c1; base = 512;   NF =   32; W = 2; }
        else if (i <  4608) { cw = c2; base = 1536;  NF =   64; W = 3; }
        else if (i < 12800) { cw = c3; base = 4608;  NF =  128; W = 4; }
        else if (i < 33280) { cw = c4; base = 12800; NF =  256; W = 5; }
        else if (i < 82432) { cw = c5; base = 33280; NF =  512; W = 6; }
        else                { cw = c6; base = 82432; NF = 1024; W = 7; }
        int local = i - base;
        int row = local / NF, f = local - row * NF;
        int c = row & 15, k = row >> 4;
        g_wsp[i] = __float2half_rn(cw[(f * 16 + c) * W + k]);
        return;
    }
    u -= WSP_TOT;
    if (u < VOCABN * 16) g_eh[u] = __float2half_rn(emb[u]);
}

// ===========================================================================
// HMMA conv (w=3..7, single-term fp16): NT filter tiles/block, X staged once
// Writes fp16 plane only.
// ===========================================================================
#define CX_W  21504u      // 8 tok * 56 rows * 48B

template<int W, int NF, int NT>
__global__ __launch_bounds__(256)
void conv_mma_kernel(const int* __restrict__ ids, const float* __restrict__ cb,
                     int colBase, int wOff)
{
    constexpr int KD = 16 * W;
    constexpr int NPOS = 51 - W;
    extern __shared__ char smc[];
    const uint32_t sb = smem_u32(smc);
    const int tid = threadIdx.x;
    const int lane = tid & 31, wid = tid >> 5;
    const int n0 = blockIdx.x * 8;

    for (int t = tid; t < 448; t += 256) {
        int tok = t / 56, r = t - tok * 56;
        uint32_t dst = sb + (uint32_t)(tok * 2688 + r * 48);
        if (r < 50) {
            int id = ids[(n0 + tok) * 50 + r];
            const uint4* eh = (const uint4*)(g_eh + id * 16);
            uint4 h0 = eh[0], h1 = eh[1];
            STS128(dst,      h0.x, h0.y, h0.z, h0.w);
            STS128(dst + 16, h1.x, h1.y, h1.z, h1.w);
        } else {
            STS128(dst, 0u, 0u, 0u, 0u);
            STS128(dst + 16, 0u, 0u, 0u, 0u);
        }
    }

    const uint32_t xb = sb + (uint32_t)(wid * 2688 + (lane & 15) * 48 + (lane >> 4) * 16);
    const uint32_t bb = sb + CX_W + (uint32_t)((lane & 15) * 144 + (lane >> 4) * 16);

    for (int ft = 0; ft < NT; ++ft) {
        const int f0 = (blockIdx.y * NT + ft) * 64;
        __syncthreads();
        for (int t = tid; t < KD * 8; t += 256) {
            int row = t >> 3, seg = t & 7;
            int gsrc = wOff + row * NF + f0 + seg * 8;
            uint4 h = *(const uint4*)(g_wsp + gsrc);
            uint32_t d = sb + CX_W + (uint32_t)(row * 144 + seg * 16);
            STS128(d, h.x, h.y, h.z, h.w);
        }
        __syncthreads();

        float C[3][8][4];
        #pragma unroll
        for (int mi = 0; mi < 3; mi++)
            #pragma unroll
            for (int nf = 0; nf < 8; nf++)
                #pragma unroll
                for (int q = 0; q < 4; q++) C[mi][nf][q] = 0.f;

        #pragma unroll
        for (int k = 0; k < W; ++k) {
            uint32_t ah[3][4];
            #pragma unroll
            for (int mi = 0; mi < 3; mi++)
                ldsm4(xb + (uint32_t)((mi * 16 + k) * 48), ah[mi]);
            uint32_t bf[8][2];
            #pragma unroll
            for (int ng = 0; ng < 4; ng++) {
                uint32_t t4[4];
                ldsm4t(bb + (uint32_t)(k * 16 * 144 + ng * 32), t4);
                bf[2*ng][0] = t4[0]; bf[2*ng][1] = t4[1];
                bf[2*ng+1][0] = t4[2]; bf[2*ng+1][1] = t4[3];
            }
            #pragma unroll
            for (int mi = 0; mi < 3; mi++)
                #pragma unroll
                for (int nf = 0; nf < 8; nf++)
                    mma_fp(C[mi][nf], ah[mi], bf[nf]);
        }

        float m0[8], m1[8];
        #pragma unroll
        for (int nf = 0; nf < 8; nf++) { m0[nf] = -1e30f; m1[nf] = -1e30f; }
        const int r0 = lane >> 2;
        #pragma unroll
        for (int mi = 0; mi < 3; mi++) {
            bool v0 = (mi * 16 + r0) < NPOS;
            bool v1 = (mi * 16 + r0 + 8) < NPOS;
            #pragma unroll
            for (int nf = 0; nf < 8; nf++) {
                if (v0) { m0[nf] = fmaxf(m0[nf], C[mi][nf][0]);
                          m1[nf] = fmaxf(m1[nf], C[mi][nf][1]); }
                if (v1) { m0[nf] = fmaxf(m0[nf], C[mi][nf][2]);
                          m1[nf] = fmaxf(m1[nf], C[mi][nf][3]); }
            }
        }
        #pragma unroll
        for (int nf = 0; nf < 8; nf++) {
            #pragma unroll
            for (int off = 4; off < 32; off <<= 1) {
                m0[nf] = fmaxf(m0[nf], __shfl_xor_sync(0xffffffffu, m0[nf], off));
                m1[nf] = fmaxf(m1[nf], __shfl_xor_sync(0xffffffffu, m1[nf], off));
            }
        }
        if (lane < 4) {
            const int token = n0 + wid;
            const size_t base = (size_t)token * TOTF + colBase + f0;
            #pragma unroll
            for (int nf = 0; nf < 8; nf++) {
                int fl = nf * 8 + lane * 2;
                float ox = fmaxf(m0[nf] + cb[f0 + fl], 0.f);
                float oy = fmaxf(m1[nf] + cb[f0 + fl + 1], 0.f);
                *(__half2*)(g_p0h + base + fl) =
                    __halves2half2(__float2half_rn(ox), __float2half_rn(oy));
            }
        }
    }
}

// ===========================================================================
// Merged w1+w2 HMMA conv (single-term fp16) — writes fp16 plane only
// ===========================================================================
#define M_XW  27648u      // 8 tok * 72 rows * 48B
#define M_SMEM (27648 + 32 * 144)

__global__ __launch_bounds__(256)
void conv_w12_kernel(const int* __restrict__ ids,
                     const float* __restrict__ cb1, const float* __restrict__ cb2)
{
    extern __shared__ char smc[];
    const uint32_t sb = smem_u32(smc);
    const int tid = threadIdx.x;
    const int lane = tid & 31, wid = tid >> 5;
    const int n0 = blockIdx.x * 8;

    for (int t = tid; t < 576; t += 256) {
        int tok = t / 72, r = t - tok * 72;
        uint32_t dst = sb + (uint32_t)(tok * 3456 + r * 48);
        if (r < 50) {
            int id = ids[(n0 + tok) * 50 + r];
            const uint4* eh = (const uint4*)(g_eh + id * 16);
            uint4 h0 = eh[0], h1 = eh[1];
            STS128(dst,      h0.x, h0.y, h0.z, h0.w);
            STS128(dst + 16, h1.x, h1.y, h1.z, h1.w);
        } else {
            STS128(dst, 0u, 0u, 0u, 0u);
            STS128(dst + 16, 0u, 0u, 0u, 0u);
        }
    }
    {
        int t = tid;
        int row = t >> 3, seg = t & 7;
        uint32_t d = sb + M_XW + (uint32_t)(row * 144 + seg * 16);
        if (seg < 4) {
            if (row < 16) {
                uint4 h = *(const uint4*)(g_wsp + 0 + row * 32 + seg * 8);
                STS128(d, h.x, h.y, h.z, h.w);
            } else {
                STS128(d, 0u, 0u, 0u, 0u);
            }
        } else {
            uint4 h = *(const uint4*)(g_wsp + 512 + row * 32 + (seg - 4) * 8);
            STS128(d, h.x, h.y, h.z, h.w);
        }
    }
    __syncthreads();

    const uint32_t xb = sb + (uint32_t)(wid * 3456 + (lane & 15) * 48 + (lane >> 4) * 16);
    const uint32_t bb = sb + M_XW + (uint32_t)((lane & 15) * 144 + (lane >> 4) * 16);

    float C[4][8][4];
    #pragma unroll
    for (int mi = 0; mi < 4; mi++)
        #pragma unroll
        for (int nf = 0; nf < 8; nf++)
            #pragma unroll
            for (int q = 0; q < 4; q++) C[mi][nf][q] = 0.f;

    #pragma unroll
    for (int k = 0; k < 2; ++k) {
        uint32_t ah[4][4];
        #pragma unroll
        for (int mi = 0; mi < 4; mi++)
            ldsm4(xb + (uint32_t)((mi * 16 + k) * 48), ah[mi]);
        uint32_t bf[8][2];
        #pragma unroll
        for (int ng = 0; ng < 4; ng++) {
            uint32_t t4[4];
            ldsm4t(bb + (uint32_t)(k * 16 * 144 + ng * 32), t4);
            bf[2*ng][0] = t4[0]; bf[2*ng][1] = t4[1];
            bf[2*ng+1][0] = t4[2]; bf[2*ng+1][1] = t4[3];
        }
        #pragma unroll
        for (int mi = 0; mi < 4; mi++)
            #pragma unroll
            for (int nf = 0; nf < 8; nf++)
                mma_fp(C[mi][nf], ah[mi], bf[nf]);
    }

    float m0[8], m1[8];
    #pragma unroll
    for (int nf = 0; nf < 8; nf++) { m0[nf] = -1e30f; m1[nf] = -1e30f; }
    const int r0 = lane >> 2;
    #pragma unroll
    for (int mi = 0; mi < 4; mi++) {
        #pragma unroll
        for (int nf = 0; nf < 8; nf++) {
            int lim = (nf < 4) ? 50 : 49;
            bool v0 = (mi * 16 + r0) < lim;
            bool v1 = (mi * 16 + r0 + 8) < lim;
            if (v0) { m0[nf] = fmaxf(m0[nf], C[mi][nf][0]);
                      m1[nf] = fmaxf(m1[nf], C[mi][nf][1]); }
            if (v1) { m0[nf] = fmaxf(m0[nf], C[mi][nf][2]);
                      m1[nf] = fmaxf(m1[nf], C[mi][nf][3]); }
        }
    }
    #pragma unroll
    for (int nf = 0; nf < 8; nf++) {
        #pragma unroll
        for (int off = 4; off < 32; off <<= 1) {
            m0[nf] = fmaxf(m0[nf], __shfl_xor_sync(0xffffffffu, m0[nf], off));
            m1[nf] = fmaxf(m1[nf], __shfl_xor_sync(0xffffffffu, m1[nf], off));
        }
    }
    if (lane < 4) {
        const int token = n0 + wid;
        const size_t base = (size_t)token * TOTF;
        #pragma unroll
        for (int nf = 0; nf < 8; nf++) {
            int fl = nf * 8 + lane * 2;
            float b0 = (fl < 32) ? cb1[fl] : cb2[fl - 32];
            float b1 = (fl < 32) ? cb1[fl + 1] : cb2[fl - 31];
            float ox = fmaxf(m0[nf] + b0, 0.f);
            float oy = fmaxf(m1[nf] + b1, 0.f);
            *(__half2*)(g_p0h + base + fl) =
                __halves2half2(__float2half_rn(ox), __float2half_rn(oy));
        }
    }
}

// ===========================================================================
// Single-term fp16 GEMM, K-chunk 64, 3-stage cp.async, 2 CTAs/SM.
//   HW : carry read from A plane (fp16); writes fp16 OutH plane only.
//   !HW: proj, writes fp32 d_out + bias.
// ===========================================================================
#define ASTRIDE 72
#define BSTRIDE 136
#define OFF_B   18432     // 128 * 72 * 2
#define BUFB    35840
#define GEMM_SMEM (3 * BUFB)   // 107520 (>= C epilogue 67584)

template<bool HW>
__global__ __launch_bounds__(256, 2)
void gemm_kernel(const __half* __restrict__ Ah,
                 const __half* __restrict__ Bh,
                 const float* __restrict__ bias,
                 float* __restrict__ outp,
                 __half* __restrict__ OutH)
{
    extern __shared__ char smg[];
    const uint32_t sb = smem_u32(smg);
    const int tid  = threadIdx.x;
    const int lane = tid & 31, wid = tid >> 5;
    const int wm = wid >> 2, wn = wid & 3;
    const int m0 = blockIdx.y * 128;
    const int bx = blockIdx.x;
    const int LDWB = HW ? (2 * TOTF) : HID;

    const int brow = tid >> 2;
    const int bs0  = (tid & 3) * 2;
    int bcolv[2];
    #pragma unroll
    for (int s = 0; s < 2; ++s) {
        int seg = bs0 + s;
        if (HW) bcolv[s] = (seg < 4) ? bx * 64 + seg * 16 : TOTF + bx * 64 + (seg - 4) * 16;
        else    bcolv[s] = bx * 128 + seg * 16;
    }
    const int ar0 = tid >> 1;
    const int as0 = (tid & 1) * 4;

    auto STAGE = [&](int b, int k0) {
        const uint32_t base = sb + (uint32_t)b * BUFB;
        {
            const size_t arow_off = (size_t)(m0 + ar0) * TOTF + k0;
            uint32_t d = base + (uint32_t)(ar0 * ASTRIDE * 2);
            #pragma unroll
            for (int s = 0; s < 4; ++s) {
                int seg = as0 + s;
                CPASYNC16(d + seg * 16, (const void*)(Ah + arow_off + seg * 8));
            }
        }
        {
            #pragma unroll
            for (int s = 0; s < 2; ++s) {
                int seg = bs0 + s;
                const size_t bsrc = (size_t)(k0 + brow) * LDWB + bcolv[s];
                uint32_t d = base + OFF_B + (uint32_t)(brow * BSTRIDE * 2 + seg * 32);
                CPASYNC16(d,      (const void*)(Bh + bsrc));
                CPASYNC16(d + 16, (const void*)(Bh + bsrc + 8));
            }
        }
    };

    float C[4][4][4];
    #pragma unroll
    for (int mi = 0; mi < 4; mi++)
        #pragma unroll
        for (int ni = 0; ni < 4; ni++)
            #pragma unroll
            for (int q = 0; q < 4; q++) C[mi][ni][q] = 0.f;

    const uint32_t a_ln = (uint32_t)(((wm * 64 + (lane & 15)) * ASTRIDE + (lane >> 4) * 8) * 2);
    const uint32_t b_ln = (uint32_t)(((lane & 15) * BSTRIDE + wn * 32 + (lane >> 4) * 8) * 2);

    STAGE(0, 0);
    CPCOMMIT();
    STAGE(1, 64);
    CPCOMMIT();

    const int NCH = TOTF / 64;   // 32
    int bufi = 0;
    for (int ci = 0; ci < NCH; ++ci) {
        if (ci + 1 < NCH) CPWAIT1(); else CPWAIT0();
        __syncthreads();
        if (ci + 2 < NCH) {
            int nb = bufi + 2; if (nb >= 3) nb -= 3;
            STAGE(nb, (ci + 2) * 64);
            CPCOMMIT();
        }

        const uint32_t base = sb + (uint32_t)bufi * BUFB;
        #pragma unroll
        for (int ks = 0; ks < 4; ++ks) {
            uint32_t ah[4][4], bf[4][2];
            const uint32_t aad = base + a_ln + (uint32_t)(ks * 32);
            #pragma unroll
            for (int mi = 0; mi < 4; mi++)
                ldsm4(aad + mi * (16 * ASTRIDE * 2), ah[mi]);
            const uint32_t bad = base + OFF_B + b_ln + (uint32_t)(ks * 16 * BSTRIDE * 2);
            #pragma unroll
            for (int ng = 0; ng < 2; ng++) {
                uint32_t t[4];
                ldsm4t(bad + ng * 32, t);
                bf[2 * ng][0] = t[0]; bf[2 * ng][1] = t[1];
                bf[2 * ng + 1][0] = t[2]; bf[2 * ng + 1][1] = t[3];
            }
            #pragma unroll
            for (int mi = 0; mi < 4; mi++)
                #pragma unroll
                for (int ni = 0; ni < 4; ni++)
                    mma_fp(C[mi][ni], ah[mi], bf[ni]);
        }
        __syncthreads();
        if (++bufi == 3) bufi = 0;
    }

    const int crow  = wm * 64 + (lane >> 2);
    const int ccol0 = wn * 32 + (lane & 3) * 2;
    #pragma unroll
    for (int mi = 0; mi < 4; mi++)
        #pragma unroll
        for (int ni = 0; ni < 4; ni++) {
            uint32_t o0 = sb + (uint32_t)(((crow + mi * 16) * 132 + ccol0 + ni * 8) * 4);
            STS64F(o0, C[mi][ni][0], C[mi][ni][1]);
            STS64F(o0 + (uint32_t)(8 * 132 * 4), C[mi][ni][2], C[mi][ni][3]);
        }
    __syncthreads();

    const float* Cs = (const float*)smg;
    if (HW) {
        const int j0h = bx * 64;
        #pragma unroll 4
        for (int t = 0; t < 32; ++t) {
            int idx = t * 256 + tid;
            int m = idx >> 6, u = idx & 63;
            float nl = fmaxf(Cs[m * 132 + u] + bias[j0h + u], 0.f);
            float gv = Cs[m * 132 + 64 + u] + bias[TOTF + j0h + u];
            float g  = 1.f / (1.f + __expf(-gv));
            size_t o = (size_t)(m0 + m) * TOTF + j0h + u;
            float tv = __half2float(Ah[o]);      // carry from fp16 plane
            float vo = g * tv + (1.f - g) * nl;
            OutH[o] = __float2half_rn(vo);
        }
    } else {
        const int j0 = bx * 128;
        #pragma unroll 4
        for (int t = 0; t < 64; ++t) {
            int idx = t * 256 + tid;
            int m = idx >> 7, n = idx & 127;
            outp[(size_t)(m0 + m) * HID + j0 + n] = Cs[m * 132 + n] + bias[j0 + n];
        }
    }
}

// ---------------------------------------------------------------------------
template<int W, int NF, int NT>
static void launch_conv_mma(const int* ids, const float* cb, int colBase, int wOff)
{
    size_t smem = CX_W + (size_t)(16 * W) * 144;
    cudaFuncSetAttribute(conv_mma_kernel<W, NF, NT>,
                         cudaFuncAttributeMaxDynamicSharedMemorySize, (int)smem);
    conv_mma_kernel<W, NF, NT>
        <<<dim3(N_TOK / 8, NF / 64 / NT), 256, smem>>>(ids, cb, colBase, wOff);
}

extern "C" void kernel_launch(void* const* d_in, const int* in_sizes, int n_in,
                              void* d_out, int out_size)
{
    const int*   ids = (const int*)  d_in[0];
    const float* emb = (const float*)d_in[1];
    const float* cw[7]; const float* cb[7];
    for (int i = 0; i < 7; i++) {
        cw[i] = (const float*)d_in[2 + 2 * i];
        cb[i] = (const float*)d_in[3 + 2 * i];
    }
    const float* hw_w0 = (const float*)d_in[16];
    const float* hw_b0 = (const float*)d_in[17];
    const float* hw_w1 = (const float*)d_in[18];
    const float* hw_b1 = (const float*)d_in[19];
    const float* pw    = (const float*)d_in[20];
    const float* pb    = (const float*)d_in[21];
    float* out = (float*)d_out;

    __half *p0h, *p1h, *w0h, *w1h, *pwh;
    cudaGetSymbolAddress((void**)&p0h, g_p0h);
    cudaGetSymbolAddress((void**)&p1h, g_p1h);
    cudaGetSymbolAddress((void**)&w0h, g_w0h);
    cudaGetSymbolAddress((void**)&w1h, g_w1h);
    cudaGetSymbolAddress((void**)&pwh, g_pwh);

    // single merged prep
    {
        size_t tot = (size_t)BIGN + WSP_TOT + VOCABN * 16;
        int blocks = (int)((tot + 255) / 256);
        prep_all_kernel<<<blocks, 256>>>(hw_w0, hw_w1, pw,
                                         cw[0], cw[1], cw[2], cw[3], cw[4], cw[5], cw[6],
                                         emb);
    }

    cudaFuncSetAttribute(conv_w12_kernel,
                         cudaFuncAttributeMaxDynamicSharedMemorySize, M_SMEM);
    conv_w12_kernel<<<N_TOK / 8, 256, M_SMEM>>>(ids, cb[0], cb[1]);

    launch_conv_mma<3,   64, 1>(ids, cb[2],   64,  1536);
    launch_conv_mma<4,  128, 2>(ids, cb[3],  128,  4608);
    launch_conv_mma<5,  256, 2>(ids, cb[4],  256, 12800);
    launch_conv_mma<6,  512, 2>(ids, cb[5],  512, 33280);
    launch_conv_mma<7, 1024, 2>(ids, cb[6], 1024, 82432);

    cudaFuncSetAttribute(gemm_kernel<true>,
                         cudaFuncAttributeMaxDynamicSharedMemorySize, GEMM_SMEM);
    cudaFuncSetAttribute(gemm_kernel<false>,
                         cudaFuncAttributeMaxDynamicSharedMemorySize, GEMM_SMEM);
    gemm_kernel<true><<<dim3(32, 32), 256, GEMM_SMEM>>>(p0h, w0h, hw_b0, nullptr, p1h);
    gemm_kernel<true><<<dim3(32, 32), 256, GEMM_SMEM>>>(p1h, w1h, hw_b1, nullptr, p0h);
    gemm_kernel<false><<<dim3(6, 32), 256, GEMM_SMEM>>>(p0h, pwh, pb, out, nullptr);
}